// round 9
// baseline (speedup 1.0000x reference)
#include <cuda_runtime.h>
#include <cuda_bf16.h>
#include <cstdint>

// Problem constants
#define S_LEN 2048
#define D_DIM 1024
#define H_NUM 16
#define DH 64
#define LN_EPS 1e-5f
#define LOG2E 1.4426950408889634f

// ---------------------------------------------------------------------------
// PTX helpers
// ---------------------------------------------------------------------------
__device__ __forceinline__ uint32_t smem_u32(const void* p) {
    uint32_t a;
    asm("{ .reg .u64 t; cvta.to.shared.u64 t, %1; cvt.u32.u64 %0, t; }"
        : "=r"(a) : "l"(p));
    return a;
}

__device__ __forceinline__ void ldsm4(uint32_t* r, uint32_t a) {
    asm volatile("ldmatrix.sync.aligned.m8n8.x4.shared.b16 {%0,%1,%2,%3}, [%4];"
                 : "=r"(r[0]), "=r"(r[1]), "=r"(r[2]), "=r"(r[3]) : "r"(a));
}
__device__ __forceinline__ void ldsm4t(uint32_t* r, uint32_t a) {
    asm volatile("ldmatrix.sync.aligned.m8n8.x4.trans.shared.b16 {%0,%1,%2,%3}, [%4];"
                 : "=r"(r[0]), "=r"(r[1]), "=r"(r[2]), "=r"(r[3]) : "r"(a));
}

__device__ __forceinline__ void mma16816(float* c, const uint32_t* a, const uint32_t* b) {
    asm volatile("mma.sync.aligned.m16n8k16.row.col.f32.bf16.bf16.f32 "
                 "{%0,%1,%2,%3}, {%4,%5,%6,%7}, {%8,%9}, {%0,%1,%2,%3};"
                 : "+f"(c[0]), "+f"(c[1]), "+f"(c[2]), "+f"(c[3])
                 : "r"(a[0]), "r"(a[1]), "r"(a[2]), "r"(a[3]),
                   "r"(b[0]), "r"(b[1]));
}

#define MBARRIER_INIT(addr, cnt) \
    asm volatile("mbarrier.init.shared.b64 [%0], %1;" :: "r"((uint32_t)(addr)), "r"((uint32_t)(cnt)) : "memory")

#define MBARRIER_EXPECT_TX(addr, tx) \
    asm volatile("mbarrier.arrive.expect_tx.shared.b64 _, [%0], %1;" \
                 :: "r"((uint32_t)(addr)), "r"((uint32_t)(tx)) : "memory")

#define MBARRIER_WAIT_PARITY(mbar_smem_addr, phase_parity) do { \
    uint32_t _mbar = (uint32_t)(mbar_smem_addr); \
    uint32_t _parity = (uint32_t)(phase_parity); \
    uint32_t _done; \
    asm volatile("{\n\t.reg .pred p;\n\t" \
        "mbarrier.try_wait.parity.acquire.cta.shared::cta.b64 p, [%1], %2;\n\t" \
        "selp.b32 %0, 1, 0, p;\n\t}" \
        : "=r"(_done) : "r"(_mbar), "r"(_parity) : "memory"); \
    if (!_done) { \
        asm volatile("{\n\t.reg .pred P1;\n\t" \
            "WAIT_LOOP_%=:\n\t" \
            "mbarrier.try_wait.parity.acquire.cta.shared::cta.b64 P1, [%0], %1, 0x989680;\n\t" \
            "@P1 bra.uni WAIT_DONE_%=;\n\t" \
            "bra.uni WAIT_LOOP_%=;\n\t" \
            "WAIT_DONE_%=:\n\t}" \
            :: "r"(_mbar), "r"(_parity) : "memory"); \
    } \
} while (0)

__device__ __forceinline__ void bulk_g2s(uint32_t dst, const void* src, uint32_t bytes, uint32_t mbar) {
    asm volatile("cp.async.bulk.shared::cluster.global.mbarrier::complete_tx::bytes "
                 "[%0], [%1], %2, [%3];"
                 :: "r"(dst), "l"(src), "r"(bytes), "r"(mbar) : "memory");
}

#define FENCE_PROXY_ASYNC() asm volatile("fence.proxy.async.shared::cta;" ::: "memory")

#define SMEM_SWZ(off) ((off) ^ (((off) >> 3) & 0x70))

__device__ __forceinline__ uint32_t pack_bf16x2(float a, float b) {
    __nv_bfloat162 t = __floats2bfloat162_rn(a, b);
    return *reinterpret_cast<uint32_t*>(&t);
}
__device__ __forceinline__ void split2(float a, float b, uint32_t& hi, uint32_t& lo) {
    float ha = __bfloat162float(__float2bfloat16(a));
    float hb = __bfloat162float(__float2bfloat16(b));
    hi = pack_bf16x2(ha, hb);
    lo = pack_bf16x2(a - ha, b - hb);
}
__device__ __forceinline__ float ex2(float x) {
    float y; asm("ex2.approx.ftz.f32 %0, %1;" : "=f"(y) : "f"(x)); return y;
}

// ---------------------------------------------------------------------------
// Scratch (device globals)
// ---------------------------------------------------------------------------
__device__ __align__(128) __nv_bfloat16 g_xb [2 * S_LEN * D_DIM];
__device__ __align__(128) __nv_bfloat16 g_wqb[2 * D_DIM * D_DIM];
__device__ __align__(128) __nv_bfloat16 g_wkb[2 * D_DIM * D_DIM];
__device__ __align__(128) __nv_bfloat16 g_wvb[2 * D_DIM * D_DIM];
__device__ __align__(128) __nv_bfloat16 g_wob[2 * D_DIM * D_DIM];
__device__ __align__(128) __nv_bfloat16 g_qb [2 * S_LEN * D_DIM];
__device__ __align__(128) __nv_bfloat16 g_kvb[4 * S_LEN * D_DIM];
__device__ __align__(128) __nv_bfloat16 g_ab [2 * S_LEN * D_DIM];
__device__ float g_res[S_LEN * D_DIM];
__device__ __align__(8) uint32_t g_mpack[S_LEN * (S_LEN / 32)];

// ---------------------------------------------------------------------------
// Mask bit-pack
// ---------------------------------------------------------------------------
__global__ __launch_bounds__(256) void pack_mask_kernel(
    const unsigned int* __restrict__ mask, uint32_t* __restrict__ mp)
{
    int row = blockIdx.x;
    int w = threadIdx.x >> 5;
    int lane = threadIdx.x & 31;
#pragma unroll
    for (int i = 0; i < 8; i++) {
        int word = w * 8 + i;
        unsigned int v = mask[(size_t)row * S_LEN + word * 32 + lane];
        unsigned int bal = __ballot_sync(0xffffffffu, v != 0u);
        if (lane == 0) mp[row * 64 + word] = bal;
    }
}

// ---------------------------------------------------------------------------
// Fused split (unchanged)
// ---------------------------------------------------------------------------
__global__ __launch_bounds__(256) void split_all_kernel(
    const float* __restrict__ x,
    const float* __restrict__ Wq, const float* __restrict__ Wk,
    const float* __restrict__ Wv, const float* __restrict__ Wo,
    __nv_bfloat16* __restrict__ xb,
    __nv_bfloat16* __restrict__ wqb, __nv_bfloat16* __restrict__ wkb,
    __nv_bfloat16* __restrict__ wvb, __nv_bfloat16* __restrict__ wob)
{
    int bid = blockIdx.x;
    const float* src;
    __nv_bfloat16* dst;
    int lbid;
    if (bid < 1024) { src = x; dst = xb; lbid = bid; }
    else {
        int w = (bid - 1024) >> 9;
        lbid = (bid - 1024) & 511;
        src = (w == 0) ? Wq : (w == 1) ? Wk : (w == 2) ? Wv : Wo;
        dst = (w == 0) ? wqb : (w == 1) ? wkb : (w == 2) ? wvb : wob;
    }
    int idx = lbid * 256 + threadIdx.x;
    int row = idx >> 7;
    int k   = (idx & 127) * 8;

    float4 v0 = *(const float4*)(src + (size_t)row * D_DIM + k);
    float4 v1 = *(const float4*)(src + (size_t)row * D_DIM + k + 4);

    uint4 hi, lo;
    uint32_t h, l;
    split2(v0.x, v0.y, h, l); hi.x = h; lo.x = l;
    split2(v0.z, v0.w, h, l); hi.y = h; lo.y = l;
    split2(v1.x, v1.y, h, l); hi.z = h; lo.z = l;
    split2(v1.z, v1.w, h, l); hi.w = h; lo.w = l;

    size_t base = ((size_t)(row >> 7) * 16 + (k >> 6)) * 32768;
    uint32_t off = SMEM_SWZ((uint32_t)((row & 127) * 128 + (k & 63) * 2));
    char* p = (char*)dst + base;
    *(uint4*)(p + off) = hi;
    *(uint4*)(p + 16384 + off) = lo;
}

// ---------------------------------------------------------------------------
// GEMM mainloop (R8 tiling: 64x128, BK=64, 2-stage, 2 CTAs/SM)
// ---------------------------------------------------------------------------
#define GSTAGE 49152
#define GEMM_SMEM (64 + 2 * GSTAGE)

__device__ __forceinline__ void gemm_mainloop64(
    uint32_t sb, const char* Abase, const char* Bsrc, int NCH,
    int wm, int wn, int lane, int tid, float acc[2][4][4])
{
    if (tid == 0) {
        MBARRIER_INIT(sb + 0, 1);
        MBARRIER_INIT(sb + 8, 1);
        FENCE_PROXY_ASYNC();
    }
    __syncthreads();

    auto issue = [&](int ch) {
        const int s = ch & 1;
        uint32_t mbar = sb + 8 * s;
        uint32_t dst = sb + 64 + s * GSTAGE;
        const char* ab = Abase + (size_t)ch * 32768;
        MBARRIER_EXPECT_TX(mbar, GSTAGE);
        bulk_g2s(dst,         ab,          8192, mbar);
        bulk_g2s(dst + 8192,  ab + 16384,  8192, mbar);
        bulk_g2s(dst + 16384, Bsrc + (size_t)ch * 32768, 32768, mbar);
    };

    if (tid == 0) { issue(0); issue(1); }

#pragma unroll
    for (int i = 0; i < 2; i++)
#pragma unroll
        for (int j = 0; j < 4; j++)
#pragma unroll
            for (int r = 0; r < 4; r++) acc[i][j][r] = 0.0f;

    const int arow = wm * 32 + (lane & 15);
    const int brow = wn * 32 + ((lane >> 4) & 1) * 8 + (lane & 7);

    for (int ch = 0; ch < NCH; ch++) {
        const int s = ch & 1;
        MBARRIER_WAIT_PARITY(sb + 8 * s, (ch >> 1) & 1);

        const uint32_t bufA = sb + 64 + s * GSTAGE;
        const uint32_t bufB = bufA + 16384;

#pragma unroll
        for (int kc = 0; kc < 4; kc++) {
            uint32_t ah[2][4], alr[2][4], bh[4][2], bl[4][2];
#pragma unroll
            for (int mt = 0; mt < 2; mt++) {
                uint32_t off = SMEM_SWZ((uint32_t)((arow + mt * 16) * 128 + kc * 32 + (lane >> 4) * 16));
                ldsm4(ah[mt],  bufA + off);
                ldsm4(alr[mt], bufA + 8192 + off);
            }
#pragma unroll
            for (int np = 0; np < 2; np++) {
                uint32_t off = SMEM_SWZ((uint32_t)((brow + np * 16) * 128 + kc * 32 + ((lane >> 3) & 1) * 16));
                uint32_t r[4];
                ldsm4(r, bufB + off);
                bh[np * 2][0] = r[0]; bh[np * 2][1] = r[1];
                bh[np * 2 + 1][0] = r[2]; bh[np * 2 + 1][1] = r[3];
                ldsm4(r, bufB + 16384 + off);
                bl[np * 2][0] = r[0]; bl[np * 2][1] = r[1];
                bl[np * 2 + 1][0] = r[2]; bl[np * 2 + 1][1] = r[3];
            }
#pragma unroll
            for (int mt = 0; mt < 2; mt++)
#pragma unroll
                for (int nt = 0; nt < 4; nt++) {
                    mma16816(acc[mt][nt], ah[mt],  bh[nt]);
                    mma16816(acc[mt][nt], ah[mt],  bl[nt]);
                    mma16816(acc[mt][nt], alr[mt], bh[nt]);
                }
        }
        __syncthreads();

        if (ch + 2 < NCH && tid == 0) issue(ch + 2);
    }
}

// Fused QKV: z = 0 (Q), 1 (K), 2 (V). Grid (8, 32, 3).
__global__ __launch_bounds__(256, 2) void gemm_qkv_kernel(
    const __nv_bfloat16* __restrict__ xb,
    const __nv_bfloat16* __restrict__ wqb, const __nv_bfloat16* __restrict__ wkb,
    const __nv_bfloat16* __restrict__ wvb,
    __nv_bfloat16* __restrict__ qb, __nv_bfloat16* __restrict__ kvb)
{
    extern __shared__ char smem[];
    const uint32_t sb = smem_u32(smem);
    const int tid  = threadIdx.x;
    const int wid  = tid >> 5;
    const int lane = tid & 31;
    const int wm   = wid >> 2;
    const int wn   = wid & 3;
    const int z  = blockIdx.z;
    const int mb = blockIdx.y;
    const int nb = blockIdx.x;
    const int NCH = D_DIM >> 6;

    const __nv_bfloat16* Bblob = (z == 0) ? wqb : (z == 1) ? wkb : wvb;
    const float scale = (z == 0) ? 0.125f * LOG2E : 1.0f;

    const char* Abase = (const char*)xb + (size_t)(mb >> 1) * NCH * 32768
                        + (size_t)(mb & 1) * 8192;
    const char* Bsrc  = (const char*)Bblob + (size_t)nb * NCH * 32768;

    float acc[2][4][4];
    gemm_mainloop64(sb, Abase, Bsrc, NCH, wm, wn, lane, tid, acc);

#pragma unroll
    for (int mt = 0; mt < 2; mt++) {
        int row = mb * 64 + wm * 32 + mt * 16 + (lane >> 2);
#pragma unroll
        for (int nt = 0; nt < 4; nt++) {
            int col = nb * 128 + wn * 32 + nt * 8 + (lane & 3) * 2;
            float v0 = acc[mt][nt][0] * scale;
            float v1 = acc[mt][nt][1] * scale;
            float v2 = acc[mt][nt][2] * scale;
            float v3 = acc[mt][nt][3] * scale;
            uint32_t h01, l01, h23, l23;
            split2(v0, v1, h01, l01);
            split2(v2, v3, h23, l23);
            if (z == 0) {
                size_t base = ((size_t)(row >> 7) * 16 + (col >> 6)) * 32768;
                uint32_t o0 = SMEM_SWZ((uint32_t)((row & 127) * 128 + (col & 63) * 2));
                uint32_t o1 = SMEM_SWZ((uint32_t)(((row + 8) & 127) * 128 + (col & 63) * 2));
                char* p = (char*)qb + base;
                *(uint32_t*)(p + o0) = h01; *(uint32_t*)(p + 16384 + o0) = l01;
                *(uint32_t*)(p + o1) = h23; *(uint32_t*)(p + 16384 + o1) = l23;
            } else {
                size_t base = ((size_t)(col >> 6) * 32 + (row >> 6)) * 32768
                              + (z == 2 ? 16384 : 0);
                uint32_t o0 = SMEM_SWZ((uint32_t)((row & 63) * 128 + (col & 63) * 2));
                uint32_t o1 = SMEM_SWZ((uint32_t)(((row + 8) & 63) * 128 + (col & 63) * 2));
                char* p = (char*)kvb + base;
                *(uint32_t*)(p + o0) = h01; *(uint32_t*)(p + 8192 + o0) = l01;
                *(uint32_t*)(p + o1) = h23; *(uint32_t*)(p + 8192 + o1) = l23;
            }
        }
    }
}

// Output projection: fp32 + residual
__global__ __launch_bounds__(256, 2) void gemm_out_kernel(
    const __nv_bfloat16* __restrict__ Ablob, const __nv_bfloat16* __restrict__ Bblob,
    const float* __restrict__ resid, float* __restrict__ Cf)
{
    extern __shared__ char smem[];
    const uint32_t sb = smem_u32(smem);
    const int tid  = threadIdx.x;
    const int wid  = tid >> 5;
    const int lane = tid & 31;
    const int wm   = wid >> 2;
    const int wn   = wid & 3;
    const int mb = blockIdx.y;
    const int nb = blockIdx.x;
    const int NCH = D_DIM >> 6;

    const char* Abase = (const char*)Ablob + (size_t)(mb >> 1) * NCH * 32768
                        + (size_t)(mb & 1) * 8192;
    const char* Bsrc  = (const char*)Bblob + (size_t)nb * NCH * 32768;

    float acc[2][4][4];
    gemm_mainloop64(sb, Abase, Bsrc, NCH, wm, wn, lane, tid, acc);

#pragma unroll
    for (int mt = 0; mt < 2; mt++) {
        int row = mb * 64 + wm * 32 + mt * 16 + (lane >> 2);
#pragma unroll
        for (int nt = 0; nt < 4; nt++) {
            int col = nb * 128 + wn * 32 + nt * 8 + (lane & 3) * 2;
            float2 r0 = *(const float2*)(resid + (size_t)row * D_DIM + col);
            float2 r1 = *(const float2*)(resid + (size_t)(row + 8) * D_DIM + col);
            *(float2*)(Cf + (size_t)row * D_DIM + col) =
                make_float2(acc[mt][nt][0] + r0.x, acc[mt][nt][1] + r0.y);
            *(float2*)(Cf + (size_t)(row + 8) * D_DIM + col) =
                make_float2(acc[mt][nt][2] + r1.x, acc[mt][nt][3] + r1.y);
        }
    }
}

// ---------------------------------------------------------------------------
// Flash attention: 2-stage KV ring, 2 CTAs/SM, bias loads hoisted before QK.
// ---------------------------------------------------------------------------
#define ATT_SMEM (64 + 32768 + 2 * 32768)

__global__ __launch_bounds__(256, 2) void attn_blob_kernel(
    const __nv_bfloat16* __restrict__ Qb, const __nv_bfloat16* __restrict__ KVb,
    const float* __restrict__ bias, const uint32_t* __restrict__ mpack,
    __nv_bfloat16* __restrict__ Ob)
{
    extern __shared__ char smem[];
    const uint32_t sb = smem_u32(smem);
    const uint32_t qsm  = sb + 64;
    const uint32_t kvsm = sb + 64 + 32768;
    const int tid  = threadIdx.x;
    const int wid  = tid >> 5;
    const int lane = tid & 31;
    const int h  = blockIdx.y;
    const int qb = blockIdx.x;
    const int q0 = qb * 128;

    const char* Qsrc  = (const char*)Qb + ((size_t)qb * 16 + h) * 32768;
    const char* KVsrc = (const char*)KVb + (size_t)h * 32 * 32768;

    if (tid == 0) {
        MBARRIER_INIT(sb + 0, 1);
        MBARRIER_INIT(sb + 8, 1);
        MBARRIER_INIT(sb + 16, 1);
        FENCE_PROXY_ASYNC();
    }
    __syncthreads();

    if (tid == 0) {
        MBARRIER_EXPECT_TX(sb + 0, 32768);
        bulk_g2s(qsm, Qsrc, 32768, sb + 0);
#pragma unroll
        for (int i = 0; i < 2; i++) {
            MBARRIER_EXPECT_TX(sb + 8 + 8 * i, 32768);
            bulk_g2s(kvsm + i * 32768, KVsrc + (size_t)i * 32768, 32768, sb + 8 + 8 * i);
        }
    }

    float Oacc[8][4];
#pragma unroll
    for (int i = 0; i < 8; i++)
#pragma unroll
        for (int j = 0; j < 4; j++) Oacc[i][j] = 0.0f;
    float m0 = -1e30f, m1 = -1e30f, l0 = 0.0f, l1 = 0.0f;

    const int r = lane >> 2;
    const int grow0 = q0 + wid * 16 + r;
    const int grow1 = grow0 + 8;
    const float* brow0 = bias + (size_t)grow0 * (H_NUM * S_LEN) + (size_t)h * S_LEN;
    const float* brow1 = bias + (size_t)grow1 * (H_NUM * S_LEN) + (size_t)h * S_LEN;
    const uint32_t* mp0 = mpack + grow0 * (S_LEN / 32);
    const uint32_t* mp1 = mpack + grow1 * (S_LEN / 32);
    const int cbase = (lane & 3) * 2;
    const int qrow = wid * 16 + (lane & 15);
    const int qsel = (lane >> 4) * 16;

    MBARRIER_WAIT_PARITY(sb + 0, 0);

    for (int t = 0; t < S_LEN / 64; t++) {
        MBARRIER_WAIT_PARITY(sb + 8 + 8 * (t & 1), (t >> 1) & 1);
        const uint32_t base = kvsm + (t & 1) * 32768;
        const int j0 = t * 64;

        uint2 mwa = *(const uint2*)(mp0 + (j0 >> 5));
        uint2 mwb = *(const uint2*)(mp1 + (j0 >> 5));
        uint64_t sm0 = (((uint64_t)mwa.y << 32) | mwa.x) >> cbase;
        uint64_t sm1 = (((uint64_t)mwb.y << 32) | mwb.x) >> cbase;

        // ---- HOISTED bias loads: issue before QK MMAs so DRAM latency
        //      overlaps the tensor phase ----
        float2 bv0[8], bv1[8];
#pragma unroll
        for (int nt = 0; nt < 8; nt++) {
            bv0[nt] = *(const float2*)(brow0 + j0 + nt * 8 + cbase);
            bv1[nt] = *(const float2*)(brow1 + j0 + nt * 8 + cbase);
        }

        float acc[8][4];
#pragma unroll
        for (int i = 0; i < 8; i++)
#pragma unroll
            for (int j = 0; j < 4; j++) acc[i][j] = 0.0f;

#pragma unroll
        for (int kc = 0; kc < 4; kc++) {
            uint32_t qh[4], ql[4];
            uint32_t qoff = SMEM_SWZ((uint32_t)(qrow * 128 + kc * 32 + qsel));
            ldsm4(qh, qsm + qoff);
            ldsm4(ql, qsm + 16384 + qoff);
#pragma unroll
            for (int np = 0; np < 4; np++) {
                int krow = np * 16 + (lane >> 4) * 8 + (lane & 7);
                uint32_t koff = SMEM_SWZ((uint32_t)(krow * 128 + kc * 32 + ((lane >> 3) & 1) * 16));
                uint32_t bh[4], bl[4];
                ldsm4(bh, base + koff);
                ldsm4(bl, base + 8192 + koff);
                mma16816(acc[2 * np],     qh, bh + 0);
                mma16816(acc[2 * np],     qh, bl + 0);
                mma16816(acc[2 * np],     ql, bh + 0);
                mma16816(acc[2 * np + 1], qh, bh + 2);
                mma16816(acc[2 * np + 1], qh, bl + 2);
                mma16816(acc[2 * np + 1], ql, bh + 2);
            }
        }

        float mx0 = -1e30f, mx1 = -1e30f;
#pragma unroll
        for (int nt = 0; nt < 8; nt++) {
            uint32_t w0 = (uint32_t)(sm0 >> (nt * 8));
            uint32_t w1 = (uint32_t)(sm1 >> (nt * 8));
            acc[nt][0] = (w0 & 1u) ? fmaf(bv0[nt].x, LOG2E, acc[nt][0]) : -1e30f;
            acc[nt][1] = (w0 & 2u) ? fmaf(bv0[nt].y, LOG2E, acc[nt][1]) : -1e30f;
            acc[nt][2] = (w1 & 1u) ? fmaf(bv1[nt].x, LOG2E, acc[nt][2]) : -1e30f;
            acc[nt][3] = (w1 & 2u) ? fmaf(bv1[nt].y, LOG2E, acc[nt][3]) : -1e30f;
            mx0 = fmaxf(mx0, fmaxf(acc[nt][0], acc[nt][1]));
            mx1 = fmaxf(mx1, fmaxf(acc[nt][2], acc[nt][3]));
        }
        mx0 = fmaxf(mx0, __shfl_xor_sync(0xffffffffu, mx0, 1));
        mx0 = fmaxf(mx0, __shfl_xor_sync(0xffffffffu, mx0, 2));
        mx1 = fmaxf(mx1, __shfl_xor_sync(0xffffffffu, mx1, 1));
        mx1 = fmaxf(mx1, __shfl_xor_sync(0xffffffffu, mx1, 2));

        float mn0 = fmaxf(m0, mx0), mn1 = fmaxf(m1, mx1);
        float a0 = ex2(m0 - mn0), a1 = ex2(m1 - mn1);
        m0 = mn0; m1 = mn1;

        float s0 = 0.0f, s1 = 0.0f;
#pragma unroll
        for (int nt = 0; nt < 8; nt++) {
            acc[nt][0] = ex2(acc[nt][0] - mn0);
            acc[nt][1] = ex2(acc[nt][1] - mn0);
            acc[nt][2] = ex2(acc[nt][2] - mn1);
            acc[nt][3] = ex2(acc[nt][3] - mn1);
            s0 += acc[nt][0] + acc[nt][1];
            s1 += acc[nt][2] + acc[nt][3];
        }
        s0 += __shfl_xor_sync(0xffffffffu, s0, 1);
        s0 += __shfl_xor_sync(0xffffffffu, s0, 2);
        s1 += __shfl_xor_sync(0xffffffffu, s1, 1);
        s1 += __shfl_xor_sync(0xffffffffu, s1, 2);
        l0 = l0 * a0 + s0;
        l1 = l1 * a1 + s1;

#pragma unroll
        for (int nt = 0; nt < 8; nt++) {
            Oacc[nt][0] *= a0; Oacc[nt][1] *= a0;
            Oacc[nt][2] *= a1; Oacc[nt][3] *= a1;
        }

#pragma unroll
        for (int kc = 0; kc < 4; kc++) {
            uint32_t pha[4], pla[4];
            split2(acc[2 * kc][0],     acc[2 * kc][1],     pha[0], pla[0]);
            split2(acc[2 * kc][2],     acc[2 * kc][3],     pha[1], pla[1]);
            split2(acc[2 * kc + 1][0], acc[2 * kc + 1][1], pha[2], pla[2]);
            split2(acc[2 * kc + 1][2], acc[2 * kc + 1][3], pha[3], pla[3]);
#pragma unroll
            for (int dp = 0; dp < 4; dp++) {
                int vrow = kc * 16 + (lane & 15);
                uint32_t voff = SMEM_SWZ((uint32_t)(vrow * 128 + dp * 32 + (lane >> 4) * 16));
                uint32_t vh[4], vl[4];
                ldsm4t(vh, base + 16384 + voff);
                ldsm4t(vl, base + 24576 + voff);
                mma16816(Oacc[2 * dp],     pha, vh + 0);
                mma16816(Oacc[2 * dp],     pla, vh + 0);
                mma16816(Oacc[2 * dp],     pha, vl + 0);
                mma16816(Oacc[2 * dp + 1], pha, vh + 2);
                mma16816(Oacc[2 * dp + 1], pla, vh + 2);
                mma16816(Oacc[2 * dp + 1], pha, vl + 2);
            }
        }
        __syncthreads();

        if (t + 2 < S_LEN / 64 && tid == 0) {
            uint32_t mbar = sb + 8 + 8 * (t & 1);
            MBARRIER_EXPECT_TX(mbar, 32768);
            bulk_g2s(kvsm + (t & 1) * 32768, KVsrc + (size_t)(t + 2) * 32768, 32768, mbar);
        }
    }

    float inv0 = 1.0f / l0, inv1 = 1.0f / l1;
    char* outb = (char*)Ob + ((size_t)qb * 16 + h) * 32768;
    const int r128 = wid * 16 + r;
#pragma unroll
    for (int nt = 0; nt < 8; nt++) {
        int d = nt * 8 + cbase;
        float v0 = Oacc[nt][0] * inv0, v1 = Oacc[nt][1] * inv0;
        float v2 = Oacc[nt][2] * inv1, v3 = Oacc[nt][3] * inv1;
        uint32_t h01, l01, h23, l23;
        split2(v0, v1, h01, l01);
        split2(v2, v3, h23, l23);
        uint32_t o0 = SMEM_SWZ((uint32_t)(r128 * 128 + d * 2));
        uint32_t o1 = SMEM_SWZ((uint32_t)((r128 + 8) * 128 + d * 2));
        *(uint32_t*)(outb + o0) = h01; *(uint32_t*)(outb + 16384 + o0) = l01;
        *(uint32_t*)(outb + o1) = h23; *(uint32_t*)(outb + 16384 + o1) = l23;
    }
}

// ---------------------------------------------------------------------------
// LayerNorm
// ---------------------------------------------------------------------------
__device__ __forceinline__ float block_reduce_sum(float v) {
    __shared__ float red[8];
    int lane = threadIdx.x & 31, w = threadIdx.x >> 5;
#pragma unroll
    for (int o = 16; o > 0; o >>= 1) v += __shfl_xor_sync(0xffffffffu, v, o);
    __syncthreads();
    if (lane == 0) red[w] = v;
    __syncthreads();
    float t = 0.0f;
#pragma unroll
    for (int i = 0; i < 8; i++) t += red[i];
    return t;
}

__global__ __launch_bounds__(256) void ln_kernel(
    const float* __restrict__ res, const float* __restrict__ w,
    const float* __restrict__ b, float* __restrict__ out)
{
    int row = blockIdx.x;
    int tid = threadIdx.x;
    const float* r = res + (size_t)row * D_DIM;

    float4 x4 = *(const float4*)(r + tid * 4);
    float sum = x4.x + x4.y + x4.z + x4.w;
    sum = block_reduce_sum(sum);
    float mean = sum * (1.0f / D_DIM);

    float d0 = x4.x - mean, d1 = x4.y - mean, d2 = x4.z - mean, d3 = x4.w - mean;
    float sq = d0 * d0 + d1 * d1 + d2 * d2 + d3 * d3;
    sq = block_reduce_sum(sq);
    float inv = rsqrtf(sq * (1.0f / D_DIM) + LN_EPS);

    float4 w4 = *(const float4*)(w + tid * 4);
    float4 b4 = *(const float4*)(b + tid * 4);
    float4 o4;
    o4.x = d0 * inv * w4.x + b4.x;
    o4.y = d1 * inv * w4.y + b4.y;
    o4.z = d2 * inv * w4.z + b4.z;
    o4.w = d3 * inv * w4.w + b4.w;
    *(float4*)(out + (size_t)row * D_DIM + tid * 4) = o4;
}

// ---------------------------------------------------------------------------
// Launch
// ---------------------------------------------------------------------------
extern "C" void kernel_launch(void* const* d_in, const int* in_sizes, int n_in,
                              void* d_out, int out_size)
{
    (void)in_sizes; (void)n_in; (void)out_size;

    const float*        x    = (const float*)d_in[0];
    const float*        bias = (const float*)d_in[1];
    const unsigned int* mask = (const unsigned int*)d_in[2];
    const float*        Wq   = (const float*)d_in[3];
    const float*        Wk   = (const float*)d_in[4];
    const float*        Wv   = (const float*)d_in[5];
    const float*        Wo   = (const float*)d_in[6];
    const float*        lnw  = (const float*)d_in[7];
    const float*        lnb  = (const float*)d_in[8];
    float*              out  = (float*)d_out;

    void *pxb, *pwq, *pwk, *pwv, *pwo, *pqb, *pkv, *pab, *pres, *pmp;
    cudaGetSymbolAddress(&pxb, g_xb);
    cudaGetSymbolAddress(&pwq, g_wqb);
    cudaGetSymbolAddress(&pwk, g_wkb);
    cudaGetSymbolAddress(&pwv, g_wvb);
    cudaGetSymbolAddress(&pwo, g_wob);
    cudaGetSymbolAddress(&pqb, g_qb);
    cudaGetSymbolAddress(&pkv, g_kvb);
    cudaGetSymbolAddress(&pab, g_ab);
    cudaGetSymbolAddress(&pres, g_res);
    cudaGetSymbolAddress(&pmp, g_mpack);

    __nv_bfloat16 *xb = (__nv_bfloat16*)pxb;
    __nv_bfloat16 *wqb = (__nv_bfloat16*)pwq, *wkb = (__nv_bfloat16*)pwk;
    __nv_bfloat16 *wvb = (__nv_bfloat16*)pwv, *wob = (__nv_bfloat16*)pwo;
    __nv_bfloat16 *qb = (__nv_bfloat16*)pqb, *kvb = (__nv_bfloat16*)pkv;
    __nv_bfloat16 *ab = (__nv_bfloat16*)pab;
    float* res = (float*)pres;
    uint32_t* mp = (uint32_t*)pmp;

    cudaFuncSetAttribute(gemm_qkv_kernel, cudaFuncAttributeMaxDynamicSharedMemorySize, GEMM_SMEM);
    cudaFuncSetAttribute(gemm_out_kernel, cudaFuncAttributeMaxDynamicSharedMemorySize, GEMM_SMEM);
    cudaFuncSetAttribute(attn_blob_kernel, cudaFuncAttributeMaxDynamicSharedMemorySize, ATT_SMEM);

    split_all_kernel<<<3072, 256>>>(x, Wq, Wk, Wv, Wo, xb, wqb, wkb, wvb, wob);
    pack_mask_kernel<<<S_LEN, 256>>>(mask, mp);

    // Fused QKV projections (Q pre-scaled by 1/8 * log2e)
    gemm_qkv_kernel<<<dim3(8, 32, 3), 256, GEMM_SMEM>>>(xb, wqb, wkb, wvb, qb, kvb);

    attn_blob_kernel<<<dim3(S_LEN / 128, H_NUM), 256, ATT_SMEM>>>(qb, kvb, bias, mp, ab);

    gemm_out_kernel<<<dim3(8, 32), 256, GEMM_SMEM>>>(ab, wob, x, res);

    ln_kernel<<<S_LEN, 256>>>(res, lnw, lnb, out);
}

// round 10
// speedup vs baseline: 1.4256x; 1.4256x over previous
#include <cuda_runtime.h>
#include <cuda_bf16.h>
#include <cstdint>

// Problem constants
#define S_LEN 2048
#define D_DIM 1024
#define H_NUM 16
#define DH 64
#define LN_EPS 1e-5f
#define LOG2E 1.4426950408889634f

// ---------------------------------------------------------------------------
// PTX helpers
// ---------------------------------------------------------------------------
__device__ __forceinline__ uint32_t smem_u32(const void* p) {
    uint32_t a;
    asm("{ .reg .u64 t; cvta.to.shared.u64 t, %1; cvt.u32.u64 %0, t; }"
        : "=r"(a) : "l"(p));
    return a;
}

__device__ __forceinline__ void ldsm4(uint32_t* r, uint32_t a) {
    asm volatile("ldmatrix.sync.aligned.m8n8.x4.shared.b16 {%0,%1,%2,%3}, [%4];"
                 : "=r"(r[0]), "=r"(r[1]), "=r"(r[2]), "=r"(r[3]) : "r"(a));
}
__device__ __forceinline__ void ldsm4t(uint32_t* r, uint32_t a) {
    asm volatile("ldmatrix.sync.aligned.m8n8.x4.trans.shared.b16 {%0,%1,%2,%3}, [%4];"
                 : "=r"(r[0]), "=r"(r[1]), "=r"(r[2]), "=r"(r[3]) : "r"(a));
}

__device__ __forceinline__ void mma16816(float* c, const uint32_t* a, const uint32_t* b) {
    asm volatile("mma.sync.aligned.m16n8k16.row.col.f32.bf16.bf16.f32 "
                 "{%0,%1,%2,%3}, {%4,%5,%6,%7}, {%8,%9}, {%0,%1,%2,%3};"
                 : "+f"(c[0]), "+f"(c[1]), "+f"(c[2]), "+f"(c[3])
                 : "r"(a[0]), "r"(a[1]), "r"(a[2]), "r"(a[3]),
                   "r"(b[0]), "r"(b[1]));
}

#define MBARRIER_INIT(addr, cnt) \
    asm volatile("mbarrier.init.shared.b64 [%0], %1;" :: "r"((uint32_t)(addr)), "r"((uint32_t)(cnt)) : "memory")

#define MBARRIER_EXPECT_TX(addr, tx) \
    asm volatile("mbarrier.arrive.expect_tx.shared.b64 _, [%0], %1;" \
                 :: "r"((uint32_t)(addr)), "r"((uint32_t)(tx)) : "memory")

#define MBARRIER_ARRIVE(addr) \
    asm volatile("mbarrier.arrive.shared.b64 _, [%0];" \
                 :: "r"((uint32_t)(addr)) : "memory")

#define MBARRIER_WAIT_PARITY(mbar_smem_addr, phase_parity) do { \
    uint32_t _mbar = (uint32_t)(mbar_smem_addr); \
    uint32_t _parity = (uint32_t)(phase_parity); \
    uint32_t _done; \
    asm volatile("{\n\t.reg .pred p;\n\t" \
        "mbarrier.try_wait.parity.acquire.cta.shared::cta.b64 p, [%1], %2;\n\t" \
        "selp.b32 %0, 1, 0, p;\n\t}" \
        : "=r"(_done) : "r"(_mbar), "r"(_parity) : "memory"); \
    if (!_done) { \
        asm volatile("{\n\t.reg .pred P1;\n\t" \
            "WAIT_LOOP_%=:\n\t" \
            "mbarrier.try_wait.parity.acquire.cta.shared::cta.b64 P1, [%0], %1, 0x989680;\n\t" \
            "@P1 bra.uni WAIT_DONE_%=;\n\t" \
            "bra.uni WAIT_LOOP_%=;\n\t" \
            "WAIT_DONE_%=:\n\t}" \
            :: "r"(_mbar), "r"(_parity) : "memory"); \
    } \
} while (0)

__device__ __forceinline__ void bulk_g2s(uint32_t dst, const void* src, uint32_t bytes, uint32_t mbar) {
    asm volatile("cp.async.bulk.shared::cluster.global.mbarrier::complete_tx::bytes "
                 "[%0], [%1], %2, [%3];"
                 :: "r"(dst), "l"(src), "r"(bytes), "r"(mbar) : "memory");
}

#define FENCE_PROXY_ASYNC() asm volatile("fence.proxy.async.shared::cta;" ::: "memory")

#define SMEM_SWZ(off) ((off) ^ (((off) >> 3) & 0x70))

__device__ __forceinline__ uint32_t pack_bf16x2(float a, float b) {
    __nv_bfloat162 t = __floats2bfloat162_rn(a, b);
    return *reinterpret_cast<uint32_t*>(&t);
}
__device__ __forceinline__ void split2(float a, float b, uint32_t& hi, uint32_t& lo) {
    float ha = __bfloat162float(__float2bfloat16(a));
    float hb = __bfloat162float(__float2bfloat16(b));
    hi = pack_bf16x2(ha, hb);
    lo = pack_bf16x2(a - ha, b - hb);
}
__device__ __forceinline__ float ex2(float x) {
    float y; asm("ex2.approx.ftz.f32 %0, %1;" : "=f"(y) : "f"(x)); return y;
}

// ---------------------------------------------------------------------------
// Scratch (device globals)
// ---------------------------------------------------------------------------
__device__ __align__(128) __nv_bfloat16 g_xb [2 * S_LEN * D_DIM];
__device__ __align__(128) __nv_bfloat16 g_wqb[2 * D_DIM * D_DIM];
__device__ __align__(128) __nv_bfloat16 g_wkb[2 * D_DIM * D_DIM];
__device__ __align__(128) __nv_bfloat16 g_wvb[2 * D_DIM * D_DIM];
__device__ __align__(128) __nv_bfloat16 g_wob[2 * D_DIM * D_DIM];
__device__ __align__(128) __nv_bfloat16 g_qb [2 * S_LEN * D_DIM];
__device__ __align__(128) __nv_bfloat16 g_kvb[4 * S_LEN * D_DIM];
__device__ __align__(128) __nv_bfloat16 g_ab [2 * S_LEN * D_DIM];
__device__ float g_res[S_LEN * D_DIM];
__device__ __align__(8) uint32_t g_mpack[S_LEN * (S_LEN / 32)];

// ---------------------------------------------------------------------------
// Mask bit-pack
// ---------------------------------------------------------------------------
__global__ __launch_bounds__(256) void pack_mask_kernel(
    const unsigned int* __restrict__ mask, uint32_t* __restrict__ mp)
{
    int row = blockIdx.x;
    int w = threadIdx.x >> 5;
    int lane = threadIdx.x & 31;
#pragma unroll
    for (int i = 0; i < 8; i++) {
        int word = w * 8 + i;
        unsigned int v = mask[(size_t)row * S_LEN + word * 32 + lane];
        unsigned int bal = __ballot_sync(0xffffffffu, v != 0u);
        if (lane == 0) mp[row * 64 + word] = bal;
    }
}

// ---------------------------------------------------------------------------
// Fused split
// ---------------------------------------------------------------------------
__global__ __launch_bounds__(256) void split_all_kernel(
    const float* __restrict__ x,
    const float* __restrict__ Wq, const float* __restrict__ Wk,
    const float* __restrict__ Wv, const float* __restrict__ Wo,
    __nv_bfloat16* __restrict__ xb,
    __nv_bfloat16* __restrict__ wqb, __nv_bfloat16* __restrict__ wkb,
    __nv_bfloat16* __restrict__ wvb, __nv_bfloat16* __restrict__ wob)
{
    int bid = blockIdx.x;
    const float* src;
    __nv_bfloat16* dst;
    int lbid;
    if (bid < 1024) { src = x; dst = xb; lbid = bid; }
    else {
        int w = (bid - 1024) >> 9;
        lbid = (bid - 1024) & 511;
        src = (w == 0) ? Wq : (w == 1) ? Wk : (w == 2) ? Wv : Wo;
        dst = (w == 0) ? wqb : (w == 1) ? wkb : (w == 2) ? wvb : wob;
    }
    int idx = lbid * 256 + threadIdx.x;
    int row = idx >> 7;
    int k   = (idx & 127) * 8;

    float4 v0 = *(const float4*)(src + (size_t)row * D_DIM + k);
    float4 v1 = *(const float4*)(src + (size_t)row * D_DIM + k + 4);

    uint4 hi, lo;
    uint32_t h, l;
    split2(v0.x, v0.y, h, l); hi.x = h; lo.x = l;
    split2(v0.z, v0.w, h, l); hi.y = h; lo.y = l;
    split2(v1.x, v1.y, h, l); hi.z = h; lo.z = l;
    split2(v1.z, v1.w, h, l); hi.w = h; lo.w = l;

    size_t base = ((size_t)(row >> 7) * 16 + (k >> 6)) * 32768;
    uint32_t off = SMEM_SWZ((uint32_t)((row & 127) * 128 + (k & 63) * 2));
    char* p = (char*)dst + base;
    *(uint4*)(p + off) = hi;
    *(uint4*)(p + 16384 + off) = lo;
}

// ---------------------------------------------------------------------------
// Blob GEMM (R7-proven): 128x128, BK=64, 3-stage bulk pipeline.
// modes: 0 = fp32 (+resid); 1 = Q blob; 2 = K blob; 3 = V blob
// ---------------------------------------------------------------------------
#define GEMM_SMEM (64 + 3 * 65536)

__global__ __launch_bounds__(256) void gemm_blob_kernel(
    const __nv_bfloat16* __restrict__ Ablob, const __nv_bfloat16* __restrict__ Bblob,
    const float* __restrict__ resid, float* __restrict__ Cf,
    __nv_bfloat16* __restrict__ OutB, int mode, float scale, int N, int K)
{
    extern __shared__ char smem[];
    const uint32_t sb = smem_u32(smem);
    const int tid  = threadIdx.x;
    const int wid  = tid >> 5;
    const int lane = tid & 31;
    const int wm   = wid >> 2;
    const int wn   = wid & 3;

    const int mb = blockIdx.y, nb = blockIdx.x;
    const int m0 = mb * 128, n0 = nb * 128;
    const int NCH = K >> 6;

    const char* Asrc = (const char*)Ablob + (size_t)mb * NCH * 32768;
    const char* Bsrc = (const char*)Bblob + (size_t)nb * NCH * 32768;

    if (tid == 0) {
        MBARRIER_INIT(sb + 0, 1);
        MBARRIER_INIT(sb + 8, 1);
        MBARRIER_INIT(sb + 16, 1);
        FENCE_PROXY_ASYNC();
    }
    __syncthreads();

    if (tid == 0) {
#pragma unroll
        for (int s = 0; s < 3; s++) {
            uint32_t mbar = sb + 8 * s;
            uint32_t dst = sb + 64 + s * 65536;
            MBARRIER_EXPECT_TX(mbar, 65536);
            bulk_g2s(dst,         Asrc + (size_t)s * 32768, 32768, mbar);
            bulk_g2s(dst + 32768, Bsrc + (size_t)s * 32768, 32768, mbar);
        }
    }

    float acc[4][4][4];
#pragma unroll
    for (int i = 0; i < 4; i++)
#pragma unroll
        for (int j = 0; j < 4; j++)
#pragma unroll
            for (int r = 0; r < 4; r++) acc[i][j][r] = 0.0f;

    const int arow = wm * 64 + (lane & 15);
    const int brow = wn * 32 + ((lane >> 4) & 1) * 8 + (lane & 7);

    for (int ch = 0; ch < NCH; ch++) {
        const int s = ch % 3;
        MBARRIER_WAIT_PARITY(sb + 8 * s, (ch / 3) & 1);

        const uint32_t bufA = sb + 64 + s * 65536;
        const uint32_t bufB = bufA + 32768;

#pragma unroll
        for (int kc = 0; kc < 4; kc++) {
            uint32_t ah[4][4], alr[4][4], bh[4][2], bl[4][2];
#pragma unroll
            for (int mt = 0; mt < 4; mt++) {
                uint32_t off = SMEM_SWZ((uint32_t)((arow + mt * 16) * 128 + kc * 32 + (lane >> 4) * 16));
                ldsm4(ah[mt],  bufA + off);
                ldsm4(alr[mt], bufA + 16384 + off);
            }
#pragma unroll
            for (int np = 0; np < 2; np++) {
                uint32_t off = SMEM_SWZ((uint32_t)((brow + np * 16) * 128 + kc * 32 + ((lane >> 3) & 1) * 16));
                uint32_t r[4];
                ldsm4(r, bufB + off);
                bh[np * 2][0] = r[0]; bh[np * 2][1] = r[1];
                bh[np * 2 + 1][0] = r[2]; bh[np * 2 + 1][1] = r[3];
                ldsm4(r, bufB + 16384 + off);
                bl[np * 2][0] = r[0]; bl[np * 2][1] = r[1];
                bl[np * 2 + 1][0] = r[2]; bl[np * 2 + 1][1] = r[3];
            }
#pragma unroll
            for (int mt = 0; mt < 4; mt++)
#pragma unroll
                for (int nt = 0; nt < 4; nt++) {
                    mma16816(acc[mt][nt], ah[mt],  bh[nt]);
                    mma16816(acc[mt][nt], ah[mt],  bl[nt]);
                    mma16816(acc[mt][nt], alr[mt], bh[nt]);
                }
        }
        __syncthreads();

        if (ch + 3 < NCH && tid == 0) {
            uint32_t mbar = sb + 8 * s;
            uint32_t dst = sb + 64 + s * 65536;
            MBARRIER_EXPECT_TX(mbar, 65536);
            bulk_g2s(dst,         Asrc + (size_t)(ch + 3) * 32768, 32768, mbar);
            bulk_g2s(dst + 32768, Bsrc + (size_t)(ch + 3) * 32768, 32768, mbar);
        }
    }

#pragma unroll
    for (int mt = 0; mt < 4; mt++) {
        int row = m0 + wm * 64 + mt * 16 + (lane >> 2);
#pragma unroll
        for (int nt = 0; nt < 4; nt++) {
            int col = n0 + wn * 32 + nt * 8 + (lane & 3) * 2;
            float v0 = acc[mt][nt][0] * scale;
            float v1 = acc[mt][nt][1] * scale;
            float v2 = acc[mt][nt][2] * scale;
            float v3 = acc[mt][nt][3] * scale;
            if (mode == 0) {
                if (resid) {
                    float2 r0 = *(const float2*)(resid + (size_t)row * N + col);
                    float2 r1 = *(const float2*)(resid + (size_t)(row + 8) * N + col);
                    v0 += r0.x; v1 += r0.y; v2 += r1.x; v3 += r1.y;
                }
                *(float2*)(Cf + (size_t)row * N + col) = make_float2(v0, v1);
                *(float2*)(Cf + (size_t)(row + 8) * N + col) = make_float2(v2, v3);
            } else {
                uint32_t h01, l01, h23, l23;
                split2(v0, v1, h01, l01);
                split2(v2, v3, h23, l23);
                if (mode == 1) {
                    size_t base = ((size_t)(row >> 7) * 16 + (col >> 6)) * 32768;
                    uint32_t o0 = SMEM_SWZ((uint32_t)((row & 127) * 128 + (col & 63) * 2));
                    uint32_t o1 = SMEM_SWZ((uint32_t)(((row + 8) & 127) * 128 + (col & 63) * 2));
                    char* p = (char*)OutB + base;
                    *(uint32_t*)(p + o0) = h01; *(uint32_t*)(p + 16384 + o0) = l01;
                    *(uint32_t*)(p + o1) = h23; *(uint32_t*)(p + 16384 + o1) = l23;
                } else {
                    size_t base = ((size_t)(col >> 6) * 32 + (row >> 6)) * 32768
                                  + (mode == 3 ? 16384 : 0);
                    uint32_t o0 = SMEM_SWZ((uint32_t)((row & 63) * 128 + (col & 63) * 2));
                    uint32_t o1 = SMEM_SWZ((uint32_t)(((row + 8) & 63) * 128 + (col & 63) * 2));
                    char* p = (char*)OutB + base;
                    *(uint32_t*)(p + o0) = h01; *(uint32_t*)(p + 8192 + o0) = l01;
                    *(uint32_t*)(p + o1) = h23; *(uint32_t*)(p + 8192 + o1) = l23;
                }
            }
        }
    }
}

// ---------------------------------------------------------------------------
// Flash attention: 2-stage KV ring, 2 CTAs/SM, warp-decoupled via mbarrier
// full/empty pairs (no per-tile __syncthreads -> cross-warp latency overlap).
// ---------------------------------------------------------------------------
#define ATT_SMEM (64 + 32768 + 2 * 32768)

__global__ __launch_bounds__(256, 2) void attn_blob_kernel(
    const __nv_bfloat16* __restrict__ Qb, const __nv_bfloat16* __restrict__ KVb,
    const float* __restrict__ bias, const uint32_t* __restrict__ mpack,
    __nv_bfloat16* __restrict__ Ob)
{
    extern __shared__ char smem[];
    const uint32_t sb = smem_u32(smem);
    const uint32_t qsm  = sb + 64;
    const uint32_t kvsm = sb + 64 + 32768;
    // barriers: full0 @+0, full1 @+8, empty0 @+16, empty1 @+24, qbar @+32
    const int tid  = threadIdx.x;
    const int wid  = tid >> 5;
    const int lane = tid & 31;
    const int h  = blockIdx.y;
    const int qb = blockIdx.x;
    const int q0 = qb * 128;

    const char* Qsrc  = (const char*)Qb + ((size_t)qb * 16 + h) * 32768;
    const char* KVsrc = (const char*)KVb + (size_t)h * 32 * 32768;

    if (tid == 0) {
        MBARRIER_INIT(sb + 0, 1);
        MBARRIER_INIT(sb + 8, 1);
        MBARRIER_INIT(sb + 16, 256);
        MBARRIER_INIT(sb + 24, 256);
        MBARRIER_INIT(sb + 32, 1);
        FENCE_PROXY_ASYNC();
    }
    __syncthreads();

    if (tid == 0) {
        MBARRIER_EXPECT_TX(sb + 32, 32768);
        bulk_g2s(qsm, Qsrc, 32768, sb + 32);
#pragma unroll
        for (int i = 0; i < 2; i++) {
            MBARRIER_EXPECT_TX(sb + 8 * i, 32768);
            bulk_g2s(kvsm + i * 32768, KVsrc + (size_t)i * 32768, 32768, sb + 8 * i);
        }
    }

    float Oacc[8][4];
#pragma unroll
    for (int i = 0; i < 8; i++)
#pragma unroll
        for (int j = 0; j < 4; j++) Oacc[i][j] = 0.0f;
    float m0 = -1e30f, m1 = -1e30f, l0 = 0.0f, l1 = 0.0f;

    const int r = lane >> 2;
    const int grow0 = q0 + wid * 16 + r;
    const int grow1 = grow0 + 8;
    const float* brow0 = bias + (size_t)grow0 * (H_NUM * S_LEN) + (size_t)h * S_LEN;
    const float* brow1 = bias + (size_t)grow1 * (H_NUM * S_LEN) + (size_t)h * S_LEN;
    const uint32_t* mp0 = mpack + grow0 * (S_LEN / 32);
    const uint32_t* mp1 = mpack + grow1 * (S_LEN / 32);
    const int cbase = (lane & 3) * 2;
    const int qrow = wid * 16 + (lane & 15);
    const int qsel = (lane >> 4) * 16;

    MBARRIER_WAIT_PARITY(sb + 32, 0);

    for (int t = 0; t < S_LEN / 64; t++) {
        const int s = t & 1;
        const int ph = (t >> 1) & 1;
        MBARRIER_WAIT_PARITY(sb + 8 * s, ph);
        const uint32_t base = kvsm + s * 32768;
        const int j0 = t * 64;

        uint2 mwa = *(const uint2*)(mp0 + (j0 >> 5));
        uint2 mwb = *(const uint2*)(mp1 + (j0 >> 5));
        uint64_t sm0 = (((uint64_t)mwa.y << 32) | mwa.x) >> cbase;
        uint64_t sm1 = (((uint64_t)mwb.y << 32) | mwb.x) >> cbase;

        float acc[8][4];
#pragma unroll
        for (int i = 0; i < 8; i++)
#pragma unroll
            for (int j = 0; j < 4; j++) acc[i][j] = 0.0f;

#pragma unroll
        for (int kc = 0; kc < 4; kc++) {
            uint32_t qh[4], ql[4];
            uint32_t qoff = SMEM_SWZ((uint32_t)(qrow * 128 + kc * 32 + qsel));
            ldsm4(qh, qsm + qoff);
            ldsm4(ql, qsm + 16384 + qoff);
#pragma unroll
            for (int np = 0; np < 4; np++) {
                int krow = np * 16 + (lane >> 4) * 8 + (lane & 7);
                uint32_t koff = SMEM_SWZ((uint32_t)(krow * 128 + kc * 32 + ((lane >> 3) & 1) * 16));
                uint32_t bh[4], bl[4];
                ldsm4(bh, base + koff);
                ldsm4(bl, base + 8192 + koff);
                mma16816(acc[2 * np],     qh, bh + 0);
                mma16816(acc[2 * np],     qh, bl + 0);
                mma16816(acc[2 * np],     ql, bh + 0);
                mma16816(acc[2 * np + 1], qh, bh + 2);
                mma16816(acc[2 * np + 1], qh, bl + 2);
                mma16816(acc[2 * np + 1], ql, bh + 2);
            }
        }

        float mx0 = -1e30f, mx1 = -1e30f;
#pragma unroll
        for (int nt = 0; nt < 8; nt++) {
            int c = nt * 8 + cbase;
            float2 b0 = *(const float2*)(brow0 + j0 + c);
            float2 b1 = *(const float2*)(brow1 + j0 + c);
            uint32_t w0 = (uint32_t)(sm0 >> (nt * 8));
            uint32_t w1 = (uint32_t)(sm1 >> (nt * 8));
            acc[nt][0] = (w0 & 1u) ? fmaf(b0.x, LOG2E, acc[nt][0]) : -1e30f;
            acc[nt][1] = (w0 & 2u) ? fmaf(b0.y, LOG2E, acc[nt][1]) : -1e30f;
            acc[nt][2] = (w1 & 1u) ? fmaf(b1.x, LOG2E, acc[nt][2]) : -1e30f;
            acc[nt][3] = (w1 & 2u) ? fmaf(b1.y, LOG2E, acc[nt][3]) : -1e30f;
            mx0 = fmaxf(mx0, fmaxf(acc[nt][0], acc[nt][1]));
            mx1 = fmaxf(mx1, fmaxf(acc[nt][2], acc[nt][3]));
        }
        mx0 = fmaxf(mx0, __shfl_xor_sync(0xffffffffu, mx0, 1));
        mx0 = fmaxf(mx0, __shfl_xor_sync(0xffffffffu, mx0, 2));
        mx1 = fmaxf(mx1, __shfl_xor_sync(0xffffffffu, mx1, 1));
        mx1 = fmaxf(mx1, __shfl_xor_sync(0xffffffffu, mx1, 2));

        float mn0 = fmaxf(m0, mx0), mn1 = fmaxf(m1, mx1);
        float a0 = ex2(m0 - mn0), a1 = ex2(m1 - mn1);
        m0 = mn0; m1 = mn1;

        float s0 = 0.0f, s1 = 0.0f;
#pragma unroll
        for (int nt = 0; nt < 8; nt++) {
            acc[nt][0] = ex2(acc[nt][0] - mn0);
            acc[nt][1] = ex2(acc[nt][1] - mn0);
            acc[nt][2] = ex2(acc[nt][2] - mn1);
            acc[nt][3] = ex2(acc[nt][3] - mn1);
            s0 += acc[nt][0] + acc[nt][1];
            s1 += acc[nt][2] + acc[nt][3];
        }
        s0 += __shfl_xor_sync(0xffffffffu, s0, 1);
        s0 += __shfl_xor_sync(0xffffffffu, s0, 2);
        s1 += __shfl_xor_sync(0xffffffffu, s1, 1);
        s1 += __shfl_xor_sync(0xffffffffu, s1, 2);
        l0 = l0 * a0 + s0;
        l1 = l1 * a1 + s1;

#pragma unroll
        for (int nt = 0; nt < 8; nt++) {
            Oacc[nt][0] *= a0; Oacc[nt][1] *= a0;
            Oacc[nt][2] *= a1; Oacc[nt][3] *= a1;
        }

#pragma unroll
        for (int kc = 0; kc < 4; kc++) {
            uint32_t pha[4], pla[4];
            split2(acc[2 * kc][0],     acc[2 * kc][1],     pha[0], pla[0]);
            split2(acc[2 * kc][2],     acc[2 * kc][3],     pha[1], pla[1]);
            split2(acc[2 * kc + 1][0], acc[2 * kc + 1][1], pha[2], pla[2]);
            split2(acc[2 * kc + 1][2], acc[2 * kc + 1][3], pha[3], pla[3]);
#pragma unroll
            for (int dp = 0; dp < 4; dp++) {
                int vrow = kc * 16 + (lane & 15);
                uint32_t voff = SMEM_SWZ((uint32_t)(vrow * 128 + dp * 32 + (lane >> 4) * 16));
                uint32_t vh[4], vl[4];
                ldsm4t(vh, base + 16384 + voff);
                ldsm4t(vl, base + 24576 + voff);
                mma16816(Oacc[2 * dp],     pha, vh + 0);
                mma16816(Oacc[2 * dp],     pla, vh + 0);
                mma16816(Oacc[2 * dp],     pha, vl + 0);
                mma16816(Oacc[2 * dp + 1], pha, vh + 2);
                mma16816(Oacc[2 * dp + 1], pla, vh + 2);
                mma16816(Oacc[2 * dp + 1], pha, vl + 2);
            }
        }

        // done reading stage s for this tile: arrive on its empty barrier
        MBARRIER_ARRIVE(sb + 16 + 8 * s);

        // producer (warp 0 / lane 0 path): refill stage s for tile t+2 once
        // all 256 threads have arrived (round t>>1, parity (t>>1)&1)
        if (t + 2 < S_LEN / 64 && tid == 0) {
            MBARRIER_WAIT_PARITY(sb + 16 + 8 * s, ph);
            MBARRIER_EXPECT_TX(sb + 8 * s, 32768);
            bulk_g2s(kvsm + s * 32768, KVsrc + (size_t)(t + 2) * 32768, 32768, sb + 8 * s);
        }
    }

    float inv0 = 1.0f / l0, inv1 = 1.0f / l1;
    char* outb = (char*)Ob + ((size_t)qb * 16 + h) * 32768;
    const int r128 = wid * 16 + r;
#pragma unroll
    for (int nt = 0; nt < 8; nt++) {
        int d = nt * 8 + cbase;
        float v0 = Oacc[nt][0] * inv0, v1 = Oacc[nt][1] * inv0;
        float v2 = Oacc[nt][2] * inv1, v3 = Oacc[nt][3] * inv1;
        uint32_t h01, l01, h23, l23;
        split2(v0, v1, h01, l01);
        split2(v2, v3, h23, l23);
        uint32_t o0 = SMEM_SWZ((uint32_t)(r128 * 128 + d * 2));
        uint32_t o1 = SMEM_SWZ((uint32_t)((r128 + 8) * 128 + d * 2));
        *(uint32_t*)(outb + o0) = h01; *(uint32_t*)(outb + 16384 + o0) = l01;
        *(uint32_t*)(outb + o1) = h23; *(uint32_t*)(outb + 16384 + o1) = l23;
    }
}

// ---------------------------------------------------------------------------
// LayerNorm
// ---------------------------------------------------------------------------
__device__ __forceinline__ float block_reduce_sum(float v) {
    __shared__ float red[8];
    int lane = threadIdx.x & 31, w = threadIdx.x >> 5;
#pragma unroll
    for (int o = 16; o > 0; o >>= 1) v += __shfl_xor_sync(0xffffffffu, v, o);
    __syncthreads();
    if (lane == 0) red[w] = v;
    __syncthreads();
    float t = 0.0f;
#pragma unroll
    for (int i = 0; i < 8; i++) t += red[i];
    return t;
}

__global__ __launch_bounds__(256) void ln_kernel(
    const float* __restrict__ res, const float* __restrict__ w,
    const float* __restrict__ b, float* __restrict__ out)
{
    int row = blockIdx.x;
    int tid = threadIdx.x;
    const float* r = res + (size_t)row * D_DIM;

    float4 x4 = *(const float4*)(r + tid * 4);
    float sum = x4.x + x4.y + x4.z + x4.w;
    sum = block_reduce_sum(sum);
    float mean = sum * (1.0f / D_DIM);

    float d0 = x4.x - mean, d1 = x4.y - mean, d2 = x4.z - mean, d3 = x4.w - mean;
    float sq = d0 * d0 + d1 * d1 + d2 * d2 + d3 * d3;
    sq = block_reduce_sum(sq);
    float inv = rsqrtf(sq * (1.0f / D_DIM) + LN_EPS);

    float4 w4 = *(const float4*)(w + tid * 4);
    float4 b4 = *(const float4*)(b + tid * 4);
    float4 o4;
    o4.x = d0 * inv * w4.x + b4.x;
    o4.y = d1 * inv * w4.y + b4.y;
    o4.z = d2 * inv * w4.z + b4.z;
    o4.w = d3 * inv * w4.w + b4.w;
    *(float4*)(out + (size_t)row * D_DIM + tid * 4) = o4;
}

// ---------------------------------------------------------------------------
// Launch
// ---------------------------------------------------------------------------
extern "C" void kernel_launch(void* const* d_in, const int* in_sizes, int n_in,
                              void* d_out, int out_size)
{
    (void)in_sizes; (void)n_in; (void)out_size;

    const float*        x    = (const float*)d_in[0];
    const float*        bias = (const float*)d_in[1];
    const unsigned int* mask = (const unsigned int*)d_in[2];
    const float*        Wq   = (const float*)d_in[3];
    const float*        Wk   = (const float*)d_in[4];
    const float*        Wv   = (const float*)d_in[5];
    const float*        Wo   = (const float*)d_in[6];
    const float*        lnw  = (const float*)d_in[7];
    const float*        lnb  = (const float*)d_in[8];
    float*              out  = (float*)d_out;

    void *pxb, *pwq, *pwk, *pwv, *pwo, *pqb, *pkv, *pab, *pres, *pmp;
    cudaGetSymbolAddress(&pxb, g_xb);
    cudaGetSymbolAddress(&pwq, g_wqb);
    cudaGetSymbolAddress(&pwk, g_wkb);
    cudaGetSymbolAddress(&pwv, g_wvb);
    cudaGetSymbolAddress(&pwo, g_wob);
    cudaGetSymbolAddress(&pqb, g_qb);
    cudaGetSymbolAddress(&pkv, g_kvb);
    cudaGetSymbolAddress(&pab, g_ab);
    cudaGetSymbolAddress(&pres, g_res);
    cudaGetSymbolAddress(&pmp, g_mpack);

    __nv_bfloat16 *xb = (__nv_bfloat16*)pxb;
    __nv_bfloat16 *wqb = (__nv_bfloat16*)pwq, *wkb = (__nv_bfloat16*)pwk;
    __nv_bfloat16 *wvb = (__nv_bfloat16*)pwv, *wob = (__nv_bfloat16*)pwo;
    __nv_bfloat16 *qb = (__nv_bfloat16*)pqb, *kvb = (__nv_bfloat16*)pkv;
    __nv_bfloat16 *ab = (__nv_bfloat16*)pab;
    float* res = (float*)pres;
    uint32_t* mp = (uint32_t*)pmp;

    cudaFuncSetAttribute(gemm_blob_kernel, cudaFuncAttributeMaxDynamicSharedMemorySize, GEMM_SMEM);
    cudaFuncSetAttribute(attn_blob_kernel, cudaFuncAttributeMaxDynamicSharedMemorySize, ATT_SMEM);

    dim3 gt(D_DIM / 128, S_LEN / 128);   // (8, 16)

    split_all_kernel<<<3072, 256>>>(x, Wq, Wk, Wv, Wo, xb, wqb, wkb, wvb, wob);
    pack_mask_kernel<<<S_LEN, 256>>>(mask, mp);

    gemm_blob_kernel<<<gt, 256, GEMM_SMEM>>>(xb, wqb, nullptr, nullptr, qb,
                                             1, 0.125f * LOG2E, D_DIM, D_DIM);
    gemm_blob_kernel<<<gt, 256, GEMM_SMEM>>>(xb, wkb, nullptr, nullptr, kvb,
                                             2, 1.0f, D_DIM, D_DIM);
    gemm_blob_kernel<<<gt, 256, GEMM_SMEM>>>(xb, wvb, nullptr, nullptr, kvb,
                                             3, 1.0f, D_DIM, D_DIM);

    attn_blob_kernel<<<dim3(S_LEN / 128, H_NUM), 256, ATT_SMEM>>>(qb, kvb, bias, mp, ab);

    gemm_blob_kernel<<<gt, 256, GEMM_SMEM>>>(ab, wob, x, res, nullptr,
                                             0, 1.0f, D_DIM, D_DIM);

    ln_kernel<<<S_LEN, 256>>>(res, lnw, lnb, out);
}

// round 11
// speedup vs baseline: 1.7020x; 1.1939x over previous
#include <cuda_runtime.h>
#include <cuda_fp16.h>
#include <cstdint>

// Problem constants
#define S_LEN 2048
#define D_DIM 1024
#define H_NUM 16
#define DH 64
#define LN_EPS 1e-5f
#define LOG2E 1.4426950408889634f

// ---------------------------------------------------------------------------
// PTX helpers
// ---------------------------------------------------------------------------
__device__ __forceinline__ uint32_t smem_u32(const void* p) {
    uint32_t a;
    asm("{ .reg .u64 t; cvta.to.shared.u64 t, %1; cvt.u32.u64 %0, t; }"
        : "=r"(a) : "l"(p));
    return a;
}

__device__ __forceinline__ void ldsm4(uint32_t* r, uint32_t a) {
    asm volatile("ldmatrix.sync.aligned.m8n8.x4.shared.b16 {%0,%1,%2,%3}, [%4];"
                 : "=r"(r[0]), "=r"(r[1]), "=r"(r[2]), "=r"(r[3]) : "r"(a));
}
__device__ __forceinline__ void ldsm4t(uint32_t* r, uint32_t a) {
    asm volatile("ldmatrix.sync.aligned.m8n8.x4.trans.shared.b16 {%0,%1,%2,%3}, [%4];"
                 : "=r"(r[0]), "=r"(r[1]), "=r"(r[2]), "=r"(r[3]) : "r"(a));
}

// fp16 MMA, fp32 accumulate
__device__ __forceinline__ void mma16816(float* c, const uint32_t* a, const uint32_t* b) {
    asm volatile("mma.sync.aligned.m16n8k16.row.col.f32.f16.f16.f32 "
                 "{%0,%1,%2,%3}, {%4,%5,%6,%7}, {%8,%9}, {%0,%1,%2,%3};"
                 : "+f"(c[0]), "+f"(c[1]), "+f"(c[2]), "+f"(c[3])
                 : "r"(a[0]), "r"(a[1]), "r"(a[2]), "r"(a[3]),
                   "r"(b[0]), "r"(b[1]));
}

#define MBARRIER_INIT(addr, cnt) \
    asm volatile("mbarrier.init.shared.b64 [%0], %1;" :: "r"((uint32_t)(addr)), "r"((uint32_t)(cnt)) : "memory")

#define MBARRIER_EXPECT_TX(addr, tx) \
    asm volatile("mbarrier.arrive.expect_tx.shared.b64 _, [%0], %1;" \
                 :: "r"((uint32_t)(addr)), "r"((uint32_t)(tx)) : "memory")

#define MBARRIER_ARRIVE(addr) \
    asm volatile("mbarrier.arrive.shared.b64 _, [%0];" \
                 :: "r"((uint32_t)(addr)) : "memory")

#define MBARRIER_WAIT_PARITY(mbar_smem_addr, phase_parity) do { \
    uint32_t _mbar = (uint32_t)(mbar_smem_addr); \
    uint32_t _parity = (uint32_t)(phase_parity); \
    uint32_t _done; \
    asm volatile("{\n\t.reg .pred p;\n\t" \
        "mbarrier.try_wait.parity.acquire.cta.shared::cta.b64 p, [%1], %2;\n\t" \
        "selp.b32 %0, 1, 0, p;\n\t}" \
        : "=r"(_done) : "r"(_mbar), "r"(_parity) : "memory"); \
    if (!_done) { \
        asm volatile("{\n\t.reg .pred P1;\n\t" \
            "WAIT_LOOP_%=:\n\t" \
            "mbarrier.try_wait.parity.acquire.cta.shared::cta.b64 P1, [%0], %1, 0x989680;\n\t" \
            "@P1 bra.uni WAIT_DONE_%=;\n\t" \
            "bra.uni WAIT_LOOP_%=;\n\t" \
            "WAIT_DONE_%=:\n\t}" \
            :: "r"(_mbar), "r"(_parity) : "memory"); \
    } \
} while (0)

__device__ __forceinline__ void bulk_g2s(uint32_t dst, const void* src, uint32_t bytes, uint32_t mbar) {
    asm volatile("cp.async.bulk.shared::cluster.global.mbarrier::complete_tx::bytes "
                 "[%0], [%1], %2, [%3];"
                 :: "r"(dst), "l"(src), "r"(bytes), "r"(mbar) : "memory");
}

#define FENCE_PROXY_ASYNC() asm volatile("fence.proxy.async.shared::cta;" ::: "memory")

#define SMEM_SWZ(off) ((off) ^ (((off) >> 3) & 0x70))

__device__ __forceinline__ uint32_t packh2(float a, float b) {
    __half2 t = __floats2half2_rn(a, b);
    return *reinterpret_cast<uint32_t*>(&t);
}
// fp16 hi/lo split
__device__ __forceinline__ void split2(float a, float b, uint32_t& hi, uint32_t& lo) {
    __half2 h = __floats2half2_rn(a, b);
    float2 hf = __half22float2(h);
    hi = *reinterpret_cast<uint32_t*>(&h);
    lo = packh2(a - hf.x, b - hf.y);
}
__device__ __forceinline__ float ex2(float x) {
    float y; asm("ex2.approx.ftz.f32 %0, %1;" : "=f"(y) : "f"(x)); return y;
}

// ---------------------------------------------------------------------------
// Scratch (device globals)
//  x blob  : [mb][ch] 32KB {hi 16KB, lo 16KB}
//  W blobs : [nb][ch] 16KB {hi only}
//  Q blob  : [qb][head] 32KB {Qh, Ql}
//  KV blob : [head][tile] 16KB {Kh 8KB, Vh 8KB}
//  A blob  : [mb][head] 32KB {hi, lo}  (attention output)
// ---------------------------------------------------------------------------
__device__ __align__(128) __half g_xb [2 * S_LEN * D_DIM];
__device__ __align__(128) __half g_wqb[D_DIM * D_DIM];
__device__ __align__(128) __half g_wkb[D_DIM * D_DIM];
__device__ __align__(128) __half g_wvb[D_DIM * D_DIM];
__device__ __align__(128) __half g_wob[D_DIM * D_DIM];
__device__ __align__(128) __half g_qb [2 * S_LEN * D_DIM];
__device__ __align__(128) __half g_kvb[2 * S_LEN * D_DIM];
__device__ __align__(128) __half g_ab [2 * S_LEN * D_DIM];
__device__ float g_res[S_LEN * D_DIM];
__device__ __align__(8) uint32_t g_mpack[S_LEN * (S_LEN / 32)];

// ---------------------------------------------------------------------------
// Mask bit-pack
// ---------------------------------------------------------------------------
__global__ __launch_bounds__(256) void pack_mask_kernel(
    const unsigned int* __restrict__ mask, uint32_t* __restrict__ mp)
{
    int row = blockIdx.x;
    int w = threadIdx.x >> 5;
    int lane = threadIdx.x & 31;
#pragma unroll
    for (int i = 0; i < 8; i++) {
        int word = w * 8 + i;
        unsigned int v = mask[(size_t)row * S_LEN + word * 32 + lane];
        unsigned int bal = __ballot_sync(0xffffffffu, v != 0u);
        if (lane == 0) mp[row * 64 + word] = bal;
    }
}

// ---------------------------------------------------------------------------
// Fused split: x -> hi/lo 32KB blocks; W -> hi-only 16KB blocks.
// ---------------------------------------------------------------------------
__global__ __launch_bounds__(256) void split_all_kernel(
    const float* __restrict__ x,
    const float* __restrict__ Wq, const float* __restrict__ Wk,
    const float* __restrict__ Wv, const float* __restrict__ Wo,
    __half* __restrict__ xb,
    __half* __restrict__ wqb, __half* __restrict__ wkb,
    __half* __restrict__ wvb, __half* __restrict__ wob)
{
    int bid = blockIdx.x;
    const float* src;
    __half* dst;
    int lbid;
    bool isx = (bid < 1024);
    if (isx) { src = x; dst = xb; lbid = bid; }
    else {
        int w = (bid - 1024) >> 9;
        lbid = (bid - 1024) & 511;
        src = (w == 0) ? Wq : (w == 1) ? Wk : (w == 2) ? Wv : Wo;
        dst = (w == 0) ? wqb : (w == 1) ? wkb : (w == 2) ? wvb : wob;
    }
    int idx = lbid * 256 + threadIdx.x;
    int row = idx >> 7;
    int k   = (idx & 127) * 8;

    float4 v0 = *(const float4*)(src + (size_t)row * D_DIM + k);
    float4 v1 = *(const float4*)(src + (size_t)row * D_DIM + k + 4);

    uint4 hi, lo;
    uint32_t h, l;
    split2(v0.x, v0.y, h, l); hi.x = h; lo.x = l;
    split2(v0.z, v0.w, h, l); hi.y = h; lo.y = l;
    split2(v1.x, v1.y, h, l); hi.z = h; lo.z = l;
    split2(v1.z, v1.w, h, l); hi.w = h; lo.w = l;

    uint32_t off = SMEM_SWZ((uint32_t)((row & 127) * 128 + (k & 63) * 2));
    if (isx) {
        size_t base = ((size_t)(row >> 7) * 16 + (k >> 6)) * 32768;
        char* p = (char*)dst + base;
        *(uint4*)(p + off) = hi;
        *(uint4*)(p + 16384 + off) = lo;
    } else {
        size_t base = ((size_t)(row >> 7) * 16 + (k >> 6)) * 16384;
        *(uint4*)((char*)dst + base + off) = hi;
    }
}

// ---------------------------------------------------------------------------
// Blob GEMM: 128x128, BK=64, 3-stage. 2-pass fp16: Ah.Bh + Al.Bh.
// Stage = A{hi,lo} 32KB + Bh 16KB = 48KB.
// modes: 0 = fp32 (+resid); 1 = Q blob; 2 = K blob; 3 = V blob
// ---------------------------------------------------------------------------
#define GSTAGE 49152
#define GEMM_SMEM (64 + 3 * GSTAGE)

__global__ __launch_bounds__(256) void gemm_blob_kernel(
    const __half* __restrict__ Ablob, const __half* __restrict__ Bblob,
    const float* __restrict__ resid, float* __restrict__ Cf,
    __half* __restrict__ OutB, int mode, float scale, int N, int K)
{
    extern __shared__ char smem[];
    const uint32_t sb = smem_u32(smem);
    const int tid  = threadIdx.x;
    const int wid  = tid >> 5;
    const int lane = tid & 31;
    const int wm   = wid >> 2;
    const int wn   = wid & 3;

    const int mb = blockIdx.y, nb = blockIdx.x;
    const int m0 = mb * 128, n0 = nb * 128;
    const int NCH = K >> 6;

    const char* Asrc = (const char*)Ablob + (size_t)mb * NCH * 32768;
    const char* Bsrc = (const char*)Bblob + (size_t)nb * NCH * 16384;

    if (tid == 0) {
        MBARRIER_INIT(sb + 0, 1);
        MBARRIER_INIT(sb + 8, 1);
        MBARRIER_INIT(sb + 16, 1);
        FENCE_PROXY_ASYNC();
    }
    __syncthreads();

    if (tid == 0) {
#pragma unroll
        for (int s = 0; s < 3; s++) {
            uint32_t mbar = sb + 8 * s;
            uint32_t dst = sb + 64 + s * GSTAGE;
            MBARRIER_EXPECT_TX(mbar, GSTAGE);
            bulk_g2s(dst,         Asrc + (size_t)s * 32768, 32768, mbar);
            bulk_g2s(dst + 32768, Bsrc + (size_t)s * 16384, 16384, mbar);
        }
    }

    float acc[4][4][4];
#pragma unroll
    for (int i = 0; i < 4; i++)
#pragma unroll
        for (int j = 0; j < 4; j++)
#pragma unroll
            for (int r = 0; r < 4; r++) acc[i][j][r] = 0.0f;

    const int arow = wm * 64 + (lane & 15);
    const int brow = wn * 32 + ((lane >> 4) & 1) * 8 + (lane & 7);

    for (int ch = 0; ch < NCH; ch++) {
        const int s = ch % 3;
        MBARRIER_WAIT_PARITY(sb + 8 * s, (ch / 3) & 1);

        const uint32_t bufA = sb + 64 + s * GSTAGE;
        const uint32_t bufB = bufA + 32768;

#pragma unroll
        for (int kc = 0; kc < 4; kc++) {
            uint32_t ah[4][4], alr[4][4], bh[4][2];
#pragma unroll
            for (int mt = 0; mt < 4; mt++) {
                uint32_t off = SMEM_SWZ((uint32_t)((arow + mt * 16) * 128 + kc * 32 + (lane >> 4) * 16));
                ldsm4(ah[mt],  bufA + off);
                ldsm4(alr[mt], bufA + 16384 + off);
            }
#pragma unroll
            for (int np = 0; np < 2; np++) {
                uint32_t off = SMEM_SWZ((uint32_t)((brow + np * 16) * 128 + kc * 32 + ((lane >> 3) & 1) * 16));
                uint32_t r[4];
                ldsm4(r, bufB + off);
                bh[np * 2][0] = r[0]; bh[np * 2][1] = r[1];
                bh[np * 2 + 1][0] = r[2]; bh[np * 2 + 1][1] = r[3];
            }
#pragma unroll
            for (int mt = 0; mt < 4; mt++)
#pragma unroll
                for (int nt = 0; nt < 4; nt++) {
                    mma16816(acc[mt][nt], ah[mt],  bh[nt]);
                    mma16816(acc[mt][nt], alr[mt], bh[nt]);
                }
        }
        __syncthreads();

        if (ch + 3 < NCH && tid == 0) {
            uint32_t mbar = sb + 8 * s;
            uint32_t dst = sb + 64 + s * GSTAGE;
            MBARRIER_EXPECT_TX(mbar, GSTAGE);
            bulk_g2s(dst,         Asrc + (size_t)(ch + 3) * 32768, 32768, mbar);
            bulk_g2s(dst + 32768, Bsrc + (size_t)(ch + 3) * 16384, 16384, mbar);
        }
    }

#pragma unroll
    for (int mt = 0; mt < 4; mt++) {
        int row = m0 + wm * 64 + mt * 16 + (lane >> 2);
#pragma unroll
        for (int nt = 0; nt < 4; nt++) {
            int col = n0 + wn * 32 + nt * 8 + (lane & 3) * 2;
            float v0 = acc[mt][nt][0] * scale;
            float v1 = acc[mt][nt][1] * scale;
            float v2 = acc[mt][nt][2] * scale;
            float v3 = acc[mt][nt][3] * scale;
            if (mode == 0) {
                if (resid) {
                    float2 r0 = *(const float2*)(resid + (size_t)row * N + col);
                    float2 r1 = *(const float2*)(resid + (size_t)(row + 8) * N + col);
                    v0 += r0.x; v1 += r0.y; v2 += r1.x; v3 += r1.y;
                }
                *(float2*)(Cf + (size_t)row * N + col) = make_float2(v0, v1);
                *(float2*)(Cf + (size_t)(row + 8) * N + col) = make_float2(v2, v3);
            } else if (mode == 1) {
                uint32_t h01, l01, h23, l23;
                split2(v0, v1, h01, l01);
                split2(v2, v3, h23, l23);
                size_t base = ((size_t)(row >> 7) * 16 + (col >> 6)) * 32768;
                uint32_t o0 = SMEM_SWZ((uint32_t)((row & 127) * 128 + (col & 63) * 2));
                uint32_t o1 = SMEM_SWZ((uint32_t)(((row + 8) & 127) * 128 + (col & 63) * 2));
                char* p = (char*)OutB + base;
                *(uint32_t*)(p + o0) = h01; *(uint32_t*)(p + 16384 + o0) = l01;
                *(uint32_t*)(p + o1) = h23; *(uint32_t*)(p + 16384 + o1) = l23;
            } else {
                // K (mode 2) / V (mode 3): hi only into 16KB {Kh,Vh} blocks
                size_t base = ((size_t)(col >> 6) * 32 + (row >> 6)) * 16384
                              + (mode == 3 ? 8192 : 0);
                uint32_t o0 = SMEM_SWZ((uint32_t)((row & 63) * 128 + (col & 63) * 2));
                uint32_t o1 = SMEM_SWZ((uint32_t)(((row + 8) & 63) * 128 + (col & 63) * 2));
                char* p = (char*)OutB + base;
                *(uint32_t*)(p + o0) = packh2(v0, v1);
                *(uint32_t*)(p + o1) = packh2(v2, v3);
            }
        }
    }
}

// ---------------------------------------------------------------------------
// Flash attention: fp16 2-pass, 4-stage 16KB KV ring, 2 CTAs/SM,
// warp-decoupled mbarrier full/empty pairs.
// ---------------------------------------------------------------------------
#define ATT_SMEM (128 + 32768 + 4 * 16384)

__global__ __launch_bounds__(256, 2) void attn_blob_kernel(
    const __half* __restrict__ Qb, const __half* __restrict__ KVb,
    const float* __restrict__ bias, const uint32_t* __restrict__ mpack,
    __half* __restrict__ Ob)
{
    extern __shared__ char smem[];
    const uint32_t sb = smem_u32(smem);
    // full[s] @ sb+8s (s=0..3), empty[s] @ sb+32+8s, qbar @ sb+64
    const uint32_t qsm  = sb + 128;
    const uint32_t kvsm = sb + 128 + 32768;
    const int tid  = threadIdx.x;
    const int wid  = tid >> 5;
    const int lane = tid & 31;
    const int h  = blockIdx.y;
    const int qb = blockIdx.x;
    const int q0 = qb * 128;

    const char* Qsrc  = (const char*)Qb + ((size_t)qb * 16 + h) * 32768;
    const char* KVsrc = (const char*)KVb + (size_t)h * 32 * 16384;

    if (tid == 0) {
#pragma unroll
        for (int i = 0; i < 4; i++) {
            MBARRIER_INIT(sb + 8 * i, 1);
            MBARRIER_INIT(sb + 32 + 8 * i, 256);
        }
        MBARRIER_INIT(sb + 64, 1);
        FENCE_PROXY_ASYNC();
    }
    __syncthreads();

    if (tid == 0) {
        MBARRIER_EXPECT_TX(sb + 64, 32768);
        bulk_g2s(qsm, Qsrc, 32768, sb + 64);
#pragma unroll
        for (int i = 0; i < 4; i++) {
            MBARRIER_EXPECT_TX(sb + 8 * i, 16384);
            bulk_g2s(kvsm + i * 16384, KVsrc + (size_t)i * 16384, 16384, sb + 8 * i);
        }
    }

    float Oacc[8][4];
#pragma unroll
    for (int i = 0; i < 8; i++)
#pragma unroll
        for (int j = 0; j < 4; j++) Oacc[i][j] = 0.0f;
    float m0 = -1e30f, m1 = -1e30f, l0 = 0.0f, l1 = 0.0f;

    const int r = lane >> 2;
    const int grow0 = q0 + wid * 16 + r;
    const int grow1 = grow0 + 8;
    const float* brow0 = bias + (size_t)grow0 * (H_NUM * S_LEN) + (size_t)h * S_LEN;
    const float* brow1 = bias + (size_t)grow1 * (H_NUM * S_LEN) + (size_t)h * S_LEN;
    const uint32_t* mp0 = mpack + grow0 * (S_LEN / 32);
    const uint32_t* mp1 = mpack + grow1 * (S_LEN / 32);
    const int cbase = (lane & 3) * 2;
    const int qrow = wid * 16 + (lane & 15);
    const int qsel = (lane >> 4) * 16;

    MBARRIER_WAIT_PARITY(sb + 64, 0);

    for (int t = 0; t < S_LEN / 64; t++) {
        const int s = t & 3;
        const int ph = (t >> 2) & 1;
        MBARRIER_WAIT_PARITY(sb + 8 * s, ph);
        const uint32_t base = kvsm + s * 16384;   // Kh @ +0, Vh @ +8192
        const int j0 = t * 64;

        uint2 mwa = *(const uint2*)(mp0 + (j0 >> 5));
        uint2 mwb = *(const uint2*)(mp1 + (j0 >> 5));
        uint64_t sm0 = (((uint64_t)mwa.y << 32) | mwa.x) >> cbase;
        uint64_t sm1 = (((uint64_t)mwb.y << 32) | mwb.x) >> cbase;

        float acc[8][4];
#pragma unroll
        for (int i = 0; i < 8; i++)
#pragma unroll
            for (int j = 0; j < 4; j++) acc[i][j] = 0.0f;

#pragma unroll
        for (int kc = 0; kc < 4; kc++) {
            uint32_t qh[4], ql[4];
            uint32_t qoff = SMEM_SWZ((uint32_t)(qrow * 128 + kc * 32 + qsel));
            ldsm4(qh, qsm + qoff);
            ldsm4(ql, qsm + 16384 + qoff);
#pragma unroll
            for (int np = 0; np < 4; np++) {
                int krow = np * 16 + (lane >> 4) * 8 + (lane & 7);
                uint32_t koff = SMEM_SWZ((uint32_t)(krow * 128 + kc * 32 + ((lane >> 3) & 1) * 16));
                uint32_t bh[4];
                ldsm4(bh, base + koff);
                mma16816(acc[2 * np],     qh, bh + 0);
                mma16816(acc[2 * np],     ql, bh + 0);
                mma16816(acc[2 * np + 1], qh, bh + 2);
                mma16816(acc[2 * np + 1], ql, bh + 2);
            }
        }

        float mx0 = -1e30f, mx1 = -1e30f;
#pragma unroll
        for (int nt = 0; nt < 8; nt++) {
            int c = nt * 8 + cbase;
            float2 b0 = *(const float2*)(brow0 + j0 + c);
            float2 b1 = *(const float2*)(brow1 + j0 + c);
            uint32_t w0 = (uint32_t)(sm0 >> (nt * 8));
            uint32_t w1 = (uint32_t)(sm1 >> (nt * 8));
            acc[nt][0] = (w0 & 1u) ? fmaf(b0.x, LOG2E, acc[nt][0]) : -1e30f;
            acc[nt][1] = (w0 & 2u) ? fmaf(b0.y, LOG2E, acc[nt][1]) : -1e30f;
            acc[nt][2] = (w1 & 1u) ? fmaf(b1.x, LOG2E, acc[nt][2]) : -1e30f;
            acc[nt][3] = (w1 & 2u) ? fmaf(b1.y, LOG2E, acc[nt][3]) : -1e30f;
            mx0 = fmaxf(mx0, fmaxf(acc[nt][0], acc[nt][1]));
            mx1 = fmaxf(mx1, fmaxf(acc[nt][2], acc[nt][3]));
        }
        mx0 = fmaxf(mx0, __shfl_xor_sync(0xffffffffu, mx0, 1));
        mx0 = fmaxf(mx0, __shfl_xor_sync(0xffffffffu, mx0, 2));
        mx1 = fmaxf(mx1, __shfl_xor_sync(0xffffffffu, mx1, 1));
        mx1 = fmaxf(mx1, __shfl_xor_sync(0xffffffffu, mx1, 2));

        float mn0 = fmaxf(m0, mx0), mn1 = fmaxf(m1, mx1);
        float a0 = ex2(m0 - mn0), a1 = ex2(m1 - mn1);
        m0 = mn0; m1 = mn1;

        float s0 = 0.0f, s1 = 0.0f;
#pragma unroll
        for (int nt = 0; nt < 8; nt++) {
            acc[nt][0] = ex2(acc[nt][0] - mn0);
            acc[nt][1] = ex2(acc[nt][1] - mn0);
            acc[nt][2] = ex2(acc[nt][2] - mn1);
            acc[nt][3] = ex2(acc[nt][3] - mn1);
            s0 += acc[nt][0] + acc[nt][1];
            s1 += acc[nt][2] + acc[nt][3];
        }
        s0 += __shfl_xor_sync(0xffffffffu, s0, 1);
        s0 += __shfl_xor_sync(0xffffffffu, s0, 2);
        s1 += __shfl_xor_sync(0xffffffffu, s1, 1);
        s1 += __shfl_xor_sync(0xffffffffu, s1, 2);
        l0 = l0 * a0 + s0;
        l1 = l1 * a1 + s1;

#pragma unroll
        for (int nt = 0; nt < 8; nt++) {
            Oacc[nt][0] *= a0; Oacc[nt][1] *= a0;
            Oacc[nt][2] *= a1; Oacc[nt][3] *= a1;
        }

#pragma unroll
        for (int kc = 0; kc < 4; kc++) {
            uint32_t pha[4], pla[4];
            split2(acc[2 * kc][0],     acc[2 * kc][1],     pha[0], pla[0]);
            split2(acc[2 * kc][2],     acc[2 * kc][3],     pha[1], pla[1]);
            split2(acc[2 * kc + 1][0], acc[2 * kc + 1][1], pha[2], pla[2]);
            split2(acc[2 * kc + 1][2], acc[2 * kc + 1][3], pha[3], pla[3]);
#pragma unroll
            for (int dp = 0; dp < 4; dp++) {
                int vrow = kc * 16 + (lane & 15);
                uint32_t voff = SMEM_SWZ((uint32_t)(vrow * 128 + dp * 32 + (lane >> 4) * 16));
                uint32_t vh[4];
                ldsm4t(vh, base + 8192 + voff);
                mma16816(Oacc[2 * dp],     pha, vh + 0);
                mma16816(Oacc[2 * dp],     pla, vh + 0);
                mma16816(Oacc[2 * dp + 1], pha, vh + 2);
                mma16816(Oacc[2 * dp + 1], pla, vh + 2);
            }
        }

        MBARRIER_ARRIVE(sb + 32 + 8 * s);

        if (t + 4 < S_LEN / 64 && tid == 0) {
            MBARRIER_WAIT_PARITY(sb + 32 + 8 * s, ph);
            MBARRIER_EXPECT_TX(sb + 8 * s, 16384);
            bulk_g2s(kvsm + s * 16384, KVsrc + (size_t)(t + 4) * 16384, 16384, sb + 8 * s);
        }
    }

    float inv0 = 1.0f / l0, inv1 = 1.0f / l1;
    char* outb = (char*)Ob + ((size_t)qb * 16 + h) * 32768;
    const int r128 = wid * 16 + r;
#pragma unroll
    for (int nt = 0; nt < 8; nt++) {
        int d = nt * 8 + cbase;
        float v0 = Oacc[nt][0] * inv0, v1 = Oacc[nt][1] * inv0;
        float v2 = Oacc[nt][2] * inv1, v3 = Oacc[nt][3] * inv1;
        uint32_t h01, l01, h23, l23;
        split2(v0, v1, h01, l01);
        split2(v2, v3, h23, l23);
        uint32_t o0 = SMEM_SWZ((uint32_t)(r128 * 128 + d * 2));
        uint32_t o1 = SMEM_SWZ((uint32_t)((r128 + 8) * 128 + d * 2));
        *(uint32_t*)(outb + o0) = h01; *(uint32_t*)(outb + 16384 + o0) = l01;
        *(uint32_t*)(outb + o1) = h23; *(uint32_t*)(outb + 16384 + o1) = l23;
    }
}

// ---------------------------------------------------------------------------
// LayerNorm
// ---------------------------------------------------------------------------
__device__ __forceinline__ float block_reduce_sum(float v) {
    __shared__ float red[8];
    int lane = threadIdx.x & 31, w = threadIdx.x >> 5;
#pragma unroll
    for (int o = 16; o > 0; o >>= 1) v += __shfl_xor_sync(0xffffffffu, v, o);
    __syncthreads();
    if (lane == 0) red[w] = v;
    __syncthreads();
    float t = 0.0f;
#pragma unroll
    for (int i = 0; i < 8; i++) t += red[i];
    return t;
}

__global__ __launch_bounds__(256) void ln_kernel(
    const float* __restrict__ res, const float* __restrict__ w,
    const float* __restrict__ b, float* __restrict__ out)
{
    int row = blockIdx.x;
    int tid = threadIdx.x;
    const float* r = res + (size_t)row * D_DIM;

    float4 x4 = *(const float4*)(r + tid * 4);
    float sum = x4.x + x4.y + x4.z + x4.w;
    sum = block_reduce_sum(sum);
    float mean = sum * (1.0f / D_DIM);

    float d0 = x4.x - mean, d1 = x4.y - mean, d2 = x4.z - mean, d3 = x4.w - mean;
    float sq = d0 * d0 + d1 * d1 + d2 * d2 + d3 * d3;
    sq = block_reduce_sum(sq);
    float inv = rsqrtf(sq * (1.0f / D_DIM) + LN_EPS);

    float4 w4 = *(const float4*)(w + tid * 4);
    float4 b4 = *(const float4*)(b + tid * 4);
    float4 o4;
    o4.x = d0 * inv * w4.x + b4.x;
    o4.y = d1 * inv * w4.y + b4.y;
    o4.z = d2 * inv * w4.z + b4.z;
    o4.w = d3 * inv * w4.w + b4.w;
    *(float4*)(out + (size_t)row * D_DIM + tid * 4) = o4;
}

// ---------------------------------------------------------------------------
// Launch
// ---------------------------------------------------------------------------
extern "C" void kernel_launch(void* const* d_in, const int* in_sizes, int n_in,
                              void* d_out, int out_size)
{
    (void)in_sizes; (void)n_in; (void)out_size;

    const float*        x    = (const float*)d_in[0];
    const float*        bias = (const float*)d_in[1];
    const unsigned int* mask = (const unsigned int*)d_in[2];
    const float*        Wq   = (const float*)d_in[3];
    const float*        Wk   = (const float*)d_in[4];
    const float*        Wv   = (const float*)d_in[5];
    const float*        Wo   = (const float*)d_in[6];
    const float*        lnw  = (const float*)d_in[7];
    const float*        lnb  = (const float*)d_in[8];
    float*              out  = (float*)d_out;

    void *pxb, *pwq, *pwk, *pwv, *pwo, *pqb, *pkv, *pab, *pres, *pmp;
    cudaGetSymbolAddress(&pxb, g_xb);
    cudaGetSymbolAddress(&pwq, g_wqb);
    cudaGetSymbolAddress(&pwk, g_wkb);
    cudaGetSymbolAddress(&pwv, g_wvb);
    cudaGetSymbolAddress(&pwo, g_wob);
    cudaGetSymbolAddress(&pqb, g_qb);
    cudaGetSymbolAddress(&pkv, g_kvb);
    cudaGetSymbolAddress(&pab, g_ab);
    cudaGetSymbolAddress(&pres, g_res);
    cudaGetSymbolAddress(&pmp, g_mpack);

    __half *xb = (__half*)pxb;
    __half *wqb = (__half*)pwq, *wkb = (__half*)pwk;
    __half *wvb = (__half*)pwv, *wob = (__half*)pwo;
    __half *qb = (__half*)pqb, *kvb = (__half*)pkv;
    __half *ab = (__half*)pab;
    float* res = (float*)pres;
    uint32_t* mp = (uint32_t*)pmp;

    cudaFuncSetAttribute(gemm_blob_kernel, cudaFuncAttributeMaxDynamicSharedMemorySize, GEMM_SMEM);
    cudaFuncSetAttribute(attn_blob_kernel, cudaFuncAttributeMaxDynamicSharedMemorySize, ATT_SMEM);

    dim3 gt(D_DIM / 128, S_LEN / 128);   // (8, 16)

    split_all_kernel<<<3072, 256>>>(x, Wq, Wk, Wv, Wo, xb, wqb, wkb, wvb, wob);
    pack_mask_kernel<<<S_LEN, 256>>>(mask, mp);

    gemm_blob_kernel<<<gt, 256, GEMM_SMEM>>>(xb, wqb, nullptr, nullptr, qb,
                                             1, 0.125f * LOG2E, D_DIM, D_DIM);
    gemm_blob_kernel<<<gt, 256, GEMM_SMEM>>>(xb, wkb, nullptr, nullptr, kvb,
                                             2, 1.0f, D_DIM, D_DIM);
    gemm_blob_kernel<<<gt, 256, GEMM_SMEM>>>(xb, wvb, nullptr, nullptr, kvb,
                                             3, 1.0f, D_DIM, D_DIM);

    attn_blob_kernel<<<dim3(S_LEN / 128, H_NUM), 256, ATT_SMEM>>>(qb, kvb, bias, mp, ab);

    gemm_blob_kernel<<<gt, 256, GEMM_SMEM>>>(ab, wob, x, res, nullptr,
                                             0, 1.0f, D_DIM, D_DIM);

    ln_kernel<<<S_LEN, 256>>>(res, lnw, lnb, out);
}

// round 12
// speedup vs baseline: 1.9095x; 1.1219x over previous
#include <cuda_runtime.h>
#include <cuda_fp16.h>
#include <cstdint>

// Problem constants
#define S_LEN 2048
#define D_DIM 1024
#define H_NUM 16
#define DH 64
#define LN_EPS 1e-5f
#define LOG2E 1.4426950408889634f

// ---------------------------------------------------------------------------
// PTX helpers
// ---------------------------------------------------------------------------
__device__ __forceinline__ uint32_t smem_u32(const void* p) {
    uint32_t a;
    asm("{ .reg .u64 t; cvta.to.shared.u64 t, %1; cvt.u32.u64 %0, t; }"
        : "=r"(a) : "l"(p));
    return a;
}

__device__ __forceinline__ void ldsm4(uint32_t* r, uint32_t a) {
    asm volatile("ldmatrix.sync.aligned.m8n8.x4.shared.b16 {%0,%1,%2,%3}, [%4];"
                 : "=r"(r[0]), "=r"(r[1]), "=r"(r[2]), "=r"(r[3]) : "r"(a));
}
__device__ __forceinline__ void ldsm4t(uint32_t* r, uint32_t a) {
    asm volatile("ldmatrix.sync.aligned.m8n8.x4.trans.shared.b16 {%0,%1,%2,%3}, [%4];"
                 : "=r"(r[0]), "=r"(r[1]), "=r"(r[2]), "=r"(r[3]) : "r"(a));
}

// fp16 MMA, fp32 accumulate
__device__ __forceinline__ void mma16816(float* c, const uint32_t* a, const uint32_t* b) {
    asm volatile("mma.sync.aligned.m16n8k16.row.col.f32.f16.f16.f32 "
                 "{%0,%1,%2,%3}, {%4,%5,%6,%7}, {%8,%9}, {%0,%1,%2,%3};"
                 : "+f"(c[0]), "+f"(c[1]), "+f"(c[2]), "+f"(c[3])
                 : "r"(a[0]), "r"(a[1]), "r"(a[2]), "r"(a[3]),
                   "r"(b[0]), "r"(b[1]));
}

#define MBARRIER_INIT(addr, cnt) \
    asm volatile("mbarrier.init.shared.b64 [%0], %1;" :: "r"((uint32_t)(addr)), "r"((uint32_t)(cnt)) : "memory")

#define MBARRIER_EXPECT_TX(addr, tx) \
    asm volatile("mbarrier.arrive.expect_tx.shared.b64 _, [%0], %1;" \
                 :: "r"((uint32_t)(addr)), "r"((uint32_t)(tx)) : "memory")

#define MBARRIER_ARRIVE(addr) \
    asm volatile("mbarrier.arrive.shared.b64 _, [%0];" \
                 :: "r"((uint32_t)(addr)) : "memory")

#define MBARRIER_WAIT_PARITY(mbar_smem_addr, phase_parity) do { \
    uint32_t _mbar = (uint32_t)(mbar_smem_addr); \
    uint32_t _parity = (uint32_t)(phase_parity); \
    uint32_t _done; \
    asm volatile("{\n\t.reg .pred p;\n\t" \
        "mbarrier.try_wait.parity.acquire.cta.shared::cta.b64 p, [%1], %2;\n\t" \
        "selp.b32 %0, 1, 0, p;\n\t}" \
        : "=r"(_done) : "r"(_mbar), "r"(_parity) : "memory"); \
    if (!_done) { \
        asm volatile("{\n\t.reg .pred P1;\n\t" \
            "WAIT_LOOP_%=:\n\t" \
            "mbarrier.try_wait.parity.acquire.cta.shared::cta.b64 P1, [%0], %1, 0x989680;\n\t" \
            "@P1 bra.uni WAIT_DONE_%=;\n\t" \
            "bra.uni WAIT_LOOP_%=;\n\t" \
            "WAIT_DONE_%=:\n\t}" \
            :: "r"(_mbar), "r"(_parity) : "memory"); \
    } \
} while (0)

__device__ __forceinline__ void bulk_g2s(uint32_t dst, const void* src, uint32_t bytes, uint32_t mbar) {
    asm volatile("cp.async.bulk.shared::cluster.global.mbarrier::complete_tx::bytes "
                 "[%0], [%1], %2, [%3];"
                 :: "r"(dst), "l"(src), "r"(bytes), "r"(mbar) : "memory");
}

#define FENCE_PROXY_ASYNC() asm volatile("fence.proxy.async.shared::cta;" ::: "memory")

#define SMEM_SWZ(off) ((off) ^ (((off) >> 3) & 0x70))

__device__ __forceinline__ uint32_t packh2(float a, float b) {
    __half2 t = __floats2half2_rn(a, b);
    return *reinterpret_cast<uint32_t*>(&t);
}
// fp16 hi/lo split
__device__ __forceinline__ void split2(float a, float b, uint32_t& hi, uint32_t& lo) {
    __half2 h = __floats2half2_rn(a, b);
    float2 hf = __half22float2(h);
    hi = *reinterpret_cast<uint32_t*>(&h);
    lo = packh2(a - hf.x, b - hf.y);
}
__device__ __forceinline__ float ex2(float x) {
    float y; asm("ex2.approx.ftz.f32 %0, %1;" : "=f"(y) : "f"(x)); return y;
}

// ---------------------------------------------------------------------------
// Scratch (device globals)
// ---------------------------------------------------------------------------
__device__ __align__(128) __half g_xb [2 * S_LEN * D_DIM];
__device__ __align__(128) __half g_wqb[D_DIM * D_DIM];
__device__ __align__(128) __half g_wkb[D_DIM * D_DIM];
__device__ __align__(128) __half g_wvb[D_DIM * D_DIM];
__device__ __align__(128) __half g_wob[D_DIM * D_DIM];
__device__ __align__(128) __half g_qb [2 * S_LEN * D_DIM];
__device__ __align__(128) __half g_kvb[2 * S_LEN * D_DIM];
__device__ __align__(128) __half g_ab [2 * S_LEN * D_DIM];
__device__ float g_res[S_LEN * D_DIM];
__device__ __align__(8) uint32_t g_mpack[S_LEN * (S_LEN / 32)];

// ---------------------------------------------------------------------------
// Mask bit-pack
// ---------------------------------------------------------------------------
__global__ __launch_bounds__(256) void pack_mask_kernel(
    const unsigned int* __restrict__ mask, uint32_t* __restrict__ mp)
{
    int row = blockIdx.x;
    int w = threadIdx.x >> 5;
    int lane = threadIdx.x & 31;
#pragma unroll
    for (int i = 0; i < 8; i++) {
        int word = w * 8 + i;
        unsigned int v = mask[(size_t)row * S_LEN + word * 32 + lane];
        unsigned int bal = __ballot_sync(0xffffffffu, v != 0u);
        if (lane == 0) mp[row * 64 + word] = bal;
    }
}

// ---------------------------------------------------------------------------
// Fused split: x -> hi/lo 32KB blocks; W -> hi-only 16KB blocks.
// ---------------------------------------------------------------------------
__global__ __launch_bounds__(256) void split_all_kernel(
    const float* __restrict__ x,
    const float* __restrict__ Wq, const float* __restrict__ Wk,
    const float* __restrict__ Wv, const float* __restrict__ Wo,
    __half* __restrict__ xb,
    __half* __restrict__ wqb, __half* __restrict__ wkb,
    __half* __restrict__ wvb, __half* __restrict__ wob)
{
    int bid = blockIdx.x;
    const float* src;
    __half* dst;
    int lbid;
    bool isx = (bid < 1024);
    if (isx) { src = x; dst = xb; lbid = bid; }
    else {
        int w = (bid - 1024) >> 9;
        lbid = (bid - 1024) & 511;
        src = (w == 0) ? Wq : (w == 1) ? Wk : (w == 2) ? Wv : Wo;
        dst = (w == 0) ? wqb : (w == 1) ? wkb : (w == 2) ? wvb : wob;
    }
    int idx = lbid * 256 + threadIdx.x;
    int row = idx >> 7;
    int k   = (idx & 127) * 8;

    float4 v0 = *(const float4*)(src + (size_t)row * D_DIM + k);
    float4 v1 = *(const float4*)(src + (size_t)row * D_DIM + k + 4);

    uint4 hi, lo;
    uint32_t h, l;
    split2(v0.x, v0.y, h, l); hi.x = h; lo.x = l;
    split2(v0.z, v0.w, h, l); hi.y = h; lo.y = l;
    split2(v1.x, v1.y, h, l); hi.z = h; lo.z = l;
    split2(v1.z, v1.w, h, l); hi.w = h; lo.w = l;

    uint32_t off = SMEM_SWZ((uint32_t)((row & 127) * 128 + (k & 63) * 2));
    if (isx) {
        size_t base = ((size_t)(row >> 7) * 16 + (k >> 6)) * 32768;
        char* p = (char*)dst + base;
        *(uint4*)(p + off) = hi;
        *(uint4*)(p + 16384 + off) = lo;
    } else {
        size_t base = ((size_t)(row >> 7) * 16 + (k >> 6)) * 16384;
        *(uint4*)((char*)dst + base + off) = hi;
    }
}

// ---------------------------------------------------------------------------
// Blob GEMM: 128x128, BK=64, 2-stage (96KB -> 2 CTAs/SM). Ah.Bh + Al.Bh.
// modes: 0 = fp32 (+resid); 1 = Q blob; 2 = K blob; 3 = V blob
// ---------------------------------------------------------------------------
#define GSTAGE 49152
#define GEMM_SMEM (64 + 2 * GSTAGE)   // 98368 -> 2 CTAs/SM

__global__ __launch_bounds__(256, 2) void gemm_blob_kernel(
    const __half* __restrict__ Ablob, const __half* __restrict__ Bblob,
    const float* __restrict__ resid, float* __restrict__ Cf,
    __half* __restrict__ OutB, int mode, float scale, int N, int K)
{
    extern __shared__ char smem[];
    const uint32_t sb = smem_u32(smem);
    const int tid  = threadIdx.x;
    const int wid  = tid >> 5;
    const int lane = tid & 31;
    const int wm   = wid >> 2;
    const int wn   = wid & 3;

    const int mb = blockIdx.y, nb = blockIdx.x;
    const int m0 = mb * 128, n0 = nb * 128;
    const int NCH = K >> 6;

    const char* Asrc = (const char*)Ablob + (size_t)mb * NCH * 32768;
    const char* Bsrc = (const char*)Bblob + (size_t)nb * NCH * 16384;

    if (tid == 0) {
        MBARRIER_INIT(sb + 0, 1);
        MBARRIER_INIT(sb + 8, 1);
        FENCE_PROXY_ASYNC();
    }
    __syncthreads();

    auto issue = [&](int ch) {
        const int s = ch & 1;
        uint32_t mbar = sb + 8 * s;
        uint32_t dst = sb + 64 + s * GSTAGE;
        MBARRIER_EXPECT_TX(mbar, GSTAGE);
        bulk_g2s(dst,         Asrc + (size_t)ch * 32768, 32768, mbar);
        bulk_g2s(dst + 32768, Bsrc + (size_t)ch * 16384, 16384, mbar);
    };

    if (tid == 0) { issue(0); issue(1); }

    float acc[4][4][4];
#pragma unroll
    for (int i = 0; i < 4; i++)
#pragma unroll
        for (int j = 0; j < 4; j++)
#pragma unroll
            for (int r = 0; r < 4; r++) acc[i][j][r] = 0.0f;

    const int arow = wm * 64 + (lane & 15);
    const int brow = wn * 32 + ((lane >> 4) & 1) * 8 + (lane & 7);

    for (int ch = 0; ch < NCH; ch++) {
        const int s = ch & 1;
        MBARRIER_WAIT_PARITY(sb + 8 * s, (ch >> 1) & 1);

        const uint32_t bufA = sb + 64 + s * GSTAGE;
        const uint32_t bufB = bufA + 32768;

#pragma unroll
        for (int kc = 0; kc < 4; kc++) {
            uint32_t ah[4][4], alr[4][4], bh[4][2];
#pragma unroll
            for (int mt = 0; mt < 4; mt++) {
                uint32_t off = SMEM_SWZ((uint32_t)((arow + mt * 16) * 128 + kc * 32 + (lane >> 4) * 16));
                ldsm4(ah[mt],  bufA + off);
                ldsm4(alr[mt], bufA + 16384 + off);
            }
#pragma unroll
            for (int np = 0; np < 2; np++) {
                uint32_t off = SMEM_SWZ((uint32_t)((brow + np * 16) * 128 + kc * 32 + ((lane >> 3) & 1) * 16));
                uint32_t r[4];
                ldsm4(r, bufB + off);
                bh[np * 2][0] = r[0]; bh[np * 2][1] = r[1];
                bh[np * 2 + 1][0] = r[2]; bh[np * 2 + 1][1] = r[3];
            }
#pragma unroll
            for (int mt = 0; mt < 4; mt++)
#pragma unroll
                for (int nt = 0; nt < 4; nt++) {
                    mma16816(acc[mt][nt], ah[mt],  bh[nt]);
                    mma16816(acc[mt][nt], alr[mt], bh[nt]);
                }
        }
        __syncthreads();

        if (ch + 2 < NCH && tid == 0) issue(ch + 2);
    }

#pragma unroll
    for (int mt = 0; mt < 4; mt++) {
        int row = m0 + wm * 64 + mt * 16 + (lane >> 2);
#pragma unroll
        for (int nt = 0; nt < 4; nt++) {
            int col = n0 + wn * 32 + nt * 8 + (lane & 3) * 2;
            float v0 = acc[mt][nt][0] * scale;
            float v1 = acc[mt][nt][1] * scale;
            float v2 = acc[mt][nt][2] * scale;
            float v3 = acc[mt][nt][3] * scale;
            if (mode == 0) {
                if (resid) {
                    float2 r0 = *(const float2*)(resid + (size_t)row * N + col);
                    float2 r1 = *(const float2*)(resid + (size_t)(row + 8) * N + col);
                    v0 += r0.x; v1 += r0.y; v2 += r1.x; v3 += r1.y;
                }
                *(float2*)(Cf + (size_t)row * N + col) = make_float2(v0, v1);
                *(float2*)(Cf + (size_t)(row + 8) * N + col) = make_float2(v2, v3);
            } else if (mode == 1) {
                uint32_t h01, l01, h23, l23;
                split2(v0, v1, h01, l01);
                split2(v2, v3, h23, l23);
                size_t base = ((size_t)(row >> 7) * 16 + (col >> 6)) * 32768;
                uint32_t o0 = SMEM_SWZ((uint32_t)((row & 127) * 128 + (col & 63) * 2));
                uint32_t o1 = SMEM_SWZ((uint32_t)(((row + 8) & 127) * 128 + (col & 63) * 2));
                char* p = (char*)OutB + base;
                *(uint32_t*)(p + o0) = h01; *(uint32_t*)(p + 16384 + o0) = l01;
                *(uint32_t*)(p + o1) = h23; *(uint32_t*)(p + 16384 + o1) = l23;
            } else {
                size_t base = ((size_t)(col >> 6) * 32 + (row >> 6)) * 16384
                              + (mode == 3 ? 8192 : 0);
                uint32_t o0 = SMEM_SWZ((uint32_t)((row & 63) * 128 + (col & 63) * 2));
                uint32_t o1 = SMEM_SWZ((uint32_t)(((row + 8) & 63) * 128 + (col & 63) * 2));
                char* p = (char*)OutB + base;
                *(uint32_t*)(p + o0) = packh2(v0, v1);
                *(uint32_t*)(p + o1) = packh2(v2, v3);
            }
        }
    }
}

// ---------------------------------------------------------------------------
// Flash attention: fp16, QK 2-pass + PV 1-pass (P hi-only), 4-stage KV ring,
// 2 CTAs/SM, warp-decoupled mbarrier full/empty pairs.
// ---------------------------------------------------------------------------
#define ATT_SMEM (128 + 32768 + 4 * 16384)

__global__ __launch_bounds__(256, 2) void attn_blob_kernel(
    const __half* __restrict__ Qb, const __half* __restrict__ KVb,
    const float* __restrict__ bias, const uint32_t* __restrict__ mpack,
    __half* __restrict__ Ob)
{
    extern __shared__ char smem[];
    const uint32_t sb = smem_u32(smem);
    const uint32_t qsm  = sb + 128;
    const uint32_t kvsm = sb + 128 + 32768;
    const int tid  = threadIdx.x;
    const int wid  = tid >> 5;
    const int lane = tid & 31;
    const int h  = blockIdx.y;
    const int qb = blockIdx.x;
    const int q0 = qb * 128;

    const char* Qsrc  = (const char*)Qb + ((size_t)qb * 16 + h) * 32768;
    const char* KVsrc = (const char*)KVb + (size_t)h * 32 * 16384;

    if (tid == 0) {
#pragma unroll
        for (int i = 0; i < 4; i++) {
            MBARRIER_INIT(sb + 8 * i, 1);
            MBARRIER_INIT(sb + 32 + 8 * i, 256);
        }
        MBARRIER_INIT(sb + 64, 1);
        FENCE_PROXY_ASYNC();
    }
    __syncthreads();

    if (tid == 0) {
        MBARRIER_EXPECT_TX(sb + 64, 32768);
        bulk_g2s(qsm, Qsrc, 32768, sb + 64);
#pragma unroll
        for (int i = 0; i < 4; i++) {
            MBARRIER_EXPECT_TX(sb + 8 * i, 16384);
            bulk_g2s(kvsm + i * 16384, KVsrc + (size_t)i * 16384, 16384, sb + 8 * i);
        }
    }

    float Oacc[8][4];
#pragma unroll
    for (int i = 0; i < 8; i++)
#pragma unroll
        for (int j = 0; j < 4; j++) Oacc[i][j] = 0.0f;
    float m0 = -1e30f, m1 = -1e30f, l0 = 0.0f, l1 = 0.0f;

    const int r = lane >> 2;
    const int grow0 = q0 + wid * 16 + r;
    const int grow1 = grow0 + 8;
    const float* brow0 = bias + (size_t)grow0 * (H_NUM * S_LEN) + (size_t)h * S_LEN;
    const float* brow1 = bias + (size_t)grow1 * (H_NUM * S_LEN) + (size_t)h * S_LEN;
    const uint32_t* mp0 = mpack + grow0 * (S_LEN / 32);
    const uint32_t* mp1 = mpack + grow1 * (S_LEN / 32);
    const int cbase = (lane & 3) * 2;
    const int qrow = wid * 16 + (lane & 15);
    const int qsel = (lane >> 4) * 16;

    MBARRIER_WAIT_PARITY(sb + 64, 0);

    for (int t = 0; t < S_LEN / 64; t++) {
        const int s = t & 3;
        const int ph = (t >> 2) & 1;
        MBARRIER_WAIT_PARITY(sb + 8 * s, ph);
        const uint32_t base = kvsm + s * 16384;   // Kh @ +0, Vh @ +8192
        const int j0 = t * 64;

        uint2 mwa = *(const uint2*)(mp0 + (j0 >> 5));
        uint2 mwb = *(const uint2*)(mp1 + (j0 >> 5));
        uint64_t sm0 = (((uint64_t)mwa.y << 32) | mwa.x) >> cbase;
        uint64_t sm1 = (((uint64_t)mwb.y << 32) | mwb.x) >> cbase;

        float acc[8][4];
#pragma unroll
        for (int i = 0; i < 8; i++)
#pragma unroll
            for (int j = 0; j < 4; j++) acc[i][j] = 0.0f;

#pragma unroll
        for (int kc = 0; kc < 4; kc++) {
            uint32_t qh[4], ql[4];
            uint32_t qoff = SMEM_SWZ((uint32_t)(qrow * 128 + kc * 32 + qsel));
            ldsm4(qh, qsm + qoff);
            ldsm4(ql, qsm + 16384 + qoff);
#pragma unroll
            for (int np = 0; np < 4; np++) {
                int krow = np * 16 + (lane >> 4) * 8 + (lane & 7);
                uint32_t koff = SMEM_SWZ((uint32_t)(krow * 128 + kc * 32 + ((lane >> 3) & 1) * 16));
                uint32_t bh[4];
                ldsm4(bh, base + koff);
                mma16816(acc[2 * np],     qh, bh + 0);
                mma16816(acc[2 * np],     ql, bh + 0);
                mma16816(acc[2 * np + 1], qh, bh + 2);
                mma16816(acc[2 * np + 1], ql, bh + 2);
            }
        }

        float mx0 = -1e30f, mx1 = -1e30f;
#pragma unroll
        for (int nt = 0; nt < 8; nt++) {
            int c = nt * 8 + cbase;
            float2 b0 = *(const float2*)(brow0 + j0 + c);
            float2 b1 = *(const float2*)(brow1 + j0 + c);
            uint32_t w0 = (uint32_t)(sm0 >> (nt * 8));
            uint32_t w1 = (uint32_t)(sm1 >> (nt * 8));
            acc[nt][0] = (w0 & 1u) ? fmaf(b0.x, LOG2E, acc[nt][0]) : -1e30f;
            acc[nt][1] = (w0 & 2u) ? fmaf(b0.y, LOG2E, acc[nt][1]) : -1e30f;
            acc[nt][2] = (w1 & 1u) ? fmaf(b1.x, LOG2E, acc[nt][2]) : -1e30f;
            acc[nt][3] = (w1 & 2u) ? fmaf(b1.y, LOG2E, acc[nt][3]) : -1e30f;
            mx0 = fmaxf(mx0, fmaxf(acc[nt][0], acc[nt][1]));
            mx1 = fmaxf(mx1, fmaxf(acc[nt][2], acc[nt][3]));
        }
        mx0 = fmaxf(mx0, __shfl_xor_sync(0xffffffffu, mx0, 1));
        mx0 = fmaxf(mx0, __shfl_xor_sync(0xffffffffu, mx0, 2));
        mx1 = fmaxf(mx1, __shfl_xor_sync(0xffffffffu, mx1, 1));
        mx1 = fmaxf(mx1, __shfl_xor_sync(0xffffffffu, mx1, 2));

        float mn0 = fmaxf(m0, mx0), mn1 = fmaxf(m1, mx1);
        float a0 = ex2(m0 - mn0), a1 = ex2(m1 - mn1);
        m0 = mn0; m1 = mn1;

        float s0 = 0.0f, s1 = 0.0f;
#pragma unroll
        for (int nt = 0; nt < 8; nt++) {
            acc[nt][0] = ex2(acc[nt][0] - mn0);
            acc[nt][1] = ex2(acc[nt][1] - mn0);
            acc[nt][2] = ex2(acc[nt][2] - mn1);
            acc[nt][3] = ex2(acc[nt][3] - mn1);
            s0 += acc[nt][0] + acc[nt][1];
            s1 += acc[nt][2] + acc[nt][3];
        }
        s0 += __shfl_xor_sync(0xffffffffu, s0, 1);
        s0 += __shfl_xor_sync(0xffffffffu, s0, 2);
        s1 += __shfl_xor_sync(0xffffffffu, s1, 1);
        s1 += __shfl_xor_sync(0xffffffffu, s1, 2);
        l0 = l0 * a0 + s0;
        l1 = l1 * a1 + s1;

#pragma unroll
        for (int nt = 0; nt < 8; nt++) {
            Oacc[nt][0] *= a0; Oacc[nt][1] *= a0;
            Oacc[nt][2] *= a1; Oacc[nt][3] *= a1;
        }

        // PV: P hi-only (1 pass)
#pragma unroll
        for (int kc = 0; kc < 4; kc++) {
            uint32_t pha[4];
            pha[0] = packh2(acc[2 * kc][0],     acc[2 * kc][1]);
            pha[1] = packh2(acc[2 * kc][2],     acc[2 * kc][3]);
            pha[2] = packh2(acc[2 * kc + 1][0], acc[2 * kc + 1][1]);
            pha[3] = packh2(acc[2 * kc + 1][2], acc[2 * kc + 1][3]);
#pragma unroll
            for (int dp = 0; dp < 4; dp++) {
                int vrow = kc * 16 + (lane & 15);
                uint32_t voff = SMEM_SWZ((uint32_t)(vrow * 128 + dp * 32 + (lane >> 4) * 16));
                uint32_t vh[4];
                ldsm4t(vh, base + 8192 + voff);
                mma16816(Oacc[2 * dp],     pha, vh + 0);
                mma16816(Oacc[2 * dp + 1], pha, vh + 2);
            }
        }

        MBARRIER_ARRIVE(sb + 32 + 8 * s);

        if (t + 4 < S_LEN / 64 && tid == 0) {
            MBARRIER_WAIT_PARITY(sb + 32 + 8 * s, ph);
            MBARRIER_EXPECT_TX(sb + 8 * s, 16384);
            bulk_g2s(kvsm + s * 16384, KVsrc + (size_t)(t + 4) * 16384, 16384, sb + 8 * s);
        }
    }

    float inv0 = 1.0f / l0, inv1 = 1.0f / l1;
    char* outb = (char*)Ob + ((size_t)qb * 16 + h) * 32768;
    const int r128 = wid * 16 + r;
#pragma unroll
    for (int nt = 0; nt < 8; nt++) {
        int d = nt * 8 + cbase;
        float v0 = Oacc[nt][0] * inv0, v1 = Oacc[nt][1] * inv0;
        float v2 = Oacc[nt][2] * inv1, v3 = Oacc[nt][3] * inv1;
        uint32_t h01, l01, h23, l23;
        split2(v0, v1, h01, l01);
        split2(v2, v3, h23, l23);
        uint32_t o0 = SMEM_SWZ((uint32_t)(r128 * 128 + d * 2));
        uint32_t o1 = SMEM_SWZ((uint32_t)((r128 + 8) * 128 + d * 2));
        *(uint32_t*)(outb + o0) = h01; *(uint32_t*)(outb + 16384 + o0) = l01;
        *(uint32_t*)(outb + o1) = h23; *(uint32_t*)(outb + 16384 + o1) = l23;
    }
}

// ---------------------------------------------------------------------------
// LayerNorm
// ---------------------------------------------------------------------------
__device__ __forceinline__ float block_reduce_sum(float v) {
    __shared__ float red[8];
    int lane = threadIdx.x & 31, w = threadIdx.x >> 5;
#pragma unroll
    for (int o = 16; o > 0; o >>= 1) v += __shfl_xor_sync(0xffffffffu, v, o);
    __syncthreads();
    if (lane == 0) red[w] = v;
    __syncthreads();
    float t = 0.0f;
#pragma unroll
    for (int i = 0; i < 8; i++) t += red[i];
    return t;
}

__global__ __launch_bounds__(256) void ln_kernel(
    const float* __restrict__ res, const float* __restrict__ w,
    const float* __restrict__ b, float* __restrict__ out)
{
    int row = blockIdx.x;
    int tid = threadIdx.x;
    const float* r = res + (size_t)row * D_DIM;

    float4 x4 = *(const float4*)(r + tid * 4);
    float sum = x4.x + x4.y + x4.z + x4.w;
    sum = block_reduce_sum(sum);
    float mean = sum * (1.0f / D_DIM);

    float d0 = x4.x - mean, d1 = x4.y - mean, d2 = x4.z - mean, d3 = x4.w - mean;
    float sq = d0 * d0 + d1 * d1 + d2 * d2 + d3 * d3;
    sq = block_reduce_sum(sq);
    float inv = rsqrtf(sq * (1.0f / D_DIM) + LN_EPS);

    float4 w4 = *(const float4*)(w + tid * 4);
    float4 b4 = *(const float4*)(b + tid * 4);
    float4 o4;
    o4.x = d0 * inv * w4.x + b4.x;
    o4.y = d1 * inv * w4.y + b4.y;
    o4.z = d2 * inv * w4.z + b4.z;
    o4.w = d3 * inv * w4.w + b4.w;
    *(float4*)(out + (size_t)row * D_DIM + tid * 4) = o4;
}

// ---------------------------------------------------------------------------
// Launch
// ---------------------------------------------------------------------------
extern "C" void kernel_launch(void* const* d_in, const int* in_sizes, int n_in,
                              void* d_out, int out_size)
{
    (void)in_sizes; (void)n_in; (void)out_size;

    const float*        x    = (const float*)d_in[0];
    const float*        bias = (const float*)d_in[1];
    const unsigned int* mask = (const unsigned int*)d_in[2];
    const float*        Wq   = (const float*)d_in[3];
    const float*        Wk   = (const float*)d_in[4];
    const float*        Wv   = (const float*)d_in[5];
    const float*        Wo   = (const float*)d_in[6];
    const float*        lnw  = (const float*)d_in[7];
    const float*        lnb  = (const float*)d_in[8];
    float*              out  = (float*)d_out;

    void *pxb, *pwq, *pwk, *pwv, *pwo, *pqb, *pkv, *pab, *pres, *pmp;
    cudaGetSymbolAddress(&pxb, g_xb);
    cudaGetSymbolAddress(&pwq, g_wqb);
    cudaGetSymbolAddress(&pwk, g_wkb);
    cudaGetSymbolAddress(&pwv, g_wvb);
    cudaGetSymbolAddress(&pwo, g_wob);
    cudaGetSymbolAddress(&pqb, g_qb);
    cudaGetSymbolAddress(&pkv, g_kvb);
    cudaGetSymbolAddress(&pab, g_ab);
    cudaGetSymbolAddress(&pres, g_res);
    cudaGetSymbolAddress(&pmp, g_mpack);

    __half *xb = (__half*)pxb;
    __half *wqb = (__half*)pwq, *wkb = (__half*)pwk;
    __half *wvb = (__half*)pwv, *wob = (__half*)pwo;
    __half *qb = (__half*)pqb, *kvb = (__half*)pkv;
    __half *ab = (__half*)pab;
    float* res = (float*)pres;
    uint32_t* mp = (uint32_t*)pmp;

    cudaFuncSetAttribute(gemm_blob_kernel, cudaFuncAttributeMaxDynamicSharedMemorySize, GEMM_SMEM);
    cudaFuncSetAttribute(attn_blob_kernel, cudaFuncAttributeMaxDynamicSharedMemorySize, ATT_SMEM);

    dim3 gt(D_DIM / 128, S_LEN / 128);   // (8, 16)

    split_all_kernel<<<3072, 256>>>(x, Wq, Wk, Wv, Wo, xb, wqb, wkb, wvb, wob);
    pack_mask_kernel<<<S_LEN, 256>>>(mask, mp);

    gemm_blob_kernel<<<gt, 256, GEMM_SMEM>>>(xb, wqb, nullptr, nullptr, qb,
                                             1, 0.125f * LOG2E, D_DIM, D_DIM);
    gemm_blob_kernel<<<gt, 256, GEMM_SMEM>>>(xb, wkb, nullptr, nullptr, kvb,
                                             2, 1.0f, D_DIM, D_DIM);
    gemm_blob_kernel<<<gt, 256, GEMM_SMEM>>>(xb, wvb, nullptr, nullptr, kvb,
                                             3, 1.0f, D_DIM, D_DIM);

    attn_blob_kernel<<<dim3(S_LEN / 128, H_NUM), 256, ATT_SMEM>>>(qb, kvb, bias, mp, ab);

    gemm_blob_kernel<<<gt, 256, GEMM_SMEM>>>(ab, wob, x, res, nullptr,
                                             0, 1.0f, D_DIM, D_DIM);

    ln_kernel<<<S_LEN, 256>>>(res, lnw, lnb, out);
}

// round 13
// speedup vs baseline: 1.9552x; 1.0239x over previous
#include <cuda_runtime.h>
#include <cuda_fp16.h>
#include <cstdint>

// Problem constants
#define S_LEN 2048
#define D_DIM 1024
#define H_NUM 16
#define DH 64
#define LN_EPS 1e-5f
#define LOG2E 1.4426950408889634f

// ---------------------------------------------------------------------------
// PTX helpers
// ---------------------------------------------------------------------------
__device__ __forceinline__ uint32_t smem_u32(const void* p) {
    uint32_t a;
    asm("{ .reg .u64 t; cvta.to.shared.u64 t, %1; cvt.u32.u64 %0, t; }"
        : "=r"(a) : "l"(p));
    return a;
}

__device__ __forceinline__ void ldsm4(uint32_t* r, uint32_t a) {
    asm volatile("ldmatrix.sync.aligned.m8n8.x4.shared.b16 {%0,%1,%2,%3}, [%4];"
                 : "=r"(r[0]), "=r"(r[1]), "=r"(r[2]), "=r"(r[3]) : "r"(a));
}
__device__ __forceinline__ void ldsm4t(uint32_t* r, uint32_t a) {
    asm volatile("ldmatrix.sync.aligned.m8n8.x4.trans.shared.b16 {%0,%1,%2,%3}, [%4];"
                 : "=r"(r[0]), "=r"(r[1]), "=r"(r[2]), "=r"(r[3]) : "r"(a));
}

// fp16 MMA, fp32 accumulate
__device__ __forceinline__ void mma16816(float* c, const uint32_t* a, const uint32_t* b) {
    asm volatile("mma.sync.aligned.m16n8k16.row.col.f32.f16.f16.f32 "
                 "{%0,%1,%2,%3}, {%4,%5,%6,%7}, {%8,%9}, {%0,%1,%2,%3};"
                 : "+f"(c[0]), "+f"(c[1]), "+f"(c[2]), "+f"(c[3])
                 : "r"(a[0]), "r"(a[1]), "r"(a[2]), "r"(a[3]),
                   "r"(b[0]), "r"(b[1]));
}

#define MBARRIER_INIT(addr, cnt) \
    asm volatile("mbarrier.init.shared.b64 [%0], %1;" :: "r"((uint32_t)(addr)), "r"((uint32_t)(cnt)) : "memory")

#define MBARRIER_EXPECT_TX(addr, tx) \
    asm volatile("mbarrier.arrive.expect_tx.shared.b64 _, [%0], %1;" \
                 :: "r"((uint32_t)(addr)), "r"((uint32_t)(tx)) : "memory")

#define MBARRIER_ARRIVE(addr) \
    asm volatile("mbarrier.arrive.shared.b64 _, [%0];" \
                 :: "r"((uint32_t)(addr)) : "memory")

#define MBARRIER_WAIT_PARITY(mbar_smem_addr, phase_parity) do { \
    uint32_t _mbar = (uint32_t)(mbar_smem_addr); \
    uint32_t _parity = (uint32_t)(phase_parity); \
    uint32_t _done; \
    asm volatile("{\n\t.reg .pred p;\n\t" \
        "mbarrier.try_wait.parity.acquire.cta.shared::cta.b64 p, [%1], %2;\n\t" \
        "selp.b32 %0, 1, 0, p;\n\t}" \
        : "=r"(_done) : "r"(_mbar), "r"(_parity) : "memory"); \
    if (!_done) { \
        asm volatile("{\n\t.reg .pred P1;\n\t" \
            "WAIT_LOOP_%=:\n\t" \
            "mbarrier.try_wait.parity.acquire.cta.shared::cta.b64 P1, [%0], %1, 0x989680;\n\t" \
            "@P1 bra.uni WAIT_DONE_%=;\n\t" \
            "bra.uni WAIT_LOOP_%=;\n\t" \
            "WAIT_DONE_%=:\n\t}" \
            :: "r"(_mbar), "r"(_parity) : "memory"); \
    } \
} while (0)

__device__ __forceinline__ void bulk_g2s(uint32_t dst, const void* src, uint32_t bytes, uint32_t mbar) {
    asm volatile("cp.async.bulk.shared::cluster.global.mbarrier::complete_tx::bytes "
                 "[%0], [%1], %2, [%3];"
                 :: "r"(dst), "l"(src), "r"(bytes), "r"(mbar) : "memory");
}

#define FENCE_PROXY_ASYNC() asm volatile("fence.proxy.async.shared::cta;" ::: "memory")

#define SMEM_SWZ(off) ((off) ^ (((off) >> 3) & 0x70))

__device__ __forceinline__ uint32_t packh2(float a, float b) {
    __half2 t = __floats2half2_rn(a, b);
    return *reinterpret_cast<uint32_t*>(&t);
}
__device__ __forceinline__ void split2(float a, float b, uint32_t& hi, uint32_t& lo) {
    __half2 h = __floats2half2_rn(a, b);
    float2 hf = __half22float2(h);
    hi = *reinterpret_cast<uint32_t*>(&h);
    lo = packh2(a - hf.x, b - hf.y);
}
__device__ __forceinline__ float ex2(float x) {
    float y; asm("ex2.approx.ftz.f32 %0, %1;" : "=f"(y) : "f"(x)); return y;
}

// ---------------------------------------------------------------------------
// Scratch (device globals)
// ---------------------------------------------------------------------------
__device__ __align__(128) __half g_xb [2 * S_LEN * D_DIM];
__device__ __align__(128) __half g_wqb[D_DIM * D_DIM];
__device__ __align__(128) __half g_wkb[D_DIM * D_DIM];
__device__ __align__(128) __half g_wvb[D_DIM * D_DIM];
__device__ __align__(128) __half g_wob[D_DIM * D_DIM];
__device__ __align__(128) __half g_qb [2 * S_LEN * D_DIM];
__device__ __align__(128) __half g_kvb[2 * S_LEN * D_DIM];
__device__ __align__(128) __half g_ab [2 * S_LEN * D_DIM];
__device__ float g_res[S_LEN * D_DIM];
__device__ __align__(8) uint32_t g_mpack[S_LEN * (S_LEN / 32)];

// ---------------------------------------------------------------------------
// Mask bit-pack
// ---------------------------------------------------------------------------
__global__ __launch_bounds__(256) void pack_mask_kernel(
    const unsigned int* __restrict__ mask, uint32_t* __restrict__ mp)
{
    int row = blockIdx.x;
    int w = threadIdx.x >> 5;
    int lane = threadIdx.x & 31;
#pragma unroll
    for (int i = 0; i < 8; i++) {
        int word = w * 8 + i;
        unsigned int v = mask[(size_t)row * S_LEN + word * 32 + lane];
        unsigned int bal = __ballot_sync(0xffffffffu, v != 0u);
        if (lane == 0) mp[row * 64 + word] = bal;
    }
}

// ---------------------------------------------------------------------------
// Fused split: x -> hi/lo 32KB blocks; W -> hi-only 16KB blocks.
// ---------------------------------------------------------------------------
__global__ __launch_bounds__(256) void split_all_kernel(
    const float* __restrict__ x,
    const float* __restrict__ Wq, const float* __restrict__ Wk,
    const float* __restrict__ Wv, const float* __restrict__ Wo,
    __half* __restrict__ xb,
    __half* __restrict__ wqb, __half* __restrict__ wkb,
    __half* __restrict__ wvb, __half* __restrict__ wob)
{
    int bid = blockIdx.x;
    const float* src;
    __half* dst;
    int lbid;
    bool isx = (bid < 1024);
    if (isx) { src = x; dst = xb; lbid = bid; }
    else {
        int w = (bid - 1024) >> 9;
        lbid = (bid - 1024) & 511;
        src = (w == 0) ? Wq : (w == 1) ? Wk : (w == 2) ? Wv : Wo;
        dst = (w == 0) ? wqb : (w == 1) ? wkb : (w == 2) ? wvb : wob;
    }
    int idx = lbid * 256 + threadIdx.x;
    int row = idx >> 7;
    int k   = (idx & 127) * 8;

    float4 v0 = *(const float4*)(src + (size_t)row * D_DIM + k);
    float4 v1 = *(const float4*)(src + (size_t)row * D_DIM + k + 4);

    uint4 hi, lo;
    uint32_t h, l;
    split2(v0.x, v0.y, h, l); hi.x = h; lo.x = l;
    split2(v0.z, v0.w, h, l); hi.y = h; lo.y = l;
    split2(v1.x, v1.y, h, l); hi.z = h; lo.z = l;
    split2(v1.z, v1.w, h, l); hi.w = h; lo.w = l;

    uint32_t off = SMEM_SWZ((uint32_t)((row & 127) * 128 + (k & 63) * 2));
    if (isx) {
        size_t base = ((size_t)(row >> 7) * 16 + (k >> 6)) * 32768;
        char* p = (char*)dst + base;
        *(uint4*)(p + off) = hi;
        *(uint4*)(p + 16384 + off) = lo;
    } else {
        size_t base = ((size_t)(row >> 7) * 16 + (k >> 6)) * 16384;
        *(uint4*)((char*)dst + base + off) = hi;
    }
}

// ---------------------------------------------------------------------------
// Blob GEMM: tile 64x128, BK=64, 2-stage (64KB -> 2 CTAs/SM), grid (8,32).
// fp16 2-pass: Ah.Bh + Al.Bh. Stage = Ah 8KB + Al 8KB + Bh 16KB = 32KB.
// modes: 0 = fp32 (+resid); 1 = Q blob; 2 = K blob; 3 = V blob
// ---------------------------------------------------------------------------
#define GSTAGE 32768
#define GEMM_SMEM (64 + 2 * GSTAGE)

__global__ __launch_bounds__(256, 2) void gemm_blob_kernel(
    const __half* __restrict__ Ablob, const __half* __restrict__ Bblob,
    const float* __restrict__ resid, float* __restrict__ Cf,
    __half* __restrict__ OutB, int mode, float scale, int N, int K)
{
    extern __shared__ char smem[];
    const uint32_t sb = smem_u32(smem);
    const int tid  = threadIdx.x;
    const int wid  = tid >> 5;
    const int lane = tid & 31;
    const int wm   = wid >> 2;   // 0..1 -> 32 rows
    const int wn   = wid & 3;    // 0..3 -> 32 cols

    const int mb = blockIdx.y;   // 64-row block (0..31)
    const int nb = blockIdx.x;   // 128-col block (0..7)
    const int NCH = K >> 6;

    // A blob is 128-row; take the (mb&1) 64-row half (hi @ +8192*(mb&1),
    // lo @ +16384 + 8192*(mb&1)).
    const char* Abase = (const char*)Ablob + (size_t)(mb >> 1) * NCH * 32768
                        + (size_t)(mb & 1) * 8192;
    const char* Bsrc  = (const char*)Bblob + (size_t)nb * NCH * 16384;

    if (tid == 0) {
        MBARRIER_INIT(sb + 0, 1);
        MBARRIER_INIT(sb + 8, 1);
        FENCE_PROXY_ASYNC();
    }
    __syncthreads();

    auto issue = [&](int ch) {
        const int s = ch & 1;
        uint32_t mbar = sb + 8 * s;
        uint32_t dst = sb + 64 + s * GSTAGE;
        const char* ab = Abase + (size_t)ch * 32768;
        MBARRIER_EXPECT_TX(mbar, GSTAGE);
        bulk_g2s(dst,         ab,          8192, mbar);   // Ah (64 rows)
        bulk_g2s(dst + 8192,  ab + 16384,  8192, mbar);   // Al
        bulk_g2s(dst + 16384, Bsrc + (size_t)ch * 16384, 16384, mbar); // Bh
    };

    if (tid == 0) { issue(0); issue(1); }

    float acc[2][4][4];
#pragma unroll
    for (int i = 0; i < 2; i++)
#pragma unroll
        for (int j = 0; j < 4; j++)
#pragma unroll
            for (int r = 0; r < 4; r++) acc[i][j][r] = 0.0f;

    const int arow = wm * 32 + (lane & 15);
    const int brow = wn * 32 + ((lane >> 4) & 1) * 8 + (lane & 7);

    for (int ch = 0; ch < NCH; ch++) {
        const int s = ch & 1;
        MBARRIER_WAIT_PARITY(sb + 8 * s, (ch >> 1) & 1);

        const uint32_t bufA = sb + 64 + s * GSTAGE;
        const uint32_t bufB = bufA + 16384;

#pragma unroll
        for (int kc = 0; kc < 4; kc++) {
            uint32_t ah[2][4], alr[2][4], bh[4][2];
#pragma unroll
            for (int mt = 0; mt < 2; mt++) {
                uint32_t off = SMEM_SWZ((uint32_t)((arow + mt * 16) * 128 + kc * 32 + (lane >> 4) * 16));
                ldsm4(ah[mt],  bufA + off);
                ldsm4(alr[mt], bufA + 8192 + off);
            }
#pragma unroll
            for (int np = 0; np < 2; np++) {
                uint32_t off = SMEM_SWZ((uint32_t)((brow + np * 16) * 128 + kc * 32 + ((lane >> 3) & 1) * 16));
                uint32_t r[4];
                ldsm4(r, bufB + off);
                bh[np * 2][0] = r[0]; bh[np * 2][1] = r[1];
                bh[np * 2 + 1][0] = r[2]; bh[np * 2 + 1][1] = r[3];
            }
#pragma unroll
            for (int mt = 0; mt < 2; mt++)
#pragma unroll
                for (int nt = 0; nt < 4; nt++) {
                    mma16816(acc[mt][nt], ah[mt],  bh[nt]);
                    mma16816(acc[mt][nt], alr[mt], bh[nt]);
                }
        }
        __syncthreads();

        if (ch + 2 < NCH && tid == 0) issue(ch + 2);
    }

#pragma unroll
    for (int mt = 0; mt < 2; mt++) {
        int row = mb * 64 + wm * 32 + mt * 16 + (lane >> 2);
#pragma unroll
        for (int nt = 0; nt < 4; nt++) {
            int col = nb * 128 + wn * 32 + nt * 8 + (lane & 3) * 2;
            float v0 = acc[mt][nt][0] * scale;
            float v1 = acc[mt][nt][1] * scale;
            float v2 = acc[mt][nt][2] * scale;
            float v3 = acc[mt][nt][3] * scale;
            if (mode == 0) {
                if (resid) {
                    float2 r0 = *(const float2*)(resid + (size_t)row * N + col);
                    float2 r1 = *(const float2*)(resid + (size_t)(row + 8) * N + col);
                    v0 += r0.x; v1 += r0.y; v2 += r1.x; v3 += r1.y;
                }
                *(float2*)(Cf + (size_t)row * N + col) = make_float2(v0, v1);
                *(float2*)(Cf + (size_t)(row + 8) * N + col) = make_float2(v2, v3);
            } else if (mode == 1) {
                uint32_t h01, l01, h23, l23;
                split2(v0, v1, h01, l01);
                split2(v2, v3, h23, l23);
                size_t base = ((size_t)(row >> 7) * 16 + (col >> 6)) * 32768;
                uint32_t o0 = SMEM_SWZ((uint32_t)((row & 127) * 128 + (col & 63) * 2));
                uint32_t o1 = SMEM_SWZ((uint32_t)(((row + 8) & 127) * 128 + (col & 63) * 2));
                char* p = (char*)OutB + base;
                *(uint32_t*)(p + o0) = h01; *(uint32_t*)(p + 16384 + o0) = l01;
                *(uint32_t*)(p + o1) = h23; *(uint32_t*)(p + 16384 + o1) = l23;
            } else {
                size_t base = ((size_t)(col >> 6) * 32 + (row >> 6)) * 16384
                              + (mode == 3 ? 8192 : 0);
                uint32_t o0 = SMEM_SWZ((uint32_t)((row & 63) * 128 + (col & 63) * 2));
                uint32_t o1 = SMEM_SWZ((uint32_t)(((row + 8) & 63) * 128 + (col & 63) * 2));
                char* p = (char*)OutB + base;
                *(uint32_t*)(p + o0) = packh2(v0, v1);
                *(uint32_t*)(p + o1) = packh2(v2, v3);
            }
        }
    }
}

// ---------------------------------------------------------------------------
// Flash attention (R12, unchanged): fp16 QK 2-pass + PV 1-pass, 4-stage ring.
// ---------------------------------------------------------------------------
#define ATT_SMEM (128 + 32768 + 4 * 16384)

__global__ __launch_bounds__(256, 2) void attn_blob_kernel(
    const __half* __restrict__ Qb, const __half* __restrict__ KVb,
    const float* __restrict__ bias, const uint32_t* __restrict__ mpack,
    __half* __restrict__ Ob)
{
    extern __shared__ char smem[];
    const uint32_t sb = smem_u32(smem);
    const uint32_t qsm  = sb + 128;
    const uint32_t kvsm = sb + 128 + 32768;
    const int tid  = threadIdx.x;
    const int wid  = tid >> 5;
    const int lane = tid & 31;
    const int h  = blockIdx.y;
    const int qb = blockIdx.x;
    const int q0 = qb * 128;

    const char* Qsrc  = (const char*)Qb + ((size_t)qb * 16 + h) * 32768;
    const char* KVsrc = (const char*)KVb + (size_t)h * 32 * 16384;

    if (tid == 0) {
#pragma unroll
        for (int i = 0; i < 4; i++) {
            MBARRIER_INIT(sb + 8 * i, 1);
            MBARRIER_INIT(sb + 32 + 8 * i, 256);
        }
        MBARRIER_INIT(sb + 64, 1);
        FENCE_PROXY_ASYNC();
    }
    __syncthreads();

    if (tid == 0) {
        MBARRIER_EXPECT_TX(sb + 64, 32768);
        bulk_g2s(qsm, Qsrc, 32768, sb + 64);
#pragma unroll
        for (int i = 0; i < 4; i++) {
            MBARRIER_EXPECT_TX(sb + 8 * i, 16384);
            bulk_g2s(kvsm + i * 16384, KVsrc + (size_t)i * 16384, 16384, sb + 8 * i);
        }
    }

    float Oacc[8][4];
#pragma unroll
    for (int i = 0; i < 8; i++)
#pragma unroll
        for (int j = 0; j < 4; j++) Oacc[i][j] = 0.0f;
    float m0 = -1e30f, m1 = -1e30f, l0 = 0.0f, l1 = 0.0f;

    const int r = lane >> 2;
    const int grow0 = q0 + wid * 16 + r;
    const int grow1 = grow0 + 8;
    const float* brow0 = bias + (size_t)grow0 * (H_NUM * S_LEN) + (size_t)h * S_LEN;
    const float* brow1 = bias + (size_t)grow1 * (H_NUM * S_LEN) + (size_t)h * S_LEN;
    const uint32_t* mp0 = mpack + grow0 * (S_LEN / 32);
    const uint32_t* mp1 = mpack + grow1 * (S_LEN / 32);
    const int cbase = (lane & 3) * 2;
    const int qrow = wid * 16 + (lane & 15);
    const int qsel = (lane >> 4) * 16;

    MBARRIER_WAIT_PARITY(sb + 64, 0);

    for (int t = 0; t < S_LEN / 64; t++) {
        const int s = t & 3;
        const int ph = (t >> 2) & 1;
        MBARRIER_WAIT_PARITY(sb + 8 * s, ph);
        const uint32_t base = kvsm + s * 16384;
        const int j0 = t * 64;

        uint2 mwa = *(const uint2*)(mp0 + (j0 >> 5));
        uint2 mwb = *(const uint2*)(mp1 + (j0 >> 5));
        uint64_t sm0 = (((uint64_t)mwa.y << 32) | mwa.x) >> cbase;
        uint64_t sm1 = (((uint64_t)mwb.y << 32) | mwb.x) >> cbase;

        float acc[8][4];
#pragma unroll
        for (int i = 0; i < 8; i++)
#pragma unroll
            for (int j = 0; j < 4; j++) acc[i][j] = 0.0f;

#pragma unroll
        for (int kc = 0; kc < 4; kc++) {
            uint32_t qh[4], ql[4];
            uint32_t qoff = SMEM_SWZ((uint32_t)(qrow * 128 + kc * 32 + qsel));
            ldsm4(qh, qsm + qoff);
            ldsm4(ql, qsm + 16384 + qoff);
#pragma unroll
            for (int np = 0; np < 4; np++) {
                int krow = np * 16 + (lane >> 4) * 8 + (lane & 7);
                uint32_t koff = SMEM_SWZ((uint32_t)(krow * 128 + kc * 32 + ((lane >> 3) & 1) * 16));
                uint32_t bh[4];
                ldsm4(bh, base + koff);
                mma16816(acc[2 * np],     qh, bh + 0);
                mma16816(acc[2 * np],     ql, bh + 0);
                mma16816(acc[2 * np + 1], qh, bh + 2);
                mma16816(acc[2 * np + 1], ql, bh + 2);
            }
        }

        float mx0 = -1e30f, mx1 = -1e30f;
#pragma unroll
        for (int nt = 0; nt < 8; nt++) {
            int c = nt * 8 + cbase;
            float2 b0 = *(const float2*)(brow0 + j0 + c);
            float2 b1 = *(const float2*)(brow1 + j0 + c);
            uint32_t w0 = (uint32_t)(sm0 >> (nt * 8));
            uint32_t w1 = (uint32_t)(sm1 >> (nt * 8));
            acc[nt][0] = (w0 & 1u) ? fmaf(b0.x, LOG2E, acc[nt][0]) : -1e30f;
            acc[nt][1] = (w0 & 2u) ? fmaf(b0.y, LOG2E, acc[nt][1]) : -1e30f;
            acc[nt][2] = (w1 & 1u) ? fmaf(b1.x, LOG2E, acc[nt][2]) : -1e30f;
            acc[nt][3] = (w1 & 2u) ? fmaf(b1.y, LOG2E, acc[nt][3]) : -1e30f;
            mx0 = fmaxf(mx0, fmaxf(acc[nt][0], acc[nt][1]));
            mx1 = fmaxf(mx1, fmaxf(acc[nt][2], acc[nt][3]));
        }
        mx0 = fmaxf(mx0, __shfl_xor_sync(0xffffffffu, mx0, 1));
        mx0 = fmaxf(mx0, __shfl_xor_sync(0xffffffffu, mx0, 2));
        mx1 = fmaxf(mx1, __shfl_xor_sync(0xffffffffu, mx1, 1));
        mx1 = fmaxf(mx1, __shfl_xor_sync(0xffffffffu, mx1, 2));

        float mn0 = fmaxf(m0, mx0), mn1 = fmaxf(m1, mx1);
        float a0 = ex2(m0 - mn0), a1 = ex2(m1 - mn1);
        m0 = mn0; m1 = mn1;

        float s0 = 0.0f, s1 = 0.0f;
#pragma unroll
        for (int nt = 0; nt < 8; nt++) {
            acc[nt][0] = ex2(acc[nt][0] - mn0);
            acc[nt][1] = ex2(acc[nt][1] - mn0);
            acc[nt][2] = ex2(acc[nt][2] - mn1);
            acc[nt][3] = ex2(acc[nt][3] - mn1);
            s0 += acc[nt][0] + acc[nt][1];
            s1 += acc[nt][2] + acc[nt][3];
        }
        s0 += __shfl_xor_sync(0xffffffffu, s0, 1);
        s0 += __shfl_xor_sync(0xffffffffu, s0, 2);
        s1 += __shfl_xor_sync(0xffffffffu, s1, 1);
        s1 += __shfl_xor_sync(0xffffffffu, s1, 2);
        l0 = l0 * a0 + s0;
        l1 = l1 * a1 + s1;

#pragma unroll
        for (int nt = 0; nt < 8; nt++) {
            Oacc[nt][0] *= a0; Oacc[nt][1] *= a0;
            Oacc[nt][2] *= a1; Oacc[nt][3] *= a1;
        }

#pragma unroll
        for (int kc = 0; kc < 4; kc++) {
            uint32_t pha[4];
            pha[0] = packh2(acc[2 * kc][0],     acc[2 * kc][1]);
            pha[1] = packh2(acc[2 * kc][2],     acc[2 * kc][3]);
            pha[2] = packh2(acc[2 * kc + 1][0], acc[2 * kc + 1][1]);
            pha[3] = packh2(acc[2 * kc + 1][2], acc[2 * kc + 1][3]);
#pragma unroll
            for (int dp = 0; dp < 4; dp++) {
                int vrow = kc * 16 + (lane & 15);
                uint32_t voff = SMEM_SWZ((uint32_t)(vrow * 128 + dp * 32 + (lane >> 4) * 16));
                uint32_t vh[4];
                ldsm4t(vh, base + 8192 + voff);
                mma16816(Oacc[2 * dp],     pha, vh + 0);
                mma16816(Oacc[2 * dp + 1], pha, vh + 2);
            }
        }

        MBARRIER_ARRIVE(sb + 32 + 8 * s);

        if (t + 4 < S_LEN / 64 && tid == 0) {
            MBARRIER_WAIT_PARITY(sb + 32 + 8 * s, ph);
            MBARRIER_EXPECT_TX(sb + 8 * s, 16384);
            bulk_g2s(kvsm + s * 16384, KVsrc + (size_t)(t + 4) * 16384, 16384, sb + 8 * s);
        }
    }

    float inv0 = 1.0f / l0, inv1 = 1.0f / l1;
    char* outb = (char*)Ob + ((size_t)qb * 16 + h) * 32768;
    const int r128 = wid * 16 + r;
#pragma unroll
    for (int nt = 0; nt < 8; nt++) {
        int d = nt * 8 + cbase;
        float v0 = Oacc[nt][0] * inv0, v1 = Oacc[nt][1] * inv0;
        float v2 = Oacc[nt][2] * inv1, v3 = Oacc[nt][3] * inv1;
        uint32_t h01, l01, h23, l23;
        split2(v0, v1, h01, l01);
        split2(v2, v3, h23, l23);
        uint32_t o0 = SMEM_SWZ((uint32_t)(r128 * 128 + d * 2));
        uint32_t o1 = SMEM_SWZ((uint32_t)((r128 + 8) * 128 + d * 2));
        *(uint32_t*)(outb + o0) = h01; *(uint32_t*)(outb + 16384 + o0) = l01;
        *(uint32_t*)(outb + o1) = h23; *(uint32_t*)(outb + 16384 + o1) = l23;
    }
}

// ---------------------------------------------------------------------------
// LayerNorm
// ---------------------------------------------------------------------------
__device__ __forceinline__ float block_reduce_sum(float v) {
    __shared__ float red[8];
    int lane = threadIdx.x & 31, w = threadIdx.x >> 5;
#pragma unroll
    for (int o = 16; o > 0; o >>= 1) v += __shfl_xor_sync(0xffffffffu, v, o);
    __syncthreads();
    if (lane == 0) red[w] = v;
    __syncthreads();
    float t = 0.0f;
#pragma unroll
    for (int i = 0; i < 8; i++) t += red[i];
    return t;
}

__global__ __launch_bounds__(256) void ln_kernel(
    const float* __restrict__ res, const float* __restrict__ w,
    const float* __restrict__ b, float* __restrict__ out)
{
    int row = blockIdx.x;
    int tid = threadIdx.x;
    const float* r = res + (size_t)row * D_DIM;

    float4 x4 = *(const float4*)(r + tid * 4);
    float sum = x4.x + x4.y + x4.z + x4.w;
    sum = block_reduce_sum(sum);
    float mean = sum * (1.0f / D_DIM);

    float d0 = x4.x - mean, d1 = x4.y - mean, d2 = x4.z - mean, d3 = x4.w - mean;
    float sq = d0 * d0 + d1 * d1 + d2 * d2 + d3 * d3;
    sq = block_reduce_sum(sq);
    float inv = rsqrtf(sq * (1.0f / D_DIM) + LN_EPS);

    float4 w4 = *(const float4*)(w + tid * 4);
    float4 b4 = *(const float4*)(b + tid * 4);
    float4 o4;
    o4.x = d0 * inv * w4.x + b4.x;
    o4.y = d1 * inv * w4.y + b4.y;
    o4.z = d2 * inv * w4.z + b4.z;
    o4.w = d3 * inv * w4.w + b4.w;
    *(float4*)(out + (size_t)row * D_DIM + tid * 4) = o4;
}

// ---------------------------------------------------------------------------
// Launch
// ---------------------------------------------------------------------------
extern "C" void kernel_launch(void* const* d_in, const int* in_sizes, int n_in,
                              void* d_out, int out_size)
{
    (void)in_sizes; (void)n_in; (void)out_size;

    const float*        x    = (const float*)d_in[0];
    const float*        bias = (const float*)d_in[1];
    const unsigned int* mask = (const unsigned int*)d_in[2];
    const float*        Wq   = (const float*)d_in[3];
    const float*        Wk   = (const float*)d_in[4];
    const float*        Wv   = (const float*)d_in[5];
    const float*        Wo   = (const float*)d_in[6];
    const float*        lnw  = (const float*)d_in[7];
    const float*        lnb  = (const float*)d_in[8];
    float*              out  = (float*)d_out;

    void *pxb, *pwq, *pwk, *pwv, *pwo, *pqb, *pkv, *pab, *pres, *pmp;
    cudaGetSymbolAddress(&pxb, g_xb);
    cudaGetSymbolAddress(&pwq, g_wqb);
    cudaGetSymbolAddress(&pwk, g_wkb);
    cudaGetSymbolAddress(&pwv, g_wvb);
    cudaGetSymbolAddress(&pwo, g_wob);
    cudaGetSymbolAddress(&pqb, g_qb);
    cudaGetSymbolAddress(&pkv, g_kvb);
    cudaGetSymbolAddress(&pab, g_ab);
    cudaGetSymbolAddress(&pres, g_res);
    cudaGetSymbolAddress(&pmp, g_mpack);

    __half *xb = (__half*)pxb;
    __half *wqb = (__half*)pwq, *wkb = (__half*)pwk;
    __half *wvb = (__half*)pwv, *wob = (__half*)pwo;
    __half *qb = (__half*)pqb, *kvb = (__half*)pkv;
    __half *ab = (__half*)pab;
    float* res = (float*)pres;
    uint32_t* mp = (uint32_t*)pmp;

    cudaFuncSetAttribute(gemm_blob_kernel, cudaFuncAttributeMaxDynamicSharedMemorySize, GEMM_SMEM);
    cudaFuncSetAttribute(attn_blob_kernel, cudaFuncAttributeMaxDynamicSharedMemorySize, ATT_SMEM);

    dim3 gt(D_DIM / 128, S_LEN / 64);   // (8, 32) = 256 CTAs

    split_all_kernel<<<3072, 256>>>(x, Wq, Wk, Wv, Wo, xb, wqb, wkb, wvb, wob);
    pack_mask_kernel<<<S_LEN, 256>>>(mask, mp);

    gemm_blob_kernel<<<gt, 256, GEMM_SMEM>>>(xb, wqb, nullptr, nullptr, qb,
                                             1, 0.125f * LOG2E, D_DIM, D_DIM);
    gemm_blob_kernel<<<gt, 256, GEMM_SMEM>>>(xb, wkb, nullptr, nullptr, kvb,
                                             2, 1.0f, D_DIM, D_DIM);
    gemm_blob_kernel<<<gt, 256, GEMM_SMEM>>>(xb, wvb, nullptr, nullptr, kvb,
                                             3, 1.0f, D_DIM, D_DIM);

    attn_blob_kernel<<<dim3(S_LEN / 128, H_NUM), 256, ATT_SMEM>>>(qb, kvb, bias, mp, ab);

    gemm_blob_kernel<<<gt, 256, GEMM_SMEM>>>(ab, wob, x, res, nullptr,
                                             0, 1.0f, D_DIM, D_DIM);

    ln_kernel<<<S_LEN, 256>>>(res, lnw, lnb, out);
}

// round 14
// speedup vs baseline: 1.9663x; 1.0057x over previous
#include <cuda_runtime.h>
#include <cuda_fp16.h>
#include <cstdint>

// Problem constants
#define S_LEN 2048
#define D_DIM 1024
#define H_NUM 16
#define DH 64
#define LN_EPS 1e-5f
#define LOG2E 1.4426950408889634f

// ---------------------------------------------------------------------------
// PTX helpers
// ---------------------------------------------------------------------------
__device__ __forceinline__ uint32_t smem_u32(const void* p) {
    uint32_t a;
    asm("{ .reg .u64 t; cvta.to.shared.u64 t, %1; cvt.u32.u64 %0, t; }"
        : "=r"(a) : "l"(p));
    return a;
}

__device__ __forceinline__ void ldsm4(uint32_t* r, uint32_t a) {
    asm volatile("ldmatrix.sync.aligned.m8n8.x4.shared.b16 {%0,%1,%2,%3}, [%4];"
                 : "=r"(r[0]), "=r"(r[1]), "=r"(r[2]), "=r"(r[3]) : "r"(a));
}
__device__ __forceinline__ void ldsm4t(uint32_t* r, uint32_t a) {
    asm volatile("ldmatrix.sync.aligned.m8n8.x4.trans.shared.b16 {%0,%1,%2,%3}, [%4];"
                 : "=r"(r[0]), "=r"(r[1]), "=r"(r[2]), "=r"(r[3]) : "r"(a));
}

// fp16 MMA, fp32 accumulate
__device__ __forceinline__ void mma16816(float* c, const uint32_t* a, const uint32_t* b) {
    asm volatile("mma.sync.aligned.m16n8k16.row.col.f32.f16.f16.f32 "
                 "{%0,%1,%2,%3}, {%4,%5,%6,%7}, {%8,%9}, {%0,%1,%2,%3};"
                 : "+f"(c[0]), "+f"(c[1]), "+f"(c[2]), "+f"(c[3])
                 : "r"(a[0]), "r"(a[1]), "r"(a[2]), "r"(a[3]),
                   "r"(b[0]), "r"(b[1]));
}

#define MBARRIER_INIT(addr, cnt) \
    asm volatile("mbarrier.init.shared.b64 [%0], %1;" :: "r"((uint32_t)(addr)), "r"((uint32_t)(cnt)) : "memory")

#define MBARRIER_EXPECT_TX(addr, tx) \
    asm volatile("mbarrier.arrive.expect_tx.shared.b64 _, [%0], %1;" \
                 :: "r"((uint32_t)(addr)), "r"((uint32_t)(tx)) : "memory")

#define MBARRIER_ARRIVE(addr) \
    asm volatile("mbarrier.arrive.shared.b64 _, [%0];" \
                 :: "r"((uint32_t)(addr)) : "memory")

#define MBARRIER_WAIT_PARITY(mbar_smem_addr, phase_parity) do { \
    uint32_t _mbar = (uint32_t)(mbar_smem_addr); \
    uint32_t _parity = (uint32_t)(phase_parity); \
    uint32_t _done; \
    asm volatile("{\n\t.reg .pred p;\n\t" \
        "mbarrier.try_wait.parity.acquire.cta.shared::cta.b64 p, [%1], %2;\n\t" \
        "selp.b32 %0, 1, 0, p;\n\t}" \
        : "=r"(_done) : "r"(_mbar), "r"(_parity) : "memory"); \
    if (!_done) { \
        asm volatile("{\n\t.reg .pred P1;\n\t" \
            "WAIT_LOOP_%=:\n\t" \
            "mbarrier.try_wait.parity.acquire.cta.shared::cta.b64 P1, [%0], %1, 0x989680;\n\t" \
            "@P1 bra.uni WAIT_DONE_%=;\n\t" \
            "bra.uni WAIT_LOOP_%=;\n\t" \
            "WAIT_DONE_%=:\n\t}" \
            :: "r"(_mbar), "r"(_parity) : "memory"); \
    } \
} while (0)

__device__ __forceinline__ void bulk_g2s(uint32_t dst, const void* src, uint32_t bytes, uint32_t mbar) {
    asm volatile("cp.async.bulk.shared::cluster.global.mbarrier::complete_tx::bytes "
                 "[%0], [%1], %2, [%3];"
                 :: "r"(dst), "l"(src), "r"(bytes), "r"(mbar) : "memory");
}

#define FENCE_PROXY_ASYNC() asm volatile("fence.proxy.async.shared::cta;" ::: "memory")

#define SMEM_SWZ(off) ((off) ^ (((off) >> 3) & 0x70))

__device__ __forceinline__ uint32_t packh2(float a, float b) {
    __half2 t = __floats2half2_rn(a, b);
    return *reinterpret_cast<uint32_t*>(&t);
}
__device__ __forceinline__ void split2(float a, float b, uint32_t& hi, uint32_t& lo) {
    __half2 h = __floats2half2_rn(a, b);
    float2 hf = __half22float2(h);
    hi = *reinterpret_cast<uint32_t*>(&h);
    lo = packh2(a - hf.x, b - hf.y);
}
__device__ __forceinline__ float ex2(float x) {
    float y; asm("ex2.approx.ftz.f32 %0, %1;" : "=f"(y) : "f"(x)); return y;
}

// ---------------------------------------------------------------------------
// Scratch (device globals)
// ---------------------------------------------------------------------------
__device__ __align__(128) __half g_xb [2 * S_LEN * D_DIM];
__device__ __align__(128) __half g_wqb[D_DIM * D_DIM];
__device__ __align__(128) __half g_wkb[D_DIM * D_DIM];
__device__ __align__(128) __half g_wvb[D_DIM * D_DIM];
__device__ __align__(128) __half g_wob[D_DIM * D_DIM];
__device__ __align__(128) __half g_qb [2 * S_LEN * D_DIM];
__device__ __align__(128) __half g_kvb[2 * S_LEN * D_DIM];
__device__ __align__(128) __half g_ab [2 * S_LEN * D_DIM];
__device__ float g_res[S_LEN * D_DIM];
__device__ __align__(8) uint32_t g_mpack[S_LEN * (S_LEN / 32)];

// ---------------------------------------------------------------------------
// Mask bit-pack
// ---------------------------------------------------------------------------
__global__ __launch_bounds__(256) void pack_mask_kernel(
    const unsigned int* __restrict__ mask, uint32_t* __restrict__ mp)
{
    int row = blockIdx.x;
    int w = threadIdx.x >> 5;
    int lane = threadIdx.x & 31;
#pragma unroll
    for (int i = 0; i < 8; i++) {
        int word = w * 8 + i;
        unsigned int v = mask[(size_t)row * S_LEN + word * 32 + lane];
        unsigned int bal = __ballot_sync(0xffffffffu, v != 0u);
        if (lane == 0) mp[row * 64 + word] = bal;
    }
}

// ---------------------------------------------------------------------------
// Fused split: x -> hi/lo 32KB blocks; W -> hi-only 16KB blocks.
// ---------------------------------------------------------------------------
__global__ __launch_bounds__(256) void split_all_kernel(
    const float* __restrict__ x,
    const float* __restrict__ Wq, const float* __restrict__ Wk,
    const float* __restrict__ Wv, const float* __restrict__ Wo,
    __half* __restrict__ xb,
    __half* __restrict__ wqb, __half* __restrict__ wkb,
    __half* __restrict__ wvb, __half* __restrict__ wob)
{
    int bid = blockIdx.x;
    const float* src;
    __half* dst;
    int lbid;
    bool isx = (bid < 1024);
    if (isx) { src = x; dst = xb; lbid = bid; }
    else {
        int w = (bid - 1024) >> 9;
        lbid = (bid - 1024) & 511;
        src = (w == 0) ? Wq : (w == 1) ? Wk : (w == 2) ? Wv : Wo;
        dst = (w == 0) ? wqb : (w == 1) ? wkb : (w == 2) ? wvb : wob;
    }
    int idx = lbid * 256 + threadIdx.x;
    int row = idx >> 7;
    int k   = (idx & 127) * 8;

    float4 v0 = *(const float4*)(src + (size_t)row * D_DIM + k);
    float4 v1 = *(const float4*)(src + (size_t)row * D_DIM + k + 4);

    uint4 hi, lo;
    uint32_t h, l;
    split2(v0.x, v0.y, h, l); hi.x = h; lo.x = l;
    split2(v0.z, v0.w, h, l); hi.y = h; lo.y = l;
    split2(v1.x, v1.y, h, l); hi.z = h; lo.z = l;
    split2(v1.z, v1.w, h, l); hi.w = h; lo.w = l;

    uint32_t off = SMEM_SWZ((uint32_t)((row & 127) * 128 + (k & 63) * 2));
    if (isx) {
        size_t base = ((size_t)(row >> 7) * 16 + (k >> 6)) * 32768;
        char* p = (char*)dst + base;
        *(uint4*)(p + off) = hi;
        *(uint4*)(p + 16384 + off) = lo;
    } else {
        size_t base = ((size_t)(row >> 7) * 16 + (k >> 6)) * 16384;
        *(uint4*)((char*)dst + base + off) = hi;
    }
}

// ---------------------------------------------------------------------------
// Blob GEMM: tile 64x128, BK=64, 3-stage (96KB -> 2 CTAs/SM), grid (8,32).
// two_pass=1: Ah.Bh + Al.Bh.  two_pass=0: Ah.Bh only (pure fp16 A).
// modes: 0 = fp32 (+resid); 1 = Q blob; 2 = K blob; 3 = V blob
// ---------------------------------------------------------------------------
#define GSTAGE 32768
#define GEMM_SMEM (64 + 3 * GSTAGE)

__global__ __launch_bounds__(256, 2) void gemm_blob_kernel(
    const __half* __restrict__ Ablob, const __half* __restrict__ Bblob,
    const float* __restrict__ resid, float* __restrict__ Cf,
    __half* __restrict__ OutB, int mode, int two_pass, float scale, int N, int K)
{
    extern __shared__ char smem[];
    const uint32_t sb = smem_u32(smem);
    const int tid  = threadIdx.x;
    const int wid  = tid >> 5;
    const int lane = tid & 31;
    const int wm   = wid >> 2;
    const int wn   = wid & 3;

    const int mb = blockIdx.y;   // 64-row block (0..31)
    const int nb = blockIdx.x;   // 128-col block (0..7)
    const int NCH = K >> 6;

    const char* Abase = (const char*)Ablob + (size_t)(mb >> 1) * NCH * 32768
                        + (size_t)(mb & 1) * 8192;
    const char* Bsrc  = (const char*)Bblob + (size_t)nb * NCH * 16384;

    if (tid == 0) {
        MBARRIER_INIT(sb + 0, 1);
        MBARRIER_INIT(sb + 8, 1);
        MBARRIER_INIT(sb + 16, 1);
        FENCE_PROXY_ASYNC();
    }
    __syncthreads();

    const uint32_t tx_bytes = two_pass ? 32768u : 24576u;

    auto issue = [&](int ch) {
        const int s = ch % 3;
        uint32_t mbar = sb + 8 * s;
        uint32_t dst = sb + 64 + s * GSTAGE;
        const char* ab = Abase + (size_t)ch * 32768;
        MBARRIER_EXPECT_TX(mbar, tx_bytes);
        bulk_g2s(dst, ab, 8192, mbar);                                  // Ah
        if (two_pass) bulk_g2s(dst + 8192, ab + 16384, 8192, mbar);    // Al
        bulk_g2s(dst + 16384, Bsrc + (size_t)ch * 16384, 16384, mbar); // Bh
    };

    if (tid == 0) { issue(0); issue(1); issue(2); }

    float acc[2][4][4];
#pragma unroll
    for (int i = 0; i < 2; i++)
#pragma unroll
        for (int j = 0; j < 4; j++)
#pragma unroll
            for (int r = 0; r < 4; r++) acc[i][j][r] = 0.0f;

    const int arow = wm * 32 + (lane & 15);
    const int brow = wn * 32 + ((lane >> 4) & 1) * 8 + (lane & 7);

    for (int ch = 0; ch < NCH; ch++) {
        const int s = ch % 3;
        MBARRIER_WAIT_PARITY(sb + 8 * s, (ch / 3) & 1);

        const uint32_t bufA = sb + 64 + s * GSTAGE;
        const uint32_t bufB = bufA + 16384;

#pragma unroll
        for (int kc = 0; kc < 4; kc++) {
            uint32_t ah[2][4], alr[2][4], bh[4][2];
#pragma unroll
            for (int mt = 0; mt < 2; mt++) {
                uint32_t off = SMEM_SWZ((uint32_t)((arow + mt * 16) * 128 + kc * 32 + (lane >> 4) * 16));
                ldsm4(ah[mt], bufA + off);
                if (two_pass) ldsm4(alr[mt], bufA + 8192 + off);
            }
#pragma unroll
            for (int np = 0; np < 2; np++) {
                uint32_t off = SMEM_SWZ((uint32_t)((brow + np * 16) * 128 + kc * 32 + ((lane >> 3) & 1) * 16));
                uint32_t r[4];
                ldsm4(r, bufB + off);
                bh[np * 2][0] = r[0]; bh[np * 2][1] = r[1];
                bh[np * 2 + 1][0] = r[2]; bh[np * 2 + 1][1] = r[3];
            }
#pragma unroll
            for (int mt = 0; mt < 2; mt++)
#pragma unroll
                for (int nt = 0; nt < 4; nt++) {
                    mma16816(acc[mt][nt], ah[mt], bh[nt]);
                    if (two_pass) mma16816(acc[mt][nt], alr[mt], bh[nt]);
                }
        }
        __syncthreads();

        if (ch + 3 < NCH && tid == 0) issue(ch + 3);
    }

#pragma unroll
    for (int mt = 0; mt < 2; mt++) {
        int row = mb * 64 + wm * 32 + mt * 16 + (lane >> 2);
#pragma unroll
        for (int nt = 0; nt < 4; nt++) {
            int col = nb * 128 + wn * 32 + nt * 8 + (lane & 3) * 2;
            float v0 = acc[mt][nt][0] * scale;
            float v1 = acc[mt][nt][1] * scale;
            float v2 = acc[mt][nt][2] * scale;
            float v3 = acc[mt][nt][3] * scale;
            if (mode == 0) {
                if (resid) {
                    float2 r0 = *(const float2*)(resid + (size_t)row * N + col);
                    float2 r1 = *(const float2*)(resid + (size_t)(row + 8) * N + col);
                    v0 += r0.x; v1 += r0.y; v2 += r1.x; v3 += r1.y;
                }
                *(float2*)(Cf + (size_t)row * N + col) = make_float2(v0, v1);
                *(float2*)(Cf + (size_t)(row + 8) * N + col) = make_float2(v2, v3);
            } else if (mode == 1) {
                uint32_t h01, l01, h23, l23;
                split2(v0, v1, h01, l01);
                split2(v2, v3, h23, l23);
                size_t base = ((size_t)(row >> 7) * 16 + (col >> 6)) * 32768;
                uint32_t o0 = SMEM_SWZ((uint32_t)((row & 127) * 128 + (col & 63) * 2));
                uint32_t o1 = SMEM_SWZ((uint32_t)(((row + 8) & 127) * 128 + (col & 63) * 2));
                char* p = (char*)OutB + base;
                *(uint32_t*)(p + o0) = h01; *(uint32_t*)(p + 16384 + o0) = l01;
                *(uint32_t*)(p + o1) = h23; *(uint32_t*)(p + 16384 + o1) = l23;
            } else {
                size_t base = ((size_t)(col >> 6) * 32 + (row >> 6)) * 16384
                              + (mode == 3 ? 8192 : 0);
                uint32_t o0 = SMEM_SWZ((uint32_t)((row & 63) * 128 + (col & 63) * 2));
                uint32_t o1 = SMEM_SWZ((uint32_t)(((row + 8) & 63) * 128 + (col & 63) * 2));
                char* p = (char*)OutB + base;
                *(uint32_t*)(p + o0) = packh2(v0, v1);
                *(uint32_t*)(p + o1) = packh2(v2, v3);
            }
        }
    }
}

// ---------------------------------------------------------------------------
// Flash attention: fp16 QK 2-pass + PV 1-pass, 4-stage ring, 2 CTAs/SM.
// Epilogue writes hi-only (Wo GEMM is 1-pass).
// ---------------------------------------------------------------------------
#define ATT_SMEM (128 + 32768 + 4 * 16384)

__global__ __launch_bounds__(256, 2) void attn_blob_kernel(
    const __half* __restrict__ Qb, const __half* __restrict__ KVb,
    const float* __restrict__ bias, const uint32_t* __restrict__ mpack,
    __half* __restrict__ Ob)
{
    extern __shared__ char smem[];
    const uint32_t sb = smem_u32(smem);
    const uint32_t qsm  = sb + 128;
    const uint32_t kvsm = sb + 128 + 32768;
    const int tid  = threadIdx.x;
    const int wid  = tid >> 5;
    const int lane = tid & 31;
    const int h  = blockIdx.y;
    const int qb = blockIdx.x;
    const int q0 = qb * 128;

    const char* Qsrc  = (const char*)Qb + ((size_t)qb * 16 + h) * 32768;
    const char* KVsrc = (const char*)KVb + (size_t)h * 32 * 16384;

    if (tid == 0) {
#pragma unroll
        for (int i = 0; i < 4; i++) {
            MBARRIER_INIT(sb + 8 * i, 1);
            MBARRIER_INIT(sb + 32 + 8 * i, 256);
        }
        MBARRIER_INIT(sb + 64, 1);
        FENCE_PROXY_ASYNC();
    }
    __syncthreads();

    if (tid == 0) {
        MBARRIER_EXPECT_TX(sb + 64, 32768);
        bulk_g2s(qsm, Qsrc, 32768, sb + 64);
#pragma unroll
        for (int i = 0; i < 4; i++) {
            MBARRIER_EXPECT_TX(sb + 8 * i, 16384);
            bulk_g2s(kvsm + i * 16384, KVsrc + (size_t)i * 16384, 16384, sb + 8 * i);
        }
    }

    float Oacc[8][4];
#pragma unroll
    for (int i = 0; i < 8; i++)
#pragma unroll
        for (int j = 0; j < 4; j++) Oacc[i][j] = 0.0f;
    float m0 = -1e30f, m1 = -1e30f, l0 = 0.0f, l1 = 0.0f;

    const int r = lane >> 2;
    const int grow0 = q0 + wid * 16 + r;
    const int grow1 = grow0 + 8;
    const float* brow0 = bias + (size_t)grow0 * (H_NUM * S_LEN) + (size_t)h * S_LEN;
    const float* brow1 = bias + (size_t)grow1 * (H_NUM * S_LEN) + (size_t)h * S_LEN;
    const uint32_t* mp0 = mpack + grow0 * (S_LEN / 32);
    const uint32_t* mp1 = mpack + grow1 * (S_LEN / 32);
    const int cbase = (lane & 3) * 2;
    const int qrow = wid * 16 + (lane & 15);
    const int qsel = (lane >> 4) * 16;

    MBARRIER_WAIT_PARITY(sb + 64, 0);

    for (int t = 0; t < S_LEN / 64; t++) {
        const int s = t & 3;
        const int ph = (t >> 2) & 1;
        MBARRIER_WAIT_PARITY(sb + 8 * s, ph);
        const uint32_t base = kvsm + s * 16384;
        const int j0 = t * 64;

        uint2 mwa = *(const uint2*)(mp0 + (j0 >> 5));
        uint2 mwb = *(const uint2*)(mp1 + (j0 >> 5));
        uint64_t sm0 = (((uint64_t)mwa.y << 32) | mwa.x) >> cbase;
        uint64_t sm1 = (((uint64_t)mwb.y << 32) | mwb.x) >> cbase;

        float acc[8][4];
#pragma unroll
        for (int i = 0; i < 8; i++)
#pragma unroll
            for (int j = 0; j < 4; j++) acc[i][j] = 0.0f;

#pragma unroll
        for (int kc = 0; kc < 4; kc++) {
            uint32_t qh[4], ql[4];
            uint32_t qoff = SMEM_SWZ((uint32_t)(qrow * 128 + kc * 32 + qsel));
            ldsm4(qh, qsm + qoff);
            ldsm4(ql, qsm + 16384 + qoff);
#pragma unroll
            for (int np = 0; np < 4; np++) {
                int krow = np * 16 + (lane >> 4) * 8 + (lane & 7);
                uint32_t koff = SMEM_SWZ((uint32_t)(krow * 128 + kc * 32 + ((lane >> 3) & 1) * 16));
                uint32_t bh[4];
                ldsm4(bh, base + koff);
                mma16816(acc[2 * np],     qh, bh + 0);
                mma16816(acc[2 * np],     ql, bh + 0);
                mma16816(acc[2 * np + 1], qh, bh + 2);
                mma16816(acc[2 * np + 1], ql, bh + 2);
            }
        }

        float mx0 = -1e30f, mx1 = -1e30f;
#pragma unroll
        for (int nt = 0; nt < 8; nt++) {
            int c = nt * 8 + cbase;
            float2 b0 = *(const float2*)(brow0 + j0 + c);
            float2 b1 = *(const float2*)(brow1 + j0 + c);
            uint32_t w0 = (uint32_t)(sm0 >> (nt * 8));
            uint32_t w1 = (uint32_t)(sm1 >> (nt * 8));
            acc[nt][0] = (w0 & 1u) ? fmaf(b0.x, LOG2E, acc[nt][0]) : -1e30f;
            acc[nt][1] = (w0 & 2u) ? fmaf(b0.y, LOG2E, acc[nt][1]) : -1e30f;
            acc[nt][2] = (w1 & 1u) ? fmaf(b1.x, LOG2E, acc[nt][2]) : -1e30f;
            acc[nt][3] = (w1 & 2u) ? fmaf(b1.y, LOG2E, acc[nt][3]) : -1e30f;
            mx0 = fmaxf(mx0, fmaxf(acc[nt][0], acc[nt][1]));
            mx1 = fmaxf(mx1, fmaxf(acc[nt][2], acc[nt][3]));
        }
        mx0 = fmaxf(mx0, __shfl_xor_sync(0xffffffffu, mx0, 1));
        mx0 = fmaxf(mx0, __shfl_xor_sync(0xffffffffu, mx0, 2));
        mx1 = fmaxf(mx1, __shfl_xor_sync(0xffffffffu, mx1, 1));
        mx1 = fmaxf(mx1, __shfl_xor_sync(0xffffffffu, mx1, 2));

        float mn0 = fmaxf(m0, mx0), mn1 = fmaxf(m1, mx1);
        float a0 = ex2(m0 - mn0), a1 = ex2(m1 - mn1);
        m0 = mn0; m1 = mn1;

        float s0 = 0.0f, s1 = 0.0f;
#pragma unroll
        for (int nt = 0; nt < 8; nt++) {
            acc[nt][0] = ex2(acc[nt][0] - mn0);
            acc[nt][1] = ex2(acc[nt][1] - mn0);
            acc[nt][2] = ex2(acc[nt][2] - mn1);
            acc[nt][3] = ex2(acc[nt][3] - mn1);
            s0 += acc[nt][0] + acc[nt][1];
            s1 += acc[nt][2] + acc[nt][3];
        }
        s0 += __shfl_xor_sync(0xffffffffu, s0, 1);
        s0 += __shfl_xor_sync(0xffffffffu, s0, 2);
        s1 += __shfl_xor_sync(0xffffffffu, s1, 1);
        s1 += __shfl_xor_sync(0xffffffffu, s1, 2);
        l0 = l0 * a0 + s0;
        l1 = l1 * a1 + s1;

#pragma unroll
        for (int nt = 0; nt < 8; nt++) {
            Oacc[nt][0] *= a0; Oacc[nt][1] *= a0;
            Oacc[nt][2] *= a1; Oacc[nt][3] *= a1;
        }

#pragma unroll
        for (int kc = 0; kc < 4; kc++) {
            uint32_t pha[4];
            pha[0] = packh2(acc[2 * kc][0],     acc[2 * kc][1]);
            pha[1] = packh2(acc[2 * kc][2],     acc[2 * kc][3]);
            pha[2] = packh2(acc[2 * kc + 1][0], acc[2 * kc + 1][1]);
            pha[3] = packh2(acc[2 * kc + 1][2], acc[2 * kc + 1][3]);
#pragma unroll
            for (int dp = 0; dp < 4; dp++) {
                int vrow = kc * 16 + (lane & 15);
                uint32_t voff = SMEM_SWZ((uint32_t)(vrow * 128 + dp * 32 + (lane >> 4) * 16));
                uint32_t vh[4];
                ldsm4t(vh, base + 8192 + voff);
                mma16816(Oacc[2 * dp],     pha, vh + 0);
                mma16816(Oacc[2 * dp + 1], pha, vh + 2);
            }
        }

        MBARRIER_ARRIVE(sb + 32 + 8 * s);

        if (t + 4 < S_LEN / 64 && tid == 0) {
            MBARRIER_WAIT_PARITY(sb + 32 + 8 * s, ph);
            MBARRIER_EXPECT_TX(sb + 8 * s, 16384);
            bulk_g2s(kvsm + s * 16384, KVsrc + (size_t)(t + 4) * 16384, 16384, sb + 8 * s);
        }
    }

    // epilogue: hi-only output (Wo GEMM reads Ah half only)
    float inv0 = 1.0f / l0, inv1 = 1.0f / l1;
    char* outb = (char*)Ob + ((size_t)qb * 16 + h) * 32768;
    const int r128 = wid * 16 + r;
#pragma unroll
    for (int nt = 0; nt < 8; nt++) {
        int d = nt * 8 + cbase;
        float v0 = Oacc[nt][0] * inv0, v1 = Oacc[nt][1] * inv0;
        float v2 = Oacc[nt][2] * inv1, v3 = Oacc[nt][3] * inv1;
        uint32_t o0 = SMEM_SWZ((uint32_t)(r128 * 128 + d * 2));
        uint32_t o1 = SMEM_SWZ((uint32_t)((r128 + 8) * 128 + d * 2));
        *(uint32_t*)(outb + o0) = packh2(v0, v1);
        *(uint32_t*)(outb + o1) = packh2(v2, v3);
    }
}

// ---------------------------------------------------------------------------
// LayerNorm
// ---------------------------------------------------------------------------
__device__ __forceinline__ float block_reduce_sum(float v) {
    __shared__ float red[8];
    int lane = threadIdx.x & 31, w = threadIdx.x >> 5;
#pragma unroll
    for (int o = 16; o > 0; o >>= 1) v += __shfl_xor_sync(0xffffffffu, v, o);
    __syncthreads();
    if (lane == 0) red[w] = v;
    __syncthreads();
    float t = 0.0f;
#pragma unroll
    for (int i = 0; i < 8; i++) t += red[i];
    return t;
}

__global__ __launch_bounds__(256) void ln_kernel(
    const float* __restrict__ res, const float* __restrict__ w,
    const float* __restrict__ b, float* __restrict__ out)
{
    int row = blockIdx.x;
    int tid = threadIdx.x;
    const float* r = res + (size_t)row * D_DIM;

    float4 x4 = *(const float4*)(r + tid * 4);
    float sum = x4.x + x4.y + x4.z + x4.w;
    sum = block_reduce_sum(sum);
    float mean = sum * (1.0f / D_DIM);

    float d0 = x4.x - mean, d1 = x4.y - mean, d2 = x4.z - mean, d3 = x4.w - mean;
    float sq = d0 * d0 + d1 * d1 + d2 * d2 + d3 * d3;
    sq = block_reduce_sum(sq);
    float inv = rsqrtf(sq * (1.0f / D_DIM) + LN_EPS);

    float4 w4 = *(const float4*)(w + tid * 4);
    float4 b4 = *(const float4*)(b + tid * 4);
    float4 o4;
    o4.x = d0 * inv * w4.x + b4.x;
    o4.y = d1 * inv * w4.y + b4.y;
    o4.z = d2 * inv * w4.z + b4.z;
    o4.w = d3 * inv * w4.w + b4.w;
    *(float4*)(out + (size_t)row * D_DIM + tid * 4) = o4;
}

// ---------------------------------------------------------------------------
// Launch
// ---------------------------------------------------------------------------
extern "C" void kernel_launch(void* const* d_in, const int* in_sizes, int n_in,
                              void* d_out, int out_size)
{
    (void)in_sizes; (void)n_in; (void)out_size;

    const float*        x    = (const float*)d_in[0];
    const float*        bias = (const float*)d_in[1];
    const unsigned int* mask = (const unsigned int*)d_in[2];
    const float*        Wq   = (const float*)d_in[3];
    const float*        Wk   = (const float*)d_in[4];
    const float*        Wv   = (const float*)d_in[5];
    const float*        Wo   = (const float*)d_in[6];
    const float*        lnw  = (const float*)d_in[7];
    const float*        lnb  = (const float*)d_in[8];
    float*              out  = (float*)d_out;

    void *pxb, *pwq, *pwk, *pwv, *pwo, *pqb, *pkv, *pab, *pres, *pmp;
    cudaGetSymbolAddress(&pxb, g_xb);
    cudaGetSymbolAddress(&pwq, g_wqb);
    cudaGetSymbolAddress(&pwk, g_wkb);
    cudaGetSymbolAddress(&pwv, g_wvb);
    cudaGetSymbolAddress(&pwo, g_wob);
    cudaGetSymbolAddress(&pqb, g_qb);
    cudaGetSymbolAddress(&pkv, g_kvb);
    cudaGetSymbolAddress(&pab, g_ab);
    cudaGetSymbolAddress(&pres, g_res);
    cudaGetSymbolAddress(&pmp, g_mpack);

    __half *xb = (__half*)pxb;
    __half *wqb = (__half*)pwq, *wkb = (__half*)pwk;
    __half *wvb = (__half*)pwv, *wob = (__half*)pwo;
    __half *qb = (__half*)pqb, *kvb = (__half*)pkv;
    __half *ab = (__half*)pab;
    float* res = (float*)pres;
    uint32_t* mp = (uint32_t*)pmp;

    cudaFuncSetAttribute(gemm_blob_kernel, cudaFuncAttributeMaxDynamicSharedMemorySize, GEMM_SMEM);
    cudaFuncSetAttribute(attn_blob_kernel, cudaFuncAttributeMaxDynamicSharedMemorySize, ATT_SMEM);

    dim3 gt(D_DIM / 128, S_LEN / 64);   // (8, 32) = 256 CTAs

    split_all_kernel<<<3072, 256>>>(x, Wq, Wk, Wv, Wo, xb, wqb, wkb, wvb, wob);
    pack_mask_kernel<<<S_LEN, 256>>>(mask, mp);

    gemm_blob_kernel<<<gt, 256, GEMM_SMEM>>>(xb, wqb, nullptr, nullptr, qb,
                                             1, 1, 0.125f * LOG2E, D_DIM, D_DIM);
    gemm_blob_kernel<<<gt, 256, GEMM_SMEM>>>(xb, wkb, nullptr, nullptr, kvb,
                                             2, 1, 1.0f, D_DIM, D_DIM);
    gemm_blob_kernel<<<gt, 256, GEMM_SMEM>>>(xb, wvb, nullptr, nullptr, kvb,
                                             3, 1, 1.0f, D_DIM, D_DIM);

    attn_blob_kernel<<<dim3(S_LEN / 128, H_NUM), 256, ATT_SMEM>>>(qb, kvb, bias, mp, ab);

    // Wo projection: pure-fp16 A (1-pass)
    gemm_blob_kernel<<<gt, 256, GEMM_SMEM>>>(ab, wob, x, res, nullptr,
                                             0, 0, 1.0f, D_DIM, D_DIM);

    ln_kernel<<<S_LEN, 256>>>(res, lnw, lnb, out);
}

// round 15
// speedup vs baseline: 2.2709x; 1.1549x over previous
#include <cuda_runtime.h>
#include <cuda_fp16.h>
#include <cstdint>

// Problem constants
#define S_LEN 2048
#define D_DIM 1024
#define H_NUM 16
#define DH 64
#define LN_EPS 1e-5f
#define LOG2E 1.4426950408889634f

// ---------------------------------------------------------------------------
// PTX helpers
// ---------------------------------------------------------------------------
__device__ __forceinline__ uint32_t smem_u32(const void* p) {
    uint32_t a;
    asm("{ .reg .u64 t; cvta.to.shared.u64 t, %1; cvt.u32.u64 %0, t; }"
        : "=r"(a) : "l"(p));
    return a;
}

__device__ __forceinline__ void ldsm4(uint32_t* r, uint32_t a) {
    asm volatile("ldmatrix.sync.aligned.m8n8.x4.shared.b16 {%0,%1,%2,%3}, [%4];"
                 : "=r"(r[0]), "=r"(r[1]), "=r"(r[2]), "=r"(r[3]) : "r"(a));
}
__device__ __forceinline__ void ldsm4t(uint32_t* r, uint32_t a) {
    asm volatile("ldmatrix.sync.aligned.m8n8.x4.trans.shared.b16 {%0,%1,%2,%3}, [%4];"
                 : "=r"(r[0]), "=r"(r[1]), "=r"(r[2]), "=r"(r[3]) : "r"(a));
}

// fp16 MMA, fp32 accumulate
__device__ __forceinline__ void mma16816(float* c, const uint32_t* a, const uint32_t* b) {
    asm volatile("mma.sync.aligned.m16n8k16.row.col.f32.f16.f16.f32 "
                 "{%0,%1,%2,%3}, {%4,%5,%6,%7}, {%8,%9}, {%0,%1,%2,%3};"
                 : "+f"(c[0]), "+f"(c[1]), "+f"(c[2]), "+f"(c[3])
                 : "r"(a[0]), "r"(a[1]), "r"(a[2]), "r"(a[3]),
                   "r"(b[0]), "r"(b[1]));
}

#define MBARRIER_INIT(addr, cnt) \
    asm volatile("mbarrier.init.shared.b64 [%0], %1;" :: "r"((uint32_t)(addr)), "r"((uint32_t)(cnt)) : "memory")

#define MBARRIER_EXPECT_TX(addr, tx) \
    asm volatile("mbarrier.arrive.expect_tx.shared.b64 _, [%0], %1;" \
                 :: "r"((uint32_t)(addr)), "r"((uint32_t)(tx)) : "memory")

#define MBARRIER_ARRIVE(addr) \
    asm volatile("mbarrier.arrive.shared.b64 _, [%0];" \
                 :: "r"((uint32_t)(addr)) : "memory")

#define MBARRIER_WAIT_PARITY(mbar_smem_addr, phase_parity) do { \
    uint32_t _mbar = (uint32_t)(mbar_smem_addr); \
    uint32_t _parity = (uint32_t)(phase_parity); \
    uint32_t _done; \
    asm volatile("{\n\t.reg .pred p;\n\t" \
        "mbarrier.try_wait.parity.acquire.cta.shared::cta.b64 p, [%1], %2;\n\t" \
        "selp.b32 %0, 1, 0, p;\n\t}" \
        : "=r"(_done) : "r"(_mbar), "r"(_parity) : "memory"); \
    if (!_done) { \
        asm volatile("{\n\t.reg .pred P1;\n\t" \
            "WAIT_LOOP_%=:\n\t" \
            "mbarrier.try_wait.parity.acquire.cta.shared::cta.b64 P1, [%0], %1, 0x989680;\n\t" \
            "@P1 bra.uni WAIT_DONE_%=;\n\t" \
            "bra.uni WAIT_LOOP_%=;\n\t" \
            "WAIT_DONE_%=:\n\t}" \
            :: "r"(_mbar), "r"(_parity) : "memory"); \
    } \
} while (0)

__device__ __forceinline__ void bulk_g2s(uint32_t dst, const void* src, uint32_t bytes, uint32_t mbar) {
    asm volatile("cp.async.bulk.shared::cluster.global.mbarrier::complete_tx::bytes "
                 "[%0], [%1], %2, [%3];"
                 :: "r"(dst), "l"(src), "r"(bytes), "r"(mbar) : "memory");
}

#define FENCE_PROXY_ASYNC() asm volatile("fence.proxy.async.shared::cta;" ::: "memory")

#define SMEM_SWZ(off) ((off) ^ (((off) >> 3) & 0x70))

__device__ __forceinline__ uint32_t packh2(float a, float b) {
    __half2 t = __floats2half2_rn(a, b);
    return *reinterpret_cast<uint32_t*>(&t);
}
__device__ __forceinline__ void split2(float a, float b, uint32_t& hi, uint32_t& lo) {
    __half2 h = __floats2half2_rn(a, b);
    float2 hf = __half22float2(h);
    hi = *reinterpret_cast<uint32_t*>(&h);
    lo = packh2(a - hf.x, b - hf.y);
}
__device__ __forceinline__ float ex2(float x) {
    float y; asm("ex2.approx.ftz.f32 %0, %1;" : "=f"(y) : "f"(x)); return y;
}

// ---------------------------------------------------------------------------
// Scratch (device globals)
// ---------------------------------------------------------------------------
__device__ __align__(128) __half g_xb [2 * S_LEN * D_DIM];
__device__ __align__(128) __half g_wqb[D_DIM * D_DIM];
__device__ __align__(128) __half g_wkb[D_DIM * D_DIM];
__device__ __align__(128) __half g_wvb[D_DIM * D_DIM];
__device__ __align__(128) __half g_wob[D_DIM * D_DIM];
__device__ __align__(128) __half g_qb [2 * S_LEN * D_DIM];
__device__ __align__(128) __half g_kvb[2 * S_LEN * D_DIM];
__device__ __align__(128) __half g_ab [2 * S_LEN * D_DIM];
__device__ float g_res[S_LEN * D_DIM];
__device__ __align__(8) uint32_t g_mpack[S_LEN * (S_LEN / 32)];

// ---------------------------------------------------------------------------
// Mask bit-pack
// ---------------------------------------------------------------------------
__global__ __launch_bounds__(256) void pack_mask_kernel(
    const unsigned int* __restrict__ mask, uint32_t* __restrict__ mp)
{
    int row = blockIdx.x;
    int w = threadIdx.x >> 5;
    int lane = threadIdx.x & 31;
#pragma unroll
    for (int i = 0; i < 8; i++) {
        int word = w * 8 + i;
        unsigned int v = mask[(size_t)row * S_LEN + word * 32 + lane];
        unsigned int bal = __ballot_sync(0xffffffffu, v != 0u);
        if (lane == 0) mp[row * 64 + word] = bal;
    }
}

// ---------------------------------------------------------------------------
// Fused split: x -> hi/lo 32KB blocks; W -> hi-only 16KB blocks.
// ---------------------------------------------------------------------------
__global__ __launch_bounds__(256) void split_all_kernel(
    const float* __restrict__ x,
    const float* __restrict__ Wq, const float* __restrict__ Wk,
    const float* __restrict__ Wv, const float* __restrict__ Wo,
    __half* __restrict__ xb,
    __half* __restrict__ wqb, __half* __restrict__ wkb,
    __half* __restrict__ wvb, __half* __restrict__ wob)
{
    int bid = blockIdx.x;
    const float* src;
    __half* dst;
    int lbid;
    bool isx = (bid < 1024);
    if (isx) { src = x; dst = xb; lbid = bid; }
    else {
        int w = (bid - 1024) >> 9;
        lbid = (bid - 1024) & 511;
        src = (w == 0) ? Wq : (w == 1) ? Wk : (w == 2) ? Wv : Wo;
        dst = (w == 0) ? wqb : (w == 1) ? wkb : (w == 2) ? wvb : wob;
    }
    int idx = lbid * 256 + threadIdx.x;
    int row = idx >> 7;
    int k   = (idx & 127) * 8;

    float4 v0 = *(const float4*)(src + (size_t)row * D_DIM + k);
    float4 v1 = *(const float4*)(src + (size_t)row * D_DIM + k + 4);

    uint4 hi, lo;
    uint32_t h, l;
    split2(v0.x, v0.y, h, l); hi.x = h; lo.x = l;
    split2(v0.z, v0.w, h, l); hi.y = h; lo.y = l;
    split2(v1.x, v1.y, h, l); hi.z = h; lo.z = l;
    split2(v1.z, v1.w, h, l); hi.w = h; lo.w = l;

    uint32_t off = SMEM_SWZ((uint32_t)((row & 127) * 128 + (k & 63) * 2));
    if (isx) {
        size_t base = ((size_t)(row >> 7) * 16 + (k >> 6)) * 32768;
        char* p = (char*)dst + base;
        *(uint4*)(p + off) = hi;
        *(uint4*)(p + 16384 + off) = lo;
    } else {
        size_t base = ((size_t)(row >> 7) * 16 + (k >> 6)) * 16384;
        *(uint4*)((char*)dst + base + off) = hi;
    }
}

// ---------------------------------------------------------------------------
// Blob GEMM (R14): tile 64x128, BK=64, 3-stage, 2 CTAs/SM, grid (8,32).
// two_pass=1: Ah.Bh + Al.Bh.  two_pass=0: Ah.Bh only.
// modes: 0 = fp32 (+resid); 1 = Q blob; 2 = K blob; 3 = V blob
// ---------------------------------------------------------------------------
#define GSTAGE 32768
#define GEMM_SMEM (64 + 3 * GSTAGE)

__global__ __launch_bounds__(256, 2) void gemm_blob_kernel(
    const __half* __restrict__ Ablob, const __half* __restrict__ Bblob,
    const float* __restrict__ resid, float* __restrict__ Cf,
    __half* __restrict__ OutB, int mode, int two_pass, float scale, int N, int K)
{
    extern __shared__ char smem[];
    const uint32_t sb = smem_u32(smem);
    const int tid  = threadIdx.x;
    const int wid  = tid >> 5;
    const int lane = tid & 31;
    const int wm   = wid >> 2;
    const int wn   = wid & 3;

    const int mb = blockIdx.y;
    const int nb = blockIdx.x;
    const int NCH = K >> 6;

    const char* Abase = (const char*)Ablob + (size_t)(mb >> 1) * NCH * 32768
                        + (size_t)(mb & 1) * 8192;
    const char* Bsrc  = (const char*)Bblob + (size_t)nb * NCH * 16384;

    if (tid == 0) {
        MBARRIER_INIT(sb + 0, 1);
        MBARRIER_INIT(sb + 8, 1);
        MBARRIER_INIT(sb + 16, 1);
        FENCE_PROXY_ASYNC();
    }
    __syncthreads();

    const uint32_t tx_bytes = two_pass ? 32768u : 24576u;

    auto issue = [&](int ch) {
        const int s = ch % 3;
        uint32_t mbar = sb + 8 * s;
        uint32_t dst = sb + 64 + s * GSTAGE;
        const char* ab = Abase + (size_t)ch * 32768;
        MBARRIER_EXPECT_TX(mbar, tx_bytes);
        bulk_g2s(dst, ab, 8192, mbar);
        if (two_pass) bulk_g2s(dst + 8192, ab + 16384, 8192, mbar);
        bulk_g2s(dst + 16384, Bsrc + (size_t)ch * 16384, 16384, mbar);
    };

    if (tid == 0) { issue(0); issue(1); issue(2); }

    float acc[2][4][4];
#pragma unroll
    for (int i = 0; i < 2; i++)
#pragma unroll
        for (int j = 0; j < 4; j++)
#pragma unroll
            for (int r = 0; r < 4; r++) acc[i][j][r] = 0.0f;

    const int arow = wm * 32 + (lane & 15);
    const int brow = wn * 32 + ((lane >> 4) & 1) * 8 + (lane & 7);

    for (int ch = 0; ch < NCH; ch++) {
        const int s = ch % 3;
        MBARRIER_WAIT_PARITY(sb + 8 * s, (ch / 3) & 1);

        const uint32_t bufA = sb + 64 + s * GSTAGE;
        const uint32_t bufB = bufA + 16384;

#pragma unroll
        for (int kc = 0; kc < 4; kc++) {
            uint32_t ah[2][4], alr[2][4], bh[4][2];
#pragma unroll
            for (int mt = 0; mt < 2; mt++) {
                uint32_t off = SMEM_SWZ((uint32_t)((arow + mt * 16) * 128 + kc * 32 + (lane >> 4) * 16));
                ldsm4(ah[mt], bufA + off);
                if (two_pass) ldsm4(alr[mt], bufA + 8192 + off);
            }
#pragma unroll
            for (int np = 0; np < 2; np++) {
                uint32_t off = SMEM_SWZ((uint32_t)((brow + np * 16) * 128 + kc * 32 + ((lane >> 3) & 1) * 16));
                uint32_t r[4];
                ldsm4(r, bufB + off);
                bh[np * 2][0] = r[0]; bh[np * 2][1] = r[1];
                bh[np * 2 + 1][0] = r[2]; bh[np * 2 + 1][1] = r[3];
            }
#pragma unroll
            for (int mt = 0; mt < 2; mt++)
#pragma unroll
                for (int nt = 0; nt < 4; nt++) {
                    mma16816(acc[mt][nt], ah[mt], bh[nt]);
                    if (two_pass) mma16816(acc[mt][nt], alr[mt], bh[nt]);
                }
        }
        __syncthreads();

        if (ch + 3 < NCH && tid == 0) issue(ch + 3);
    }

#pragma unroll
    for (int mt = 0; mt < 2; mt++) {
        int row = mb * 64 + wm * 32 + mt * 16 + (lane >> 2);
#pragma unroll
        for (int nt = 0; nt < 4; nt++) {
            int col = nb * 128 + wn * 32 + nt * 8 + (lane & 3) * 2;
            float v0 = acc[mt][nt][0] * scale;
            float v1 = acc[mt][nt][1] * scale;
            float v2 = acc[mt][nt][2] * scale;
            float v3 = acc[mt][nt][3] * scale;
            if (mode == 0) {
                if (resid) {
                    float2 r0 = *(const float2*)(resid + (size_t)row * N + col);
                    float2 r1 = *(const float2*)(resid + (size_t)(row + 8) * N + col);
                    v0 += r0.x; v1 += r0.y; v2 += r1.x; v3 += r1.y;
                }
                *(float2*)(Cf + (size_t)row * N + col) = make_float2(v0, v1);
                *(float2*)(Cf + (size_t)(row + 8) * N + col) = make_float2(v2, v3);
            } else if (mode == 1) {
                uint32_t h01, l01, h23, l23;
                split2(v0, v1, h01, l01);
                split2(v2, v3, h23, l23);
                size_t base = ((size_t)(row >> 7) * 16 + (col >> 6)) * 32768;
                uint32_t o0 = SMEM_SWZ((uint32_t)((row & 127) * 128 + (col & 63) * 2));
                uint32_t o1 = SMEM_SWZ((uint32_t)(((row + 8) & 127) * 128 + (col & 63) * 2));
                char* p = (char*)OutB + base;
                *(uint32_t*)(p + o0) = h01; *(uint32_t*)(p + 16384 + o0) = l01;
                *(uint32_t*)(p + o1) = h23; *(uint32_t*)(p + 16384 + o1) = l23;
            } else {
                size_t base = ((size_t)(col >> 6) * 32 + (row >> 6)) * 16384
                              + (mode == 3 ? 8192 : 0);
                uint32_t o0 = SMEM_SWZ((uint32_t)((row & 63) * 128 + (col & 63) * 2));
                uint32_t o1 = SMEM_SWZ((uint32_t)(((row + 8) & 63) * 128 + (col & 63) * 2));
                char* p = (char*)OutB + base;
                *(uint32_t*)(p + o0) = packh2(v0, v1);
                *(uint32_t*)(p + o1) = packh2(v2, v3);
            }
        }
    }
}

// ---------------------------------------------------------------------------
// Flash attention: fp16 QK 2-pass + PV 1-pass, 4-stage ring, 2 CTAs/SM.
// Bias loads HOISTED before QK MMAs (latency covered by tensor phase).
// ---------------------------------------------------------------------------
#define ATT_SMEM (128 + 32768 + 4 * 16384)

__global__ __launch_bounds__(256, 2) void attn_blob_kernel(
    const __half* __restrict__ Qb, const __half* __restrict__ KVb,
    const float* __restrict__ bias, const uint32_t* __restrict__ mpack,
    __half* __restrict__ Ob)
{
    extern __shared__ char smem[];
    const uint32_t sb = smem_u32(smem);
    const uint32_t qsm  = sb + 128;
    const uint32_t kvsm = sb + 128 + 32768;
    const int tid  = threadIdx.x;
    const int wid  = tid >> 5;
    const int lane = tid & 31;
    const int h  = blockIdx.y;
    const int qb = blockIdx.x;
    const int q0 = qb * 128;

    const char* Qsrc  = (const char*)Qb + ((size_t)qb * 16 + h) * 32768;
    const char* KVsrc = (const char*)KVb + (size_t)h * 32 * 16384;

    if (tid == 0) {
#pragma unroll
        for (int i = 0; i < 4; i++) {
            MBARRIER_INIT(sb + 8 * i, 1);
            MBARRIER_INIT(sb + 32 + 8 * i, 256);
        }
        MBARRIER_INIT(sb + 64, 1);
        FENCE_PROXY_ASYNC();
    }
    __syncthreads();

    if (tid == 0) {
        MBARRIER_EXPECT_TX(sb + 64, 32768);
        bulk_g2s(qsm, Qsrc, 32768, sb + 64);
#pragma unroll
        for (int i = 0; i < 4; i++) {
            MBARRIER_EXPECT_TX(sb + 8 * i, 16384);
            bulk_g2s(kvsm + i * 16384, KVsrc + (size_t)i * 16384, 16384, sb + 8 * i);
        }
    }

    float Oacc[8][4];
#pragma unroll
    for (int i = 0; i < 8; i++)
#pragma unroll
        for (int j = 0; j < 4; j++) Oacc[i][j] = 0.0f;
    float m0 = -1e30f, m1 = -1e30f, l0 = 0.0f, l1 = 0.0f;

    const int r = lane >> 2;
    const int grow0 = q0 + wid * 16 + r;
    const int grow1 = grow0 + 8;
    const float* brow0 = bias + (size_t)grow0 * (H_NUM * S_LEN) + (size_t)h * S_LEN;
    const float* brow1 = bias + (size_t)grow1 * (H_NUM * S_LEN) + (size_t)h * S_LEN;
    const uint32_t* mp0 = mpack + grow0 * (S_LEN / 32);
    const uint32_t* mp1 = mpack + grow1 * (S_LEN / 32);
    const int cbase = (lane & 3) * 2;
    const int qrow = wid * 16 + (lane & 15);
    const int qsel = (lane >> 4) * 16;

    MBARRIER_WAIT_PARITY(sb + 64, 0);

    for (int t = 0; t < S_LEN / 64; t++) {
        const int s = t & 3;
        const int ph = (t >> 2) & 1;
        MBARRIER_WAIT_PARITY(sb + 8 * s, ph);
        const uint32_t base = kvsm + s * 16384;
        const int j0 = t * 64;

        uint2 mwa = *(const uint2*)(mp0 + (j0 >> 5));
        uint2 mwb = *(const uint2*)(mp1 + (j0 >> 5));
        uint64_t sm0 = (((uint64_t)mwa.y << 32) | mwa.x) >> cbase;
        uint64_t sm1 = (((uint64_t)mwb.y << 32) | mwb.x) >> cbase;

        // ---- hoisted bias loads: issued before the QK tensor phase so the
        //      ~600-cyc DRAM latency is covered by MMA execution ----
        float2 bv0[8], bv1[8];
#pragma unroll
        for (int nt = 0; nt < 8; nt++) {
            bv0[nt] = *(const float2*)(brow0 + j0 + nt * 8 + cbase);
            bv1[nt] = *(const float2*)(brow1 + j0 + nt * 8 + cbase);
        }

        float acc[8][4];
#pragma unroll
        for (int i = 0; i < 8; i++)
#pragma unroll
            for (int j = 0; j < 4; j++) acc[i][j] = 0.0f;

#pragma unroll
        for (int kc = 0; kc < 4; kc++) {
            uint32_t qh[4], ql[4];
            uint32_t qoff = SMEM_SWZ((uint32_t)(qrow * 128 + kc * 32 + qsel));
            ldsm4(qh, qsm + qoff);
            ldsm4(ql, qsm + 16384 + qoff);
#pragma unroll
            for (int np = 0; np < 4; np++) {
                int krow = np * 16 + (lane >> 4) * 8 + (lane & 7);
                uint32_t koff = SMEM_SWZ((uint32_t)(krow * 128 + kc * 32 + ((lane >> 3) & 1) * 16));
                uint32_t bh[4];
                ldsm4(bh, base + koff);
                mma16816(acc[2 * np],     qh, bh + 0);
                mma16816(acc[2 * np],     ql, bh + 0);
                mma16816(acc[2 * np + 1], qh, bh + 2);
                mma16816(acc[2 * np + 1], ql, bh + 2);
            }
        }

        float mx0 = -1e30f, mx1 = -1e30f;
#pragma unroll
        for (int nt = 0; nt < 8; nt++) {
            uint32_t w0 = (uint32_t)(sm0 >> (nt * 8));
            uint32_t w1 = (uint32_t)(sm1 >> (nt * 8));
            acc[nt][0] = (w0 & 1u) ? fmaf(bv0[nt].x, LOG2E, acc[nt][0]) : -1e30f;
            acc[nt][1] = (w0 & 2u) ? fmaf(bv0[nt].y, LOG2E, acc[nt][1]) : -1e30f;
            acc[nt][2] = (w1 & 1u) ? fmaf(bv1[nt].x, LOG2E, acc[nt][2]) : -1e30f;
            acc[nt][3] = (w1 & 2u) ? fmaf(bv1[nt].y, LOG2E, acc[nt][3]) : -1e30f;
            mx0 = fmaxf(mx0, fmaxf(acc[nt][0], acc[nt][1]));
            mx1 = fmaxf(mx1, fmaxf(acc[nt][2], acc[nt][3]));
        }
        mx0 = fmaxf(mx0, __shfl_xor_sync(0xffffffffu, mx0, 1));
        mx0 = fmaxf(mx0, __shfl_xor_sync(0xffffffffu, mx0, 2));
        mx1 = fmaxf(mx1, __shfl_xor_sync(0xffffffffu, mx1, 1));
        mx1 = fmaxf(mx1, __shfl_xor_sync(0xffffffffu, mx1, 2));

        float mn0 = fmaxf(m0, mx0), mn1 = fmaxf(m1, mx1);
        float a0 = ex2(m0 - mn0), a1 = ex2(m1 - mn1);
        m0 = mn0; m1 = mn1;

        float s0 = 0.0f, s1 = 0.0f;
#pragma unroll
        for (int nt = 0; nt < 8; nt++) {
            acc[nt][0] = ex2(acc[nt][0] - mn0);
            acc[nt][1] = ex2(acc[nt][1] - mn0);
            acc[nt][2] = ex2(acc[nt][2] - mn1);
            acc[nt][3] = ex2(acc[nt][3] - mn1);
            s0 += acc[nt][0] + acc[nt][1];
            s1 += acc[nt][2] + acc[nt][3];
        }
        s0 += __shfl_xor_sync(0xffffffffu, s0, 1);
        s0 += __shfl_xor_sync(0xffffffffu, s0, 2);
        s1 += __shfl_xor_sync(0xffffffffu, s1, 1);
        s1 += __shfl_xor_sync(0xffffffffu, s1, 2);
        l0 = l0 * a0 + s0;
        l1 = l1 * a1 + s1;

#pragma unroll
        for (int nt = 0; nt < 8; nt++) {
            Oacc[nt][0] *= a0; Oacc[nt][1] *= a0;
            Oacc[nt][2] *= a1; Oacc[nt][3] *= a1;
        }

#pragma unroll
        for (int kc = 0; kc < 4; kc++) {
            uint32_t pha[4];
            pha[0] = packh2(acc[2 * kc][0],     acc[2 * kc][1]);
            pha[1] = packh2(acc[2 * kc][2],     acc[2 * kc][3]);
            pha[2] = packh2(acc[2 * kc + 1][0], acc[2 * kc + 1][1]);
            pha[3] = packh2(acc[2 * kc + 1][2], acc[2 * kc + 1][3]);
#pragma unroll
            for (int dp = 0; dp < 4; dp++) {
                int vrow = kc * 16 + (lane & 15);
                uint32_t voff = SMEM_SWZ((uint32_t)(vrow * 128 + dp * 32 + (lane >> 4) * 16));
                uint32_t vh[4];
                ldsm4t(vh, base + 8192 + voff);
                mma16816(Oacc[2 * dp],     pha, vh + 0);
                mma16816(Oacc[2 * dp + 1], pha, vh + 2);
            }
        }

        MBARRIER_ARRIVE(sb + 32 + 8 * s);

        if (t + 4 < S_LEN / 64 && tid == 0) {
            MBARRIER_WAIT_PARITY(sb + 32 + 8 * s, ph);
            MBARRIER_EXPECT_TX(sb + 8 * s, 16384);
            bulk_g2s(kvsm + s * 16384, KVsrc + (size_t)(t + 4) * 16384, 16384, sb + 8 * s);
        }
    }

    float inv0 = 1.0f / l0, inv1 = 1.0f / l1;
    char* outb = (char*)Ob + ((size_t)qb * 16 + h) * 32768;
    const int r128 = wid * 16 + r;
#pragma unroll
    for (int nt = 0; nt < 8; nt++) {
        int d = nt * 8 + cbase;
        float v0 = Oacc[nt][0] * inv0, v1 = Oacc[nt][1] * inv0;
        float v2 = Oacc[nt][2] * inv1, v3 = Oacc[nt][3] * inv1;
        uint32_t o0 = SMEM_SWZ((uint32_t)(r128 * 128 + d * 2));
        uint32_t o1 = SMEM_SWZ((uint32_t)((r128 + 8) * 128 + d * 2));
        *(uint32_t*)(outb + o0) = packh2(v0, v1);
        *(uint32_t*)(outb + o1) = packh2(v2, v3);
    }
}

// ---------------------------------------------------------------------------
// LayerNorm
// ---------------------------------------------------------------------------
__device__ __forceinline__ float block_reduce_sum(float v) {
    __shared__ float red[8];
    int lane = threadIdx.x & 31, w = threadIdx.x >> 5;
#pragma unroll
    for (int o = 16; o > 0; o >>= 1) v += __shfl_xor_sync(0xffffffffu, v, o);
    __syncthreads();
    if (lane == 0) red[w] = v;
    __syncthreads();
    float t = 0.0f;
#pragma unroll
    for (int i = 0; i < 8; i++) t += red[i];
    return t;
}

__global__ __launch_bounds__(256) void ln_kernel(
    const float* __restrict__ res, const float* __restrict__ w,
    const float* __restrict__ b, float* __restrict__ out)
{
    int row = blockIdx.x;
    int tid = threadIdx.x;
    const float* r = res + (size_t)row * D_DIM;

    float4 x4 = *(const float4*)(r + tid * 4);
    float sum = x4.x + x4.y + x4.z + x4.w;
    sum = block_reduce_sum(sum);
    float mean = sum * (1.0f / D_DIM);

    float d0 = x4.x - mean, d1 = x4.y - mean, d2 = x4.z - mean, d3 = x4.w - mean;
    float sq = d0 * d0 + d1 * d1 + d2 * d2 + d3 * d3;
    sq = block_reduce_sum(sq);
    float inv = rsqrtf(sq * (1.0f / D_DIM) + LN_EPS);

    float4 w4 = *(const float4*)(w + tid * 4);
    float4 b4 = *(const float4*)(b + tid * 4);
    float4 o4;
    o4.x = d0 * inv * w4.x + b4.x;
    o4.y = d1 * inv * w4.y + b4.y;
    o4.z = d2 * inv * w4.z + b4.z;
    o4.w = d3 * inv * w4.w + b4.w;
    *(float4*)(out + (size_t)row * D_DIM + tid * 4) = o4;
}

// ---------------------------------------------------------------------------
// Launch
// ---------------------------------------------------------------------------
extern "C" void kernel_launch(void* const* d_in, const int* in_sizes, int n_in,
                              void* d_out, int out_size)
{
    (void)in_sizes; (void)n_in; (void)out_size;

    const float*        x    = (const float*)d_in[0];
    const float*        bias = (const float*)d_in[1];
    const unsigned int* mask = (const unsigned int*)d_in[2];
    const float*        Wq   = (const float*)d_in[3];
    const float*        Wk   = (const float*)d_in[4];
    const float*        Wv   = (const float*)d_in[5];
    const float*        Wo   = (const float*)d_in[6];
    const float*        lnw  = (const float*)d_in[7];
    const float*        lnb  = (const float*)d_in[8];
    float*              out  = (float*)d_out;

    void *pxb, *pwq, *pwk, *pwv, *pwo, *pqb, *pkv, *pab, *pres, *pmp;
    cudaGetSymbolAddress(&pxb, g_xb);
    cudaGetSymbolAddress(&pwq, g_wqb);
    cudaGetSymbolAddress(&pwk, g_wkb);
    cudaGetSymbolAddress(&pwv, g_wvb);
    cudaGetSymbolAddress(&pwo, g_wob);
    cudaGetSymbolAddress(&pqb, g_qb);
    cudaGetSymbolAddress(&pkv, g_kvb);
    cudaGetSymbolAddress(&pab, g_ab);
    cudaGetSymbolAddress(&pres, g_res);
    cudaGetSymbolAddress(&pmp, g_mpack);

    __half *xb = (__half*)pxb;
    __half *wqb = (__half*)pwq, *wkb = (__half*)pwk;
    __half *wvb = (__half*)pwv, *wob = (__half*)pwo;
    __half *qb = (__half*)pqb, *kvb = (__half*)pkv;
    __half *ab = (__half*)pab;
    float* res = (float*)pres;
    uint32_t* mp = (uint32_t*)pmp;

    cudaFuncSetAttribute(gemm_blob_kernel, cudaFuncAttributeMaxDynamicSharedMemorySize, GEMM_SMEM);
    cudaFuncSetAttribute(attn_blob_kernel, cudaFuncAttributeMaxDynamicSharedMemorySize, ATT_SMEM);

    dim3 gt(D_DIM / 128, S_LEN / 64);   // (8, 32) = 256 CTAs

    split_all_kernel<<<3072, 256>>>(x, Wq, Wk, Wv, Wo, xb, wqb, wkb, wvb, wob);
    pack_mask_kernel<<<S_LEN, 256>>>(mask, mp);

    gemm_blob_kernel<<<gt, 256, GEMM_SMEM>>>(xb, wqb, nullptr, nullptr, qb,
                                             1, 1, 0.125f * LOG2E, D_DIM, D_DIM);
    gemm_blob_kernel<<<gt, 256, GEMM_SMEM>>>(xb, wkb, nullptr, nullptr, kvb,
                                             2, 1, 1.0f, D_DIM, D_DIM);
    gemm_blob_kernel<<<gt, 256, GEMM_SMEM>>>(xb, wvb, nullptr, nullptr, kvb,
                                             3, 1, 1.0f, D_DIM, D_DIM);

    attn_blob_kernel<<<dim3(S_LEN / 128, H_NUM), 256, ATT_SMEM>>>(qb, kvb, bias, mp, ab);

    gemm_blob_kernel<<<gt, 256, GEMM_SMEM>>>(ab, wob, x, res, nullptr,
                                             0, 0, 1.0f, D_DIM, D_DIM);

    ln_kernel<<<S_LEN, 256>>>(res, lnw, lnb, out);
}

// round 16
// speedup vs baseline: 2.2712x; 1.0001x over previous
#include <cuda_runtime.h>
#include <cuda_fp16.h>
#include <cstdint>

// Problem constants
#define S_LEN 2048
#define D_DIM 1024
#define H_NUM 16
#define DH 64
#define LN_EPS 1e-5f
#define LOG2E 1.4426950408889634f

// ---------------------------------------------------------------------------
// PTX helpers
// ---------------------------------------------------------------------------
__device__ __forceinline__ uint32_t smem_u32(const void* p) {
    uint32_t a;
    asm("{ .reg .u64 t; cvta.to.shared.u64 t, %1; cvt.u32.u64 %0, t; }"
        : "=r"(a) : "l"(p));
    return a;
}

__device__ __forceinline__ void ldsm4(uint32_t* r, uint32_t a) {
    asm volatile("ldmatrix.sync.aligned.m8n8.x4.shared.b16 {%0,%1,%2,%3}, [%4];"
                 : "=r"(r[0]), "=r"(r[1]), "=r"(r[2]), "=r"(r[3]) : "r"(a));
}
__device__ __forceinline__ void ldsm4t(uint32_t* r, uint32_t a) {
    asm volatile("ldmatrix.sync.aligned.m8n8.x4.trans.shared.b16 {%0,%1,%2,%3}, [%4];"
                 : "=r"(r[0]), "=r"(r[1]), "=r"(r[2]), "=r"(r[3]) : "r"(a));
}

// fp16 MMA, fp32 accumulate
__device__ __forceinline__ void mma16816(float* c, const uint32_t* a, const uint32_t* b) {
    asm volatile("mma.sync.aligned.m16n8k16.row.col.f32.f16.f16.f32 "
                 "{%0,%1,%2,%3}, {%4,%5,%6,%7}, {%8,%9}, {%0,%1,%2,%3};"
                 : "+f"(c[0]), "+f"(c[1]), "+f"(c[2]), "+f"(c[3])
                 : "r"(a[0]), "r"(a[1]), "r"(a[2]), "r"(a[3]),
                   "r"(b[0]), "r"(b[1]));
}

#define MBARRIER_INIT(addr, cnt) \
    asm volatile("mbarrier.init.shared.b64 [%0], %1;" :: "r"((uint32_t)(addr)), "r"((uint32_t)(cnt)) : "memory")

#define MBARRIER_EXPECT_TX(addr, tx) \
    asm volatile("mbarrier.arrive.expect_tx.shared.b64 _, [%0], %1;" \
                 :: "r"((uint32_t)(addr)), "r"((uint32_t)(tx)) : "memory")

#define MBARRIER_ARRIVE(addr) \
    asm volatile("mbarrier.arrive.shared.b64 _, [%0];" \
                 :: "r"((uint32_t)(addr)) : "memory")

#define MBARRIER_WAIT_PARITY(mbar_smem_addr, phase_parity) do { \
    uint32_t _mbar = (uint32_t)(mbar_smem_addr); \
    uint32_t _parity = (uint32_t)(phase_parity); \
    uint32_t _done; \
    asm volatile("{\n\t.reg .pred p;\n\t" \
        "mbarrier.try_wait.parity.acquire.cta.shared::cta.b64 p, [%1], %2;\n\t" \
        "selp.b32 %0, 1, 0, p;\n\t}" \
        : "=r"(_done) : "r"(_mbar), "r"(_parity) : "memory"); \
    if (!_done) { \
        asm volatile("{\n\t.reg .pred P1;\n\t" \
            "WAIT_LOOP_%=:\n\t" \
            "mbarrier.try_wait.parity.acquire.cta.shared::cta.b64 P1, [%0], %1, 0x989680;\n\t" \
            "@P1 bra.uni WAIT_DONE_%=;\n\t" \
            "bra.uni WAIT_LOOP_%=;\n\t" \
            "WAIT_DONE_%=:\n\t}" \
            :: "r"(_mbar), "r"(_parity) : "memory"); \
    } \
} while (0)

__device__ __forceinline__ void bulk_g2s(uint32_t dst, const void* src, uint32_t bytes, uint32_t mbar) {
    asm volatile("cp.async.bulk.shared::cluster.global.mbarrier::complete_tx::bytes "
                 "[%0], [%1], %2, [%3];"
                 :: "r"(dst), "l"(src), "r"(bytes), "r"(mbar) : "memory");
}

#define FENCE_PROXY_ASYNC() asm volatile("fence.proxy.async.shared::cta;" ::: "memory")

#define SMEM_SWZ(off) ((off) ^ (((off) >> 3) & 0x70))

__device__ __forceinline__ uint32_t packh2(float a, float b) {
    __half2 t = __floats2half2_rn(a, b);
    return *reinterpret_cast<uint32_t*>(&t);
}
__device__ __forceinline__ void split2(float a, float b, uint32_t& hi, uint32_t& lo) {
    __half2 h = __floats2half2_rn(a, b);
    float2 hf = __half22float2(h);
    hi = *reinterpret_cast<uint32_t*>(&h);
    lo = packh2(a - hf.x, b - hf.y);
}
__device__ __forceinline__ float ex2(float x) {
    float y; asm("ex2.approx.ftz.f32 %0, %1;" : "=f"(y) : "f"(x)); return y;
}
// packed half2 exp2: one MUFU op for two values; the result IS the P fragment
__device__ __forceinline__ uint32_t ex2h2(uint32_t x) {
    uint32_t y; asm("ex2.approx.f16x2 %0, %1;" : "=r"(y) : "r"(x)); return y;
}
__device__ __forceinline__ float2 h2f2(uint32_t p) {
    __half2 h = *reinterpret_cast<__half2*>(&p);
    return __half22float2(h);
}

// ---------------------------------------------------------------------------
// Scratch (device globals)
// ---------------------------------------------------------------------------
__device__ __align__(128) __half g_xb [2 * S_LEN * D_DIM];
__device__ __align__(128) __half g_wqb[D_DIM * D_DIM];
__device__ __align__(128) __half g_wkb[D_DIM * D_DIM];
__device__ __align__(128) __half g_wvb[D_DIM * D_DIM];
__device__ __align__(128) __half g_wob[D_DIM * D_DIM];
__device__ __align__(128) __half g_qb [2 * S_LEN * D_DIM];
__device__ __align__(128) __half g_kvb[2 * S_LEN * D_DIM];
__device__ __align__(128) __half g_ab [2 * S_LEN * D_DIM];
__device__ float g_res[S_LEN * D_DIM];
__device__ __align__(8) uint32_t g_mpack[S_LEN * (S_LEN / 32)];

// ---------------------------------------------------------------------------
// Mask bit-pack
// ---------------------------------------------------------------------------
__global__ __launch_bounds__(256) void pack_mask_kernel(
    const unsigned int* __restrict__ mask, uint32_t* __restrict__ mp)
{
    int row = blockIdx.x;
    int w = threadIdx.x >> 5;
    int lane = threadIdx.x & 31;
#pragma unroll
    for (int i = 0; i < 8; i++) {
        int word = w * 8 + i;
        unsigned int v = mask[(size_t)row * S_LEN + word * 32 + lane];
        unsigned int bal = __ballot_sync(0xffffffffu, v != 0u);
        if (lane == 0) mp[row * 64 + word] = bal;
    }
}

// ---------------------------------------------------------------------------
// Fused split: x -> hi/lo 32KB blocks; W -> hi-only 16KB blocks.
// ---------------------------------------------------------------------------
__global__ __launch_bounds__(256) void split_all_kernel(
    const float* __restrict__ x,
    const float* __restrict__ Wq, const float* __restrict__ Wk,
    const float* __restrict__ Wv, const float* __restrict__ Wo,
    __half* __restrict__ xb,
    __half* __restrict__ wqb, __half* __restrict__ wkb,
    __half* __restrict__ wvb, __half* __restrict__ wob)
{
    int bid = blockIdx.x;
    const float* src;
    __half* dst;
    int lbid;
    bool isx = (bid < 1024);
    if (isx) { src = x; dst = xb; lbid = bid; }
    else {
        int w = (bid - 1024) >> 9;
        lbid = (bid - 1024) & 511;
        src = (w == 0) ? Wq : (w == 1) ? Wk : (w == 2) ? Wv : Wo;
        dst = (w == 0) ? wqb : (w == 1) ? wkb : (w == 2) ? wvb : wob;
    }
    int idx = lbid * 256 + threadIdx.x;
    int row = idx >> 7;
    int k   = (idx & 127) * 8;

    float4 v0 = *(const float4*)(src + (size_t)row * D_DIM + k);
    float4 v1 = *(const float4*)(src + (size_t)row * D_DIM + k + 4);

    uint4 hi, lo;
    uint32_t h, l;
    split2(v0.x, v0.y, h, l); hi.x = h; lo.x = l;
    split2(v0.z, v0.w, h, l); hi.y = h; lo.y = l;
    split2(v1.x, v1.y, h, l); hi.z = h; lo.z = l;
    split2(v1.z, v1.w, h, l); hi.w = h; lo.w = l;

    uint32_t off = SMEM_SWZ((uint32_t)((row & 127) * 128 + (k & 63) * 2));
    if (isx) {
        size_t base = ((size_t)(row >> 7) * 16 + (k >> 6)) * 32768;
        char* p = (char*)dst + base;
        *(uint4*)(p + off) = hi;
        *(uint4*)(p + 16384 + off) = lo;
    } else {
        size_t base = ((size_t)(row >> 7) * 16 + (k >> 6)) * 16384;
        *(uint4*)((char*)dst + base + off) = hi;
    }
}

// ---------------------------------------------------------------------------
// Blob GEMM (R14): tile 64x128, BK=64, 3-stage, 2 CTAs/SM, grid (8,32).
// two_pass=1: Ah.Bh + Al.Bh.  two_pass=0: Ah.Bh only.
// modes: 0 = fp32 (+resid); 1 = Q blob; 2 = K blob; 3 = V blob
// ---------------------------------------------------------------------------
#define GSTAGE 32768
#define GEMM_SMEM (64 + 3 * GSTAGE)

__global__ __launch_bounds__(256, 2) void gemm_blob_kernel(
    const __half* __restrict__ Ablob, const __half* __restrict__ Bblob,
    const float* __restrict__ resid, float* __restrict__ Cf,
    __half* __restrict__ OutB, int mode, int two_pass, float scale, int N, int K)
{
    extern __shared__ char smem[];
    const uint32_t sb = smem_u32(smem);
    const int tid  = threadIdx.x;
    const int wid  = tid >> 5;
    const int lane = tid & 31;
    const int wm   = wid >> 2;
    const int wn   = wid & 3;

    const int mb = blockIdx.y;
    const int nb = blockIdx.x;
    const int NCH = K >> 6;

    const char* Abase = (const char*)Ablob + (size_t)(mb >> 1) * NCH * 32768
                        + (size_t)(mb & 1) * 8192;
    const char* Bsrc  = (const char*)Bblob + (size_t)nb * NCH * 16384;

    if (tid == 0) {
        MBARRIER_INIT(sb + 0, 1);
        MBARRIER_INIT(sb + 8, 1);
        MBARRIER_INIT(sb + 16, 1);
        FENCE_PROXY_ASYNC();
    }
    __syncthreads();

    const uint32_t tx_bytes = two_pass ? 32768u : 24576u;

    auto issue = [&](int ch) {
        const int s = ch % 3;
        uint32_t mbar = sb + 8 * s;
        uint32_t dst = sb + 64 + s * GSTAGE;
        const char* ab = Abase + (size_t)ch * 32768;
        MBARRIER_EXPECT_TX(mbar, tx_bytes);
        bulk_g2s(dst, ab, 8192, mbar);
        if (two_pass) bulk_g2s(dst + 8192, ab + 16384, 8192, mbar);
        bulk_g2s(dst + 16384, Bsrc + (size_t)ch * 16384, 16384, mbar);
    };

    if (tid == 0) { issue(0); issue(1); issue(2); }

    float acc[2][4][4];
#pragma unroll
    for (int i = 0; i < 2; i++)
#pragma unroll
        for (int j = 0; j < 4; j++)
#pragma unroll
            for (int r = 0; r < 4; r++) acc[i][j][r] = 0.0f;

    const int arow = wm * 32 + (lane & 15);
    const int brow = wn * 32 + ((lane >> 4) & 1) * 8 + (lane & 7);

    for (int ch = 0; ch < NCH; ch++) {
        const int s = ch % 3;
        MBARRIER_WAIT_PARITY(sb + 8 * s, (ch / 3) & 1);

        const uint32_t bufA = sb + 64 + s * GSTAGE;
        const uint32_t bufB = bufA + 16384;

#pragma unroll
        for (int kc = 0; kc < 4; kc++) {
            uint32_t ah[2][4], alr[2][4], bh[4][2];
#pragma unroll
            for (int mt = 0; mt < 2; mt++) {
                uint32_t off = SMEM_SWZ((uint32_t)((arow + mt * 16) * 128 + kc * 32 + (lane >> 4) * 16));
                ldsm4(ah[mt], bufA + off);
                if (two_pass) ldsm4(alr[mt], bufA + 8192 + off);
            }
#pragma unroll
            for (int np = 0; np < 2; np++) {
                uint32_t off = SMEM_SWZ((uint32_t)((brow + np * 16) * 128 + kc * 32 + ((lane >> 3) & 1) * 16));
                uint32_t r[4];
                ldsm4(r, bufB + off);
                bh[np * 2][0] = r[0]; bh[np * 2][1] = r[1];
                bh[np * 2 + 1][0] = r[2]; bh[np * 2 + 1][1] = r[3];
            }
#pragma unroll
            for (int mt = 0; mt < 2; mt++)
#pragma unroll
                for (int nt = 0; nt < 4; nt++) {
                    mma16816(acc[mt][nt], ah[mt], bh[nt]);
                    if (two_pass) mma16816(acc[mt][nt], alr[mt], bh[nt]);
                }
        }
        __syncthreads();

        if (ch + 3 < NCH && tid == 0) issue(ch + 3);
    }

#pragma unroll
    for (int mt = 0; mt < 2; mt++) {
        int row = mb * 64 + wm * 32 + mt * 16 + (lane >> 2);
#pragma unroll
        for (int nt = 0; nt < 4; nt++) {
            int col = nb * 128 + wn * 32 + nt * 8 + (lane & 3) * 2;
            float v0 = acc[mt][nt][0] * scale;
            float v1 = acc[mt][nt][1] * scale;
            float v2 = acc[mt][nt][2] * scale;
            float v3 = acc[mt][nt][3] * scale;
            if (mode == 0) {
                if (resid) {
                    float2 r0 = *(const float2*)(resid + (size_t)row * N + col);
                    float2 r1 = *(const float2*)(resid + (size_t)(row + 8) * N + col);
                    v0 += r0.x; v1 += r0.y; v2 += r1.x; v3 += r1.y;
                }
                *(float2*)(Cf + (size_t)row * N + col) = make_float2(v0, v1);
                *(float2*)(Cf + (size_t)(row + 8) * N + col) = make_float2(v2, v3);
            } else if (mode == 1) {
                uint32_t h01, l01, h23, l23;
                split2(v0, v1, h01, l01);
                split2(v2, v3, h23, l23);
                size_t base = ((size_t)(row >> 7) * 16 + (col >> 6)) * 32768;
                uint32_t o0 = SMEM_SWZ((uint32_t)((row & 127) * 128 + (col & 63) * 2));
                uint32_t o1 = SMEM_SWZ((uint32_t)(((row + 8) & 127) * 128 + (col & 63) * 2));
                char* p = (char*)OutB + base;
                *(uint32_t*)(p + o0) = h01; *(uint32_t*)(p + 16384 + o0) = l01;
                *(uint32_t*)(p + o1) = h23; *(uint32_t*)(p + 16384 + o1) = l23;
            } else {
                size_t base = ((size_t)(col >> 6) * 32 + (row >> 6)) * 16384
                              + (mode == 3 ? 8192 : 0);
                uint32_t o0 = SMEM_SWZ((uint32_t)((row & 63) * 128 + (col & 63) * 2));
                uint32_t o1 = SMEM_SWZ((uint32_t)(((row + 8) & 63) * 128 + (col & 63) * 2));
                char* p = (char*)OutB + base;
                *(uint32_t*)(p + o0) = packh2(v0, v1);
                *(uint32_t*)(p + o1) = packh2(v2, v3);
            }
        }
    }
}

// ---------------------------------------------------------------------------
// Flash attention: fp16 QK 2-pass + PV 1-pass, 4-stage ring, 2 CTAs/SM.
// Bias loads hoisted; softmax exp via ex2.approx.f16x2 (result IS P fragment).
// ---------------------------------------------------------------------------
#define ATT_SMEM (128 + 32768 + 4 * 16384)

__global__ __launch_bounds__(256, 2) void attn_blob_kernel(
    const __half* __restrict__ Qb, const __half* __restrict__ KVb,
    const float* __restrict__ bias, const uint32_t* __restrict__ mpack,
    __half* __restrict__ Ob)
{
    extern __shared__ char smem[];
    const uint32_t sb = smem_u32(smem);
    const uint32_t qsm  = sb + 128;
    const uint32_t kvsm = sb + 128 + 32768;
    const int tid  = threadIdx.x;
    const int wid  = tid >> 5;
    const int lane = tid & 31;
    const int h  = blockIdx.y;
    const int qb = blockIdx.x;
    const int q0 = qb * 128;

    const char* Qsrc  = (const char*)Qb + ((size_t)qb * 16 + h) * 32768;
    const char* KVsrc = (const char*)KVb + (size_t)h * 32 * 16384;

    if (tid == 0) {
#pragma unroll
        for (int i = 0; i < 4; i++) {
            MBARRIER_INIT(sb + 8 * i, 1);
            MBARRIER_INIT(sb + 32 + 8 * i, 256);
        }
        MBARRIER_INIT(sb + 64, 1);
        FENCE_PROXY_ASYNC();
    }
    __syncthreads();

    if (tid == 0) {
        MBARRIER_EXPECT_TX(sb + 64, 32768);
        bulk_g2s(qsm, Qsrc, 32768, sb + 64);
#pragma unroll
        for (int i = 0; i < 4; i++) {
            MBARRIER_EXPECT_TX(sb + 8 * i, 16384);
            bulk_g2s(kvsm + i * 16384, KVsrc + (size_t)i * 16384, 16384, sb + 8 * i);
        }
    }

    float Oacc[8][4];
#pragma unroll
    for (int i = 0; i < 8; i++)
#pragma unroll
        for (int j = 0; j < 4; j++) Oacc[i][j] = 0.0f;
    float m0 = -1e30f, m1 = -1e30f, l0 = 0.0f, l1 = 0.0f;

    const int r = lane >> 2;
    const int grow0 = q0 + wid * 16 + r;
    const int grow1 = grow0 + 8;
    const float* brow0 = bias + (size_t)grow0 * (H_NUM * S_LEN) + (size_t)h * S_LEN;
    const float* brow1 = bias + (size_t)grow1 * (H_NUM * S_LEN) + (size_t)h * S_LEN;
    const uint32_t* mp0 = mpack + grow0 * (S_LEN / 32);
    const uint32_t* mp1 = mpack + grow1 * (S_LEN / 32);
    const int cbase = (lane & 3) * 2;
    const int qrow = wid * 16 + (lane & 15);
    const int qsel = (lane >> 4) * 16;

    MBARRIER_WAIT_PARITY(sb + 64, 0);

    for (int t = 0; t < S_LEN / 64; t++) {
        const int s = t & 3;
        const int ph = (t >> 2) & 1;
        MBARRIER_WAIT_PARITY(sb + 8 * s, ph);
        const uint32_t base = kvsm + s * 16384;
        const int j0 = t * 64;

        uint2 mwa = *(const uint2*)(mp0 + (j0 >> 5));
        uint2 mwb = *(const uint2*)(mp1 + (j0 >> 5));
        uint64_t sm0 = (((uint64_t)mwa.y << 32) | mwa.x) >> cbase;
        uint64_t sm1 = (((uint64_t)mwb.y << 32) | mwb.x) >> cbase;

        // hoisted bias loads (DRAM latency covered by QK tensor phase)
        float2 bv0[8], bv1[8];
#pragma unroll
        for (int nt = 0; nt < 8; nt++) {
            bv0[nt] = *(const float2*)(brow0 + j0 + nt * 8 + cbase);
            bv1[nt] = *(const float2*)(brow1 + j0 + nt * 8 + cbase);
        }

        float acc[8][4];
#pragma unroll
        for (int i = 0; i < 8; i++)
#pragma unroll
            for (int j = 0; j < 4; j++) acc[i][j] = 0.0f;

#pragma unroll
        for (int kc = 0; kc < 4; kc++) {
            uint32_t qh[4], ql[4];
            uint32_t qoff = SMEM_SWZ((uint32_t)(qrow * 128 + kc * 32 + qsel));
            ldsm4(qh, qsm + qoff);
            ldsm4(ql, qsm + 16384 + qoff);
#pragma unroll
            for (int np = 0; np < 4; np++) {
                int krow = np * 16 + (lane >> 4) * 8 + (lane & 7);
                uint32_t koff = SMEM_SWZ((uint32_t)(krow * 128 + kc * 32 + ((lane >> 3) & 1) * 16));
                uint32_t bh[4];
                ldsm4(bh, base + koff);
                mma16816(acc[2 * np],     qh, bh + 0);
                mma16816(acc[2 * np],     ql, bh + 0);
                mma16816(acc[2 * np + 1], qh, bh + 2);
                mma16816(acc[2 * np + 1], ql, bh + 2);
            }
        }

        float mx0 = -1e30f, mx1 = -1e30f;
#pragma unroll
        for (int nt = 0; nt < 8; nt++) {
            uint32_t w0 = (uint32_t)(sm0 >> (nt * 8));
            uint32_t w1 = (uint32_t)(sm1 >> (nt * 8));
            acc[nt][0] = (w0 & 1u) ? fmaf(bv0[nt].x, LOG2E, acc[nt][0]) : -1e30f;
            acc[nt][1] = (w0 & 2u) ? fmaf(bv0[nt].y, LOG2E, acc[nt][1]) : -1e30f;
            acc[nt][2] = (w1 & 1u) ? fmaf(bv1[nt].x, LOG2E, acc[nt][2]) : -1e30f;
            acc[nt][3] = (w1 & 2u) ? fmaf(bv1[nt].y, LOG2E, acc[nt][3]) : -1e30f;
            mx0 = fmaxf(mx0, fmaxf(acc[nt][0], acc[nt][1]));
            mx1 = fmaxf(mx1, fmaxf(acc[nt][2], acc[nt][3]));
        }
        mx0 = fmaxf(mx0, __shfl_xor_sync(0xffffffffu, mx0, 1));
        mx0 = fmaxf(mx0, __shfl_xor_sync(0xffffffffu, mx0, 2));
        mx1 = fmaxf(mx1, __shfl_xor_sync(0xffffffffu, mx1, 1));
        mx1 = fmaxf(mx1, __shfl_xor_sync(0xffffffffu, mx1, 2));

        float mn0 = fmaxf(m0, mx0), mn1 = fmaxf(m1, mx1);
        float a0 = ex2(m0 - mn0), a1 = ex2(m1 - mn1);
        m0 = mn0; m1 = mn1;

        // exp via f16x2 MUFU: result is the P fragment directly.
        // parr[nt][0] = P(row r,  cols c..c+1) ; parr[nt][1] = P(row r+8, ...)
        uint32_t parr[8][2];
        float s0 = 0.0f, s1 = 0.0f;
#pragma unroll
        for (int nt = 0; nt < 8; nt++) {
            uint32_t d01 = packh2(acc[nt][0] - mn0, acc[nt][1] - mn0);
            uint32_t d23 = packh2(acc[nt][2] - mn1, acc[nt][3] - mn1);
            parr[nt][0] = ex2h2(d01);
            parr[nt][1] = ex2h2(d23);
            float2 f01 = h2f2(parr[nt][0]);
            float2 f23 = h2f2(parr[nt][1]);
            s0 += f01.x + f01.y;
            s1 += f23.x + f23.y;
        }
        s0 += __shfl_xor_sync(0xffffffffu, s0, 1);
        s0 += __shfl_xor_sync(0xffffffffu, s0, 2);
        s1 += __shfl_xor_sync(0xffffffffu, s1, 1);
        s1 += __shfl_xor_sync(0xffffffffu, s1, 2);
        l0 = l0 * a0 + s0;
        l1 = l1 * a1 + s1;

#pragma unroll
        for (int nt = 0; nt < 8; nt++) {
            Oacc[nt][0] *= a0; Oacc[nt][1] *= a0;
            Oacc[nt][2] *= a1; Oacc[nt][3] *= a1;
        }

#pragma unroll
        for (int kc = 0; kc < 4; kc++) {
            uint32_t pha[4];
            pha[0] = parr[2 * kc][0];
            pha[1] = parr[2 * kc][1];
            pha[2] = parr[2 * kc + 1][0];
            pha[3] = parr[2 * kc + 1][1];
#pragma unroll
            for (int dp = 0; dp < 4; dp++) {
                int vrow = kc * 16 + (lane & 15);
                uint32_t voff = SMEM_SWZ((uint32_t)(vrow * 128 + dp * 32 + (lane >> 4) * 16));
                uint32_t vh[4];
                ldsm4t(vh, base + 8192 + voff);
                mma16816(Oacc[2 * dp],     pha, vh + 0);
                mma16816(Oacc[2 * dp + 1], pha, vh + 2);
            }
        }

        MBARRIER_ARRIVE(sb + 32 + 8 * s);

        if (t + 4 < S_LEN / 64 && tid == 0) {
            MBARRIER_WAIT_PARITY(sb + 32 + 8 * s, ph);
            MBARRIER_EXPECT_TX(sb + 8 * s, 16384);
            bulk_g2s(kvsm + s * 16384, KVsrc + (size_t)(t + 4) * 16384, 16384, sb + 8 * s);
        }
    }

    float inv0 = 1.0f / l0, inv1 = 1.0f / l1;
    char* outb = (char*)Ob + ((size_t)qb * 16 + h) * 32768;
    const int r128 = wid * 16 + r;
#pragma unroll
    for (int nt = 0; nt < 8; nt++) {
        int d = nt * 8 + cbase;
        float v0 = Oacc[nt][0] * inv0, v1 = Oacc[nt][1] * inv0;
        float v2 = Oacc[nt][2] * inv1, v3 = Oacc[nt][3] * inv1;
        uint32_t o0 = SMEM_SWZ((uint32_t)(r128 * 128 + d * 2));
        uint32_t o1 = SMEM_SWZ((uint32_t)((r128 + 8) * 128 + d * 2));
        *(uint32_t*)(outb + o0) = packh2(v0, v1);
        *(uint32_t*)(outb + o1) = packh2(v2, v3);
    }
}

// ---------------------------------------------------------------------------
// LayerNorm
// ---------------------------------------------------------------------------
__device__ __forceinline__ float block_reduce_sum(float v) {
    __shared__ float red[8];
    int lane = threadIdx.x & 31, w = threadIdx.x >> 5;
#pragma unroll
    for (int o = 16; o > 0; o >>= 1) v += __shfl_xor_sync(0xffffffffu, v, o);
    __syncthreads();
    if (lane == 0) red[w] = v;
    __syncthreads();
    float t = 0.0f;
#pragma unroll
    for (int i = 0; i < 8; i++) t += red[i];
    return t;
}

__global__ __launch_bounds__(256) void ln_kernel(
    const float* __restrict__ res, const float* __restrict__ w,
    const float* __restrict__ b, float* __restrict__ out)
{
    int row = blockIdx.x;
    int tid = threadIdx.x;
    const float* r = res + (size_t)row * D_DIM;

    float4 x4 = *(const float4*)(r + tid * 4);
    float sum = x4.x + x4.y + x4.z + x4.w;
    sum = block_reduce_sum(sum);
    float mean = sum * (1.0f / D_DIM);

    float d0 = x4.x - mean, d1 = x4.y - mean, d2 = x4.z - mean, d3 = x4.w - mean;
    float sq = d0 * d0 + d1 * d1 + d2 * d2 + d3 * d3;
    sq = block_reduce_sum(sq);
    float inv = rsqrtf(sq * (1.0f / D_DIM) + LN_EPS);

    float4 w4 = *(const float4*)(w + tid * 4);
    float4 b4 = *(const float4*)(b + tid * 4);
    float4 o4;
    o4.x = d0 * inv * w4.x + b4.x;
    o4.y = d1 * inv * w4.y + b4.y;
    o4.z = d2 * inv * w4.z + b4.z;
    o4.w = d3 * inv * w4.w + b4.w;
    *(float4*)(out + (size_t)row * D_DIM + tid * 4) = o4;
}

// ---------------------------------------------------------------------------
// Launch
// ---------------------------------------------------------------------------
extern "C" void kernel_launch(void* const* d_in, const int* in_sizes, int n_in,
                              void* d_out, int out_size)
{
    (void)in_sizes; (void)n_in; (void)out_size;

    const float*        x    = (const float*)d_in[0];
    const float*        bias = (const float*)d_in[1];
    const unsigned int* mask = (const unsigned int*)d_in[2];
    const float*        Wq   = (const float*)d_in[3];
    const float*        Wk   = (const float*)d_in[4];
    const float*        Wv   = (const float*)d_in[5];
    const float*        Wo   = (const float*)d_in[6];
    const float*        lnw  = (const float*)d_in[7];
    const float*        lnb  = (const float*)d_in[8];
    float*              out  = (float*)d_out;

    void *pxb, *pwq, *pwk, *pwv, *pwo, *pqb, *pkv, *pab, *pres, *pmp;
    cudaGetSymbolAddress(&pxb, g_xb);
    cudaGetSymbolAddress(&pwq, g_wqb);
    cudaGetSymbolAddress(&pwk, g_wkb);
    cudaGetSymbolAddress(&pwv, g_wvb);
    cudaGetSymbolAddress(&pwo, g_wob);
    cudaGetSymbolAddress(&pqb, g_qb);
    cudaGetSymbolAddress(&pkv, g_kvb);
    cudaGetSymbolAddress(&pab, g_ab);
    cudaGetSymbolAddress(&pres, g_res);
    cudaGetSymbolAddress(&pmp, g_mpack);

    __half *xb = (__half*)pxb;
    __half *wqb = (__half*)pwq, *wkb = (__half*)pwk;
    __half *wvb = (__half*)pwv, *wob = (__half*)pwo;
    __half *qb = (__half*)pqb, *kvb = (__half*)pkv;
    __half *ab = (__half*)pab;
    float* res = (float*)pres;
    uint32_t* mp = (uint32_t*)pmp;

    cudaFuncSetAttribute(gemm_blob_kernel, cudaFuncAttributeMaxDynamicSharedMemorySize, GEMM_SMEM);
    cudaFuncSetAttribute(attn_blob_kernel, cudaFuncAttributeMaxDynamicSharedMemorySize, ATT_SMEM);

    dim3 gt(D_DIM / 128, S_LEN / 64);   // (8, 32) = 256 CTAs

    split_all_kernel<<<3072, 256>>>(x, Wq, Wk, Wv, Wo, xb, wqb, wkb, wvb, wob);
    pack_mask_kernel<<<S_LEN, 256>>>(mask, mp);

    gemm_blob_kernel<<<gt, 256, GEMM_SMEM>>>(xb, wqb, nullptr, nullptr, qb,
                                             1, 1, 0.125f * LOG2E, D_DIM, D_DIM);
    gemm_blob_kernel<<<gt, 256, GEMM_SMEM>>>(xb, wkb, nullptr, nullptr, kvb,
                                             2, 1, 1.0f, D_DIM, D_DIM);
    // V projection: pure-fp16 x (1-pass) — linear error path, budget allows
    gemm_blob_kernel<<<gt, 256, GEMM_SMEM>>>(xb, wvb, nullptr, nullptr, kvb,
                                             3, 0, 1.0f, D_DIM, D_DIM);

    attn_blob_kernel<<<dim3(S_LEN / 128, H_NUM), 256, ATT_SMEM>>>(qb, kvb, bias, mp, ab);

    gemm_blob_kernel<<<gt, 256, GEMM_SMEM>>>(ab, wob, x, res, nullptr,
                                             0, 0, 1.0f, D_DIM, D_DIM);

    ln_kernel<<<S_LEN, 256>>>(res, lnw, lnb, out);
}

// round 17
// speedup vs baseline: 2.4107x; 1.0614x over previous
#include <cuda_runtime.h>
#include <cuda_fp16.h>
#include <cstdint>

// Problem constants
#define S_LEN 2048
#define D_DIM 1024
#define H_NUM 16
#define DH 64
#define LN_EPS 1e-5f
#define LOG2E 1.4426950408889634f

// ---------------------------------------------------------------------------
// PTX helpers
// ---------------------------------------------------------------------------
__device__ __forceinline__ uint32_t smem_u32(const void* p) {
    uint32_t a;
    asm("{ .reg .u64 t; cvta.to.shared.u64 t, %1; cvt.u32.u64 %0, t; }"
        : "=r"(a) : "l"(p));
    return a;
}

__device__ __forceinline__ void ldsm4(uint32_t* r, uint32_t a) {
    asm volatile("ldmatrix.sync.aligned.m8n8.x4.shared.b16 {%0,%1,%2,%3}, [%4];"
                 : "=r"(r[0]), "=r"(r[1]), "=r"(r[2]), "=r"(r[3]) : "r"(a));
}
__device__ __forceinline__ void ldsm4t(uint32_t* r, uint32_t a) {
    asm volatile("ldmatrix.sync.aligned.m8n8.x4.trans.shared.b16 {%0,%1,%2,%3}, [%4];"
                 : "=r"(r[0]), "=r"(r[1]), "=r"(r[2]), "=r"(r[3]) : "r"(a));
}

// fp16 MMA, fp32 accumulate
__device__ __forceinline__ void mma16816(float* c, const uint32_t* a, const uint32_t* b) {
    asm volatile("mma.sync.aligned.m16n8k16.row.col.f32.f16.f16.f32 "
                 "{%0,%1,%2,%3}, {%4,%5,%6,%7}, {%8,%9}, {%0,%1,%2,%3};"
                 : "+f"(c[0]), "+f"(c[1]), "+f"(c[2]), "+f"(c[3])
                 : "r"(a[0]), "r"(a[1]), "r"(a[2]), "r"(a[3]),
                   "r"(b[0]), "r"(b[1]));
}

#define MBARRIER_INIT(addr, cnt) \
    asm volatile("mbarrier.init.shared.b64 [%0], %1;" :: "r"((uint32_t)(addr)), "r"((uint32_t)(cnt)) : "memory")

#define MBARRIER_EXPECT_TX(addr, tx) \
    asm volatile("mbarrier.arrive.expect_tx.shared.b64 _, [%0], %1;" \
                 :: "r"((uint32_t)(addr)), "r"((uint32_t)(tx)) : "memory")

#define MBARRIER_ARRIVE(addr) \
    asm volatile("mbarrier.arrive.shared.b64 _, [%0];" \
                 :: "r"((uint32_t)(addr)) : "memory")

#define MBARRIER_WAIT_PARITY(mbar_smem_addr, phase_parity) do { \
    uint32_t _mbar = (uint32_t)(mbar_smem_addr); \
    uint32_t _parity = (uint32_t)(phase_parity); \
    uint32_t _done; \
    asm volatile("{\n\t.reg .pred p;\n\t" \
        "mbarrier.try_wait.parity.acquire.cta.shared::cta.b64 p, [%1], %2;\n\t" \
        "selp.b32 %0, 1, 0, p;\n\t}" \
        : "=r"(_done) : "r"(_mbar), "r"(_parity) : "memory"); \
    if (!_done) { \
        asm volatile("{\n\t.reg .pred P1;\n\t" \
            "WAIT_LOOP_%=:\n\t" \
            "mbarrier.try_wait.parity.acquire.cta.shared::cta.b64 P1, [%0], %1, 0x989680;\n\t" \
            "@P1 bra.uni WAIT_DONE_%=;\n\t" \
            "bra.uni WAIT_LOOP_%=;\n\t" \
            "WAIT_DONE_%=:\n\t}" \
            :: "r"(_mbar), "r"(_parity) : "memory"); \
    } \
} while (0)

__device__ __forceinline__ void bulk_g2s(uint32_t dst, const void* src, uint32_t bytes, uint32_t mbar) {
    asm volatile("cp.async.bulk.shared::cluster.global.mbarrier::complete_tx::bytes "
                 "[%0], [%1], %2, [%3];"
                 :: "r"(dst), "l"(src), "r"(bytes), "r"(mbar) : "memory");
}

#define FENCE_PROXY_ASYNC() asm volatile("fence.proxy.async.shared::cta;" ::: "memory")

#define SMEM_SWZ(off) ((off) ^ (((off) >> 3) & 0x70))

__device__ __forceinline__ uint32_t packh2(float a, float b) {
    __half2 t = __floats2half2_rn(a, b);
    return *reinterpret_cast<uint32_t*>(&t);
}
__device__ __forceinline__ void split2(float a, float b, uint32_t& hi, uint32_t& lo) {
    __half2 h = __floats2half2_rn(a, b);
    float2 hf = __half22float2(h);
    hi = *reinterpret_cast<uint32_t*>(&h);
    lo = packh2(a - hf.x, b - hf.y);
}
__device__ __forceinline__ float ex2(float x) {
    float y; asm("ex2.approx.ftz.f32 %0, %1;" : "=f"(y) : "f"(x)); return y;
}
__device__ __forceinline__ uint32_t ex2h2(uint32_t x) {
    uint32_t y; asm("ex2.approx.f16x2 %0, %1;" : "=r"(y) : "r"(x)); return y;
}
__device__ __forceinline__ float2 h2f2(uint32_t p) {
    __half2 h = *reinterpret_cast<__half2*>(&p);
    return __half22float2(h);
}

// ---------------------------------------------------------------------------
// Scratch (device globals)
//  x blob : [mb][ch] 32KB {hi, lo}
//  W blobs: [nb][ch] 16KB hi-only
//  Q blob : [qb][head] 16KB hi-only
//  KV blob: [head][tile] 16KB {Kh 8KB, Vh 8KB}
//  A blob : [mb][head] 32KB region, hi half used (Wo 1-pass)
// ---------------------------------------------------------------------------
__device__ __align__(128) __half g_xb [2 * S_LEN * D_DIM];
__device__ __align__(128) __half g_wqb[D_DIM * D_DIM];
__device__ __align__(128) __half g_wkb[D_DIM * D_DIM];
__device__ __align__(128) __half g_wvb[D_DIM * D_DIM];
__device__ __align__(128) __half g_wob[D_DIM * D_DIM];
__device__ __align__(128) __half g_qb [S_LEN * D_DIM];
__device__ __align__(128) __half g_kvb[2 * S_LEN * D_DIM];
__device__ __align__(128) __half g_ab [2 * S_LEN * D_DIM];
__device__ float g_res[S_LEN * D_DIM];
__device__ __align__(8) uint32_t g_mpack[S_LEN * (S_LEN / 32)];

// ---------------------------------------------------------------------------
// Mask bit-pack
// ---------------------------------------------------------------------------
__global__ __launch_bounds__(256) void pack_mask_kernel(
    const unsigned int* __restrict__ mask, uint32_t* __restrict__ mp)
{
    int row = blockIdx.x;
    int w = threadIdx.x >> 5;
    int lane = threadIdx.x & 31;
#pragma unroll
    for (int i = 0; i < 8; i++) {
        int word = w * 8 + i;
        unsigned int v = mask[(size_t)row * S_LEN + word * 32 + lane];
        unsigned int bal = __ballot_sync(0xffffffffu, v != 0u);
        if (lane == 0) mp[row * 64 + word] = bal;
    }
}

// ---------------------------------------------------------------------------
// Fused split: x -> hi/lo 32KB blocks; W -> hi-only 16KB blocks.
// ---------------------------------------------------------------------------
__global__ __launch_bounds__(256) void split_all_kernel(
    const float* __restrict__ x,
    const float* __restrict__ Wq, const float* __restrict__ Wk,
    const float* __restrict__ Wv, const float* __restrict__ Wo,
    __half* __restrict__ xb,
    __half* __restrict__ wqb, __half* __restrict__ wkb,
    __half* __restrict__ wvb, __half* __restrict__ wob)
{
    int bid = blockIdx.x;
    const float* src;
    __half* dst;
    int lbid;
    bool isx = (bid < 1024);
    if (isx) { src = x; dst = xb; lbid = bid; }
    else {
        int w = (bid - 1024) >> 9;
        lbid = (bid - 1024) & 511;
        src = (w == 0) ? Wq : (w == 1) ? Wk : (w == 2) ? Wv : Wo;
        dst = (w == 0) ? wqb : (w == 1) ? wkb : (w == 2) ? wvb : wob;
    }
    int idx = lbid * 256 + threadIdx.x;
    int row = idx >> 7;
    int k   = (idx & 127) * 8;

    float4 v0 = *(const float4*)(src + (size_t)row * D_DIM + k);
    float4 v1 = *(const float4*)(src + (size_t)row * D_DIM + k + 4);

    uint4 hi, lo;
    uint32_t h, l;
    split2(v0.x, v0.y, h, l); hi.x = h; lo.x = l;
    split2(v0.z, v0.w, h, l); hi.y = h; lo.y = l;
    split2(v1.x, v1.y, h, l); hi.z = h; lo.z = l;
    split2(v1.z, v1.w, h, l); hi.w = h; lo.w = l;

    uint32_t off = SMEM_SWZ((uint32_t)((row & 127) * 128 + (k & 63) * 2));
    if (isx) {
        size_t base = ((size_t)(row >> 7) * 16 + (k >> 6)) * 32768;
        char* p = (char*)dst + base;
        *(uint4*)(p + off) = hi;
        *(uint4*)(p + 16384 + off) = lo;
    } else {
        size_t base = ((size_t)(row >> 7) * 16 + (k >> 6)) * 16384;
        *(uint4*)((char*)dst + base + off) = hi;
    }
}

// ---------------------------------------------------------------------------
// Blob GEMM (R14): tile 64x128, BK=64, 3-stage, 2 CTAs/SM, grid (8,32).
// two_pass=1: Ah.Bh + Al.Bh.  two_pass=0: Ah.Bh only.
// modes: 0 = fp32 (+resid); 1 = Q blob (hi-only 16KB); 2 = K blob; 3 = V blob
// ---------------------------------------------------------------------------
#define GSTAGE 32768
#define GEMM_SMEM (64 + 3 * GSTAGE)

__global__ __launch_bounds__(256, 2) void gemm_blob_kernel(
    const __half* __restrict__ Ablob, const __half* __restrict__ Bblob,
    const float* __restrict__ resid, float* __restrict__ Cf,
    __half* __restrict__ OutB, int mode, int two_pass, float scale, int N, int K)
{
    extern __shared__ char smem[];
    const uint32_t sb = smem_u32(smem);
    const int tid  = threadIdx.x;
    const int wid  = tid >> 5;
    const int lane = tid & 31;
    const int wm   = wid >> 2;
    const int wn   = wid & 3;

    const int mb = blockIdx.y;
    const int nb = blockIdx.x;
    const int NCH = K >> 6;

    const char* Abase = (const char*)Ablob + (size_t)(mb >> 1) * NCH * 32768
                        + (size_t)(mb & 1) * 8192;
    const char* Bsrc  = (const char*)Bblob + (size_t)nb * NCH * 16384;

    if (tid == 0) {
        MBARRIER_INIT(sb + 0, 1);
        MBARRIER_INIT(sb + 8, 1);
        MBARRIER_INIT(sb + 16, 1);
        FENCE_PROXY_ASYNC();
    }
    __syncthreads();

    const uint32_t tx_bytes = two_pass ? 32768u : 24576u;

    auto issue = [&](int ch) {
        const int s = ch % 3;
        uint32_t mbar = sb + 8 * s;
        uint32_t dst = sb + 64 + s * GSTAGE;
        const char* ab = Abase + (size_t)ch * 32768;
        MBARRIER_EXPECT_TX(mbar, tx_bytes);
        bulk_g2s(dst, ab, 8192, mbar);
        if (two_pass) bulk_g2s(dst + 8192, ab + 16384, 8192, mbar);
        bulk_g2s(dst + 16384, Bsrc + (size_t)ch * 16384, 16384, mbar);
    };

    if (tid == 0) { issue(0); issue(1); issue(2); }

    float acc[2][4][4];
#pragma unroll
    for (int i = 0; i < 2; i++)
#pragma unroll
        for (int j = 0; j < 4; j++)
#pragma unroll
            for (int r = 0; r < 4; r++) acc[i][j][r] = 0.0f;

    const int arow = wm * 32 + (lane & 15);
    const int brow = wn * 32 + ((lane >> 4) & 1) * 8 + (lane & 7);

    for (int ch = 0; ch < NCH; ch++) {
        const int s = ch % 3;
        MBARRIER_WAIT_PARITY(sb + 8 * s, (ch / 3) & 1);

        const uint32_t bufA = sb + 64 + s * GSTAGE;
        const uint32_t bufB = bufA + 16384;

#pragma unroll
        for (int kc = 0; kc < 4; kc++) {
            uint32_t ah[2][4], alr[2][4], bh[4][2];
#pragma unroll
            for (int mt = 0; mt < 2; mt++) {
                uint32_t off = SMEM_SWZ((uint32_t)((arow + mt * 16) * 128 + kc * 32 + (lane >> 4) * 16));
                ldsm4(ah[mt], bufA + off);
                if (two_pass) ldsm4(alr[mt], bufA + 8192 + off);
            }
#pragma unroll
            for (int np = 0; np < 2; np++) {
                uint32_t off = SMEM_SWZ((uint32_t)((brow + np * 16) * 128 + kc * 32 + ((lane >> 3) & 1) * 16));
                uint32_t r[4];
                ldsm4(r, bufB + off);
                bh[np * 2][0] = r[0]; bh[np * 2][1] = r[1];
                bh[np * 2 + 1][0] = r[2]; bh[np * 2 + 1][1] = r[3];
            }
#pragma unroll
            for (int mt = 0; mt < 2; mt++)
#pragma unroll
                for (int nt = 0; nt < 4; nt++) {
                    mma16816(acc[mt][nt], ah[mt], bh[nt]);
                    if (two_pass) mma16816(acc[mt][nt], alr[mt], bh[nt]);
                }
        }
        __syncthreads();

        if (ch + 3 < NCH && tid == 0) issue(ch + 3);
    }

#pragma unroll
    for (int mt = 0; mt < 2; mt++) {
        int row = mb * 64 + wm * 32 + mt * 16 + (lane >> 2);
#pragma unroll
        for (int nt = 0; nt < 4; nt++) {
            int col = nb * 128 + wn * 32 + nt * 8 + (lane & 3) * 2;
            float v0 = acc[mt][nt][0] * scale;
            float v1 = acc[mt][nt][1] * scale;
            float v2 = acc[mt][nt][2] * scale;
            float v3 = acc[mt][nt][3] * scale;
            if (mode == 0) {
                if (resid) {
                    float2 r0 = *(const float2*)(resid + (size_t)row * N + col);
                    float2 r1 = *(const float2*)(resid + (size_t)(row + 8) * N + col);
                    v0 += r0.x; v1 += r0.y; v2 += r1.x; v3 += r1.y;
                }
                *(float2*)(Cf + (size_t)row * N + col) = make_float2(v0, v1);
                *(float2*)(Cf + (size_t)(row + 8) * N + col) = make_float2(v2, v3);
            } else if (mode == 1) {
                // Q blob: hi-only, 128-row 16KB blocks
                size_t base = ((size_t)(row >> 7) * 16 + (col >> 6)) * 16384;
                uint32_t o0 = SMEM_SWZ((uint32_t)((row & 127) * 128 + (col & 63) * 2));
                uint32_t o1 = SMEM_SWZ((uint32_t)(((row + 8) & 127) * 128 + (col & 63) * 2));
                char* p = (char*)OutB + base;
                *(uint32_t*)(p + o0) = packh2(v0, v1);
                *(uint32_t*)(p + o1) = packh2(v2, v3);
            } else {
                size_t base = ((size_t)(col >> 6) * 32 + (row >> 6)) * 16384
                              + (mode == 3 ? 8192 : 0);
                uint32_t o0 = SMEM_SWZ((uint32_t)((row & 63) * 128 + (col & 63) * 2));
                uint32_t o1 = SMEM_SWZ((uint32_t)(((row + 8) & 63) * 128 + (col & 63) * 2));
                char* p = (char*)OutB + base;
                *(uint32_t*)(p + o0) = packh2(v0, v1);
                *(uint32_t*)(p + o1) = packh2(v2, v3);
            }
        }
    }
}

// ---------------------------------------------------------------------------
// Flash attention: fp16 QK 1-pass + PV 1-pass, 4-stage ring, 2 CTAs/SM.
// Bias hoisted; exp via ex2.approx.f16x2 (result IS the P fragment).
// ---------------------------------------------------------------------------
#define ATT_SMEM (128 + 16384 + 4 * 16384)

__global__ __launch_bounds__(256, 2) void attn_blob_kernel(
    const __half* __restrict__ Qb, const __half* __restrict__ KVb,
    const float* __restrict__ bias, const uint32_t* __restrict__ mpack,
    __half* __restrict__ Ob)
{
    extern __shared__ char smem[];
    const uint32_t sb = smem_u32(smem);
    const uint32_t qsm  = sb + 128;
    const uint32_t kvsm = sb + 128 + 16384;
    const int tid  = threadIdx.x;
    const int wid  = tid >> 5;
    const int lane = tid & 31;
    const int h  = blockIdx.y;
    const int qb = blockIdx.x;
    const int q0 = qb * 128;

    const char* Qsrc  = (const char*)Qb + ((size_t)qb * 16 + h) * 16384;
    const char* KVsrc = (const char*)KVb + (size_t)h * 32 * 16384;

    if (tid == 0) {
#pragma unroll
        for (int i = 0; i < 4; i++) {
            MBARRIER_INIT(sb + 8 * i, 1);
            MBARRIER_INIT(sb + 32 + 8 * i, 256);
        }
        MBARRIER_INIT(sb + 64, 1);
        FENCE_PROXY_ASYNC();
    }
    __syncthreads();

    if (tid == 0) {
        MBARRIER_EXPECT_TX(sb + 64, 16384);
        bulk_g2s(qsm, Qsrc, 16384, sb + 64);
#pragma unroll
        for (int i = 0; i < 4; i++) {
            MBARRIER_EXPECT_TX(sb + 8 * i, 16384);
            bulk_g2s(kvsm + i * 16384, KVsrc + (size_t)i * 16384, 16384, sb + 8 * i);
        }
    }

    float Oacc[8][4];
#pragma unroll
    for (int i = 0; i < 8; i++)
#pragma unroll
        for (int j = 0; j < 4; j++) Oacc[i][j] = 0.0f;
    float m0 = -1e30f, m1 = -1e30f, l0 = 0.0f, l1 = 0.0f;

    const int r = lane >> 2;
    const int grow0 = q0 + wid * 16 + r;
    const int grow1 = grow0 + 8;
    const float* brow0 = bias + (size_t)grow0 * (H_NUM * S_LEN) + (size_t)h * S_LEN;
    const float* brow1 = bias + (size_t)grow1 * (H_NUM * S_LEN) + (size_t)h * S_LEN;
    const uint32_t* mp0 = mpack + grow0 * (S_LEN / 32);
    const uint32_t* mp1 = mpack + grow1 * (S_LEN / 32);
    const int cbase = (lane & 3) * 2;
    const int qrow = wid * 16 + (lane & 15);
    const int qsel = (lane >> 4) * 16;

    MBARRIER_WAIT_PARITY(sb + 64, 0);

    // Q fragments persistent (hi-only: 16 regs)
    uint32_t qfr[4][4];
#pragma unroll
    for (int kc = 0; kc < 4; kc++) {
        uint32_t qoff = SMEM_SWZ((uint32_t)(qrow * 128 + kc * 32 + qsel));
        ldsm4(qfr[kc], qsm + qoff);
    }

    for (int t = 0; t < S_LEN / 64; t++) {
        const int s = t & 3;
        const int ph = (t >> 2) & 1;
        MBARRIER_WAIT_PARITY(sb + 8 * s, ph);
        const uint32_t base = kvsm + s * 16384;
        const int j0 = t * 64;

        uint2 mwa = *(const uint2*)(mp0 + (j0 >> 5));
        uint2 mwb = *(const uint2*)(mp1 + (j0 >> 5));
        uint64_t sm0 = (((uint64_t)mwa.y << 32) | mwa.x) >> cbase;
        uint64_t sm1 = (((uint64_t)mwb.y << 32) | mwb.x) >> cbase;

        // hoisted bias loads (DRAM latency covered by QK tensor phase)
        float2 bv0[8], bv1[8];
#pragma unroll
        for (int nt = 0; nt < 8; nt++) {
            bv0[nt] = *(const float2*)(brow0 + j0 + nt * 8 + cbase);
            bv1[nt] = *(const float2*)(brow1 + j0 + nt * 8 + cbase);
        }

        float acc[8][4];
#pragma unroll
        for (int i = 0; i < 8; i++)
#pragma unroll
            for (int j = 0; j < 4; j++) acc[i][j] = 0.0f;

#pragma unroll
        for (int kc = 0; kc < 4; kc++) {
#pragma unroll
            for (int np = 0; np < 4; np++) {
                int krow = np * 16 + (lane >> 4) * 8 + (lane & 7);
                uint32_t koff = SMEM_SWZ((uint32_t)(krow * 128 + kc * 32 + ((lane >> 3) & 1) * 16));
                uint32_t bh[4];
                ldsm4(bh, base + koff);
                mma16816(acc[2 * np],     qfr[kc], bh + 0);
                mma16816(acc[2 * np + 1], qfr[kc], bh + 2);
            }
        }

        float mx0 = -1e30f, mx1 = -1e30f;
#pragma unroll
        for (int nt = 0; nt < 8; nt++) {
            uint32_t w0 = (uint32_t)(sm0 >> (nt * 8));
            uint32_t w1 = (uint32_t)(sm1 >> (nt * 8));
            acc[nt][0] = (w0 & 1u) ? fmaf(bv0[nt].x, LOG2E, acc[nt][0]) : -1e30f;
            acc[nt][1] = (w0 & 2u) ? fmaf(bv0[nt].y, LOG2E, acc[nt][1]) : -1e30f;
            acc[nt][2] = (w1 & 1u) ? fmaf(bv1[nt].x, LOG2E, acc[nt][2]) : -1e30f;
            acc[nt][3] = (w1 & 2u) ? fmaf(bv1[nt].y, LOG2E, acc[nt][3]) : -1e30f;
            mx0 = fmaxf(mx0, fmaxf(acc[nt][0], acc[nt][1]));
            mx1 = fmaxf(mx1, fmaxf(acc[nt][2], acc[nt][3]));
        }
        mx0 = fmaxf(mx0, __shfl_xor_sync(0xffffffffu, mx0, 1));
        mx0 = fmaxf(mx0, __shfl_xor_sync(0xffffffffu, mx0, 2));
        mx1 = fmaxf(mx1, __shfl_xor_sync(0xffffffffu, mx1, 1));
        mx1 = fmaxf(mx1, __shfl_xor_sync(0xffffffffu, mx1, 2));

        float mn0 = fmaxf(m0, mx0), mn1 = fmaxf(m1, mx1);
        float a0 = ex2(m0 - mn0), a1 = ex2(m1 - mn1);
        m0 = mn0; m1 = mn1;

        uint32_t parr[8][2];
        float s0 = 0.0f, s1 = 0.0f;
#pragma unroll
        for (int nt = 0; nt < 8; nt++) {
            uint32_t d01 = packh2(acc[nt][0] - mn0, acc[nt][1] - mn0);
            uint32_t d23 = packh2(acc[nt][2] - mn1, acc[nt][3] - mn1);
            parr[nt][0] = ex2h2(d01);
            parr[nt][1] = ex2h2(d23);
            float2 f01 = h2f2(parr[nt][0]);
            float2 f23 = h2f2(parr[nt][1]);
            s0 += f01.x + f01.y;
            s1 += f23.x + f23.y;
        }
        s0 += __shfl_xor_sync(0xffffffffu, s0, 1);
        s0 += __shfl_xor_sync(0xffffffffu, s0, 2);
        s1 += __shfl_xor_sync(0xffffffffu, s1, 1);
        s1 += __shfl_xor_sync(0xffffffffu, s1, 2);
        l0 = l0 * a0 + s0;
        l1 = l1 * a1 + s1;

#pragma unroll
        for (int nt = 0; nt < 8; nt++) {
            Oacc[nt][0] *= a0; Oacc[nt][1] *= a0;
            Oacc[nt][2] *= a1; Oacc[nt][3] *= a1;
        }

#pragma unroll
        for (int kc = 0; kc < 4; kc++) {
            uint32_t pha[4];
            pha[0] = parr[2 * kc][0];
            pha[1] = parr[2 * kc][1];
            pha[2] = parr[2 * kc + 1][0];
            pha[3] = parr[2 * kc + 1][1];
#pragma unroll
            for (int dp = 0; dp < 4; dp++) {
                int vrow = kc * 16 + (lane & 15);
                uint32_t voff = SMEM_SWZ((uint32_t)(vrow * 128 + dp * 32 + (lane >> 4) * 16));
                uint32_t vh[4];
                ldsm4t(vh, base + 8192 + voff);
                mma16816(Oacc[2 * dp],     pha, vh + 0);
                mma16816(Oacc[2 * dp + 1], pha, vh + 2);
            }
        }

        MBARRIER_ARRIVE(sb + 32 + 8 * s);

        if (t + 4 < S_LEN / 64 && tid == 0) {
            MBARRIER_WAIT_PARITY(sb + 32 + 8 * s, ph);
            MBARRIER_EXPECT_TX(sb + 8 * s, 16384);
            bulk_g2s(kvsm + s * 16384, KVsrc + (size_t)(t + 4) * 16384, 16384, sb + 8 * s);
        }
    }

    float inv0 = 1.0f / l0, inv1 = 1.0f / l1;
    char* outb = (char*)Ob + ((size_t)qb * 16 + h) * 32768;
    const int r128 = wid * 16 + r;
#pragma unroll
    for (int nt = 0; nt < 8; nt++) {
        int d = nt * 8 + cbase;
        float v0 = Oacc[nt][0] * inv0, v1 = Oacc[nt][1] * inv0;
        float v2 = Oacc[nt][2] * inv1, v3 = Oacc[nt][3] * inv1;
        uint32_t o0 = SMEM_SWZ((uint32_t)(r128 * 128 + d * 2));
        uint32_t o1 = SMEM_SWZ((uint32_t)((r128 + 8) * 128 + d * 2));
        *(uint32_t*)(outb + o0) = packh2(v0, v1);
        *(uint32_t*)(outb + o1) = packh2(v2, v3);
    }
}

// ---------------------------------------------------------------------------
// LayerNorm
// ---------------------------------------------------------------------------
__device__ __forceinline__ float block_reduce_sum(float v) {
    __shared__ float red[8];
    int lane = threadIdx.x & 31, w = threadIdx.x >> 5;
#pragma unroll
    for (int o = 16; o > 0; o >>= 1) v += __shfl_xor_sync(0xffffffffu, v, o);
    __syncthreads();
    if (lane == 0) red[w] = v;
    __syncthreads();
    float t = 0.0f;
#pragma unroll
    for (int i = 0; i < 8; i++) t += red[i];
    return t;
}

__global__ __launch_bounds__(256) void ln_kernel(
    const float* __restrict__ res, const float* __restrict__ w,
    const float* __restrict__ b, float* __restrict__ out)
{
    int row = blockIdx.x;
    int tid = threadIdx.x;
    const float* r = res + (size_t)row * D_DIM;

    float4 x4 = *(const float4*)(r + tid * 4);
    float sum = x4.x + x4.y + x4.z + x4.w;
    sum = block_reduce_sum(sum);
    float mean = sum * (1.0f / D_DIM);

    float d0 = x4.x - mean, d1 = x4.y - mean, d2 = x4.z - mean, d3 = x4.w - mean;
    float sq = d0 * d0 + d1 * d1 + d2 * d2 + d3 * d3;
    sq = block_reduce_sum(sq);
    float inv = rsqrtf(sq * (1.0f / D_DIM) + LN_EPS);

    float4 w4 = *(const float4*)(w + tid * 4);
    float4 b4 = *(const float4*)(b + tid * 4);
    float4 o4;
    o4.x = d0 * inv * w4.x + b4.x;
    o4.y = d1 * inv * w4.y + b4.y;
    o4.z = d2 * inv * w4.z + b4.z;
    o4.w = d3 * inv * w4.w + b4.w;
    *(float4*)(out + (size_t)row * D_DIM + tid * 4) = o4;
}

// ---------------------------------------------------------------------------
// Launch
// ---------------------------------------------------------------------------
extern "C" void kernel_launch(void* const* d_in, const int* in_sizes, int n_in,
                              void* d_out, int out_size)
{
    (void)in_sizes; (void)n_in; (void)out_size;

    const float*        x    = (const float*)d_in[0];
    const float*        bias = (const float*)d_in[1];
    const unsigned int* mask = (const unsigned int*)d_in[2];
    const float*        Wq   = (const float*)d_in[3];
    const float*        Wk   = (const float*)d_in[4];
    const float*        Wv   = (const float*)d_in[5];
    const float*        Wo   = (const float*)d_in[6];
    const float*        lnw  = (const float*)d_in[7];
    const float*        lnb  = (const float*)d_in[8];
    float*              out  = (float*)d_out;

    void *pxb, *pwq, *pwk, *pwv, *pwo, *pqb, *pkv, *pab, *pres, *pmp;
    cudaGetSymbolAddress(&pxb, g_xb);
    cudaGetSymbolAddress(&pwq, g_wqb);
    cudaGetSymbolAddress(&pwk, g_wkb);
    cudaGetSymbolAddress(&pwv, g_wvb);
    cudaGetSymbolAddress(&pwo, g_wob);
    cudaGetSymbolAddress(&pqb, g_qb);
    cudaGetSymbolAddress(&pkv, g_kvb);
    cudaGetSymbolAddress(&pab, g_ab);
    cudaGetSymbolAddress(&pres, g_res);
    cudaGetSymbolAddress(&pmp, g_mpack);

    __half *xb = (__half*)pxb;
    __half *wqb = (__half*)pwq, *wkb = (__half*)pwk;
    __half *wvb = (__half*)pwv, *wob = (__half*)pwo;
    __half *qb = (__half*)pqb, *kvb = (__half*)pkv;
    __half *ab = (__half*)pab;
    float* res = (float*)pres;
    uint32_t* mp = (uint32_t*)pmp;

    cudaFuncSetAttribute(gemm_blob_kernel, cudaFuncAttributeMaxDynamicSharedMemorySize, GEMM_SMEM);
    cudaFuncSetAttribute(attn_blob_kernel, cudaFuncAttributeMaxDynamicSharedMemorySize, ATT_SMEM);

    dim3 gt(D_DIM / 128, S_LEN / 64);   // (8, 32) = 256 CTAs

    split_all_kernel<<<3072, 256>>>(x, Wq, Wk, Wv, Wo, xb, wqb, wkb, wvb, wob);
    pack_mask_kernel<<<S_LEN, 256>>>(mask, mp);

    gemm_blob_kernel<<<gt, 256, GEMM_SMEM>>>(xb, wqb, nullptr, nullptr, qb,
                                             1, 1, 0.125f * LOG2E, D_DIM, D_DIM);
    gemm_blob_kernel<<<gt, 256, GEMM_SMEM>>>(xb, wkb, nullptr, nullptr, kvb,
                                             2, 1, 1.0f, D_DIM, D_DIM);
    gemm_blob_kernel<<<gt, 256, GEMM_SMEM>>>(xb, wvb, nullptr, nullptr, kvb,
                                             3, 0, 1.0f, D_DIM, D_DIM);

    attn_blob_kernel<<<dim3(S_LEN / 128, H_NUM), 256, ATT_SMEM>>>(qb, kvb, bias, mp, ab);

    gemm_blob_kernel<<<gt, 256, GEMM_SMEM>>>(ab, wob, x, res, nullptr,
                                             0, 0, 1.0f, D_DIM, D_DIM);

    ln_kernel<<<S_LEN, 256>>>(res, lnw, lnb, out);
}